// round 8
// baseline (speedup 1.0000x reference)
#include <cuda_runtime.h>
#include <cuda_bf16.h>
#include <math.h>
#include <stddef.h>
#include <stdint.h>

// Triangle multiplicative update (outgoing), N=512, cz=ch=128, fp32 in/out.
// All GEMMs on tensor cores via mma.sync bf16 hi/lo split (3 passes, fp32 acc).
// Round 8: LN folded into k3 GEMM (W' = s.W, u/v vectors), k2 writes x as
//          bf16 hi/lo, g-projection interleaved into k2's launch.

#define NSEQ 512
#define CDIM 128
#define NN   (NSEQ*NSEQ)          // 262144
#define PIT  136                  // bf16 smem pitch (elements)
#define PITB 272                  // bytes
#define NT   512                  // threads per CTA

__device__ __nv_bfloat16 g_a_hi[(size_t)CDIM * NN];
__device__ __nv_bfloat16 g_a_lo[(size_t)CDIM * NN];
__device__ __nv_bfloat16 g_b_hi[(size_t)CDIM * NN];
__device__ __nv_bfloat16 g_b_lo[(size_t)CDIM * NN];
__device__ float g_g[(size_t)NN * CDIM];            // g[pix][c]
__device__ __nv_bfloat16 g_xh[(size_t)CDIM * NN];   // x hi [c][i][j]
__device__ __nv_bfloat16 g_xl[(size_t)CDIM * NN];   // x lo
// pre-split weights: 0=lgate 1=left 2=rgate 3=right 4=gate 5=out(.scaled)
__device__ __align__(16) __nv_bfloat16 g_wh[6 * 16384];
__device__ __align__(16) __nv_bfloat16 g_wl[6 * 16384];
__device__ float g_u[128];   // sum_c s[c]*w_out[c][n]
__device__ float g_v[128];   // sum_c b_ln[c]*w_out[c][n]

__device__ __forceinline__ float sigmf(float x) {
    return 1.0f / (1.0f + __expf(-x));
}
__device__ __forceinline__ unsigned pk_bf16x2(float a, float b) {
    __nv_bfloat162 t = __floats2bfloat162_rn(a, b);
    return *reinterpret_cast<unsigned*>(&t);
}
__device__ __forceinline__ float bf16_res(float v) {   // v - bf16(v)
    return v - __bfloat162float(__float2bfloat16(v));
}
__device__ __forceinline__ uint32_t smem_u32(const void* p) {
    uint32_t a;
    asm("{ .reg .u64 t; cvta.to.shared.u64 t, %1; cvt.u32.u64 %0, t; }"
        : "=r"(a) : "l"(p));
    return a;
}
__device__ __forceinline__ void cp16(uint32_t dst, const void* src) {
    asm volatile("cp.async.cg.shared.global [%0], [%1], 16;"
                 :: "r"(dst), "l"(src) : "memory");
}
#define CP_COMMIT() asm volatile("cp.async.commit_group;" ::: "memory")
#define CP_WAIT0()  asm volatile("cp.async.wait_group 0;" ::: "memory")
#define SWZ(o) ((o) ^ (((o) >> 3) & 0x70))

__device__ __forceinline__ void ldsm4(uint32_t addr, uint32_t* r) {
    asm volatile("ldmatrix.sync.aligned.m8n8.x4.shared.b16 {%0,%1,%2,%3}, [%4];"
                 : "=r"(r[0]), "=r"(r[1]), "=r"(r[2]), "=r"(r[3]) : "r"(addr));
}
__device__ __forceinline__ void ldsm4_t(uint32_t addr, uint32_t* r) {
    asm volatile("ldmatrix.sync.aligned.m8n8.x4.trans.shared.b16 {%0,%1,%2,%3}, [%4];"
                 : "=r"(r[0]), "=r"(r[1]), "=r"(r[2]), "=r"(r[3]) : "r"(addr));
}
__device__ __forceinline__ void mma_bf16(float* c, const uint32_t* a,
                                         const uint32_t* b) {
    asm volatile(
        "mma.sync.aligned.m16n8k16.row.col.f32.bf16.bf16.f32 "
        "{%0,%1,%2,%3}, {%4,%5,%6,%7}, {%8,%9}, {%0,%1,%2,%3};"
        : "+f"(c[0]), "+f"(c[1]), "+f"(c[2]), "+f"(c[3])
        : "r"(a[0]), "r"(a[1]), "r"(a[2]), "r"(a[3]), "r"(b[0]), "r"(b[1]));
}

__device__ __forceinline__ void split4(float4 v, uint2& hv, uint2& lv) {
    hv.x = pk_bf16x2(v.x, v.y);
    hv.y = pk_bf16x2(v.z, v.w);
    lv.x = pk_bf16x2(bf16_res(v.x), bf16_res(v.y));
    lv.y = pk_bf16x2(bf16_res(v.z), bf16_res(v.w));
}

// ---------------------------------------------------------------------------
// Kernel 0: pre-split 6 weight matrices (w_out pre-scaled by ln_out_scale),
// plus u/v fold vectors. Grid 97 x 256.
// ---------------------------------------------------------------------------
__global__ void __launch_bounds__(256)
k0_split(const float* __restrict__ w0, const float* __restrict__ w1,
         const float* __restrict__ w2, const float* __restrict__ w3,
         const float* __restrict__ w4, const float* __restrict__ w5,
         const float* __restrict__ so, const float* __restrict__ bo)
{
    if (blockIdx.x == 96) {
        int n = threadIdx.x;
        if (n < 128) {
            float u = 0.f, v = 0.f;
            for (int c = 0; c < 128; ++c) {
                float w = w5[c * 128 + n];
                u += so[c] * w;
                v += bo[c] * w;
            }
            g_u[n] = u; g_v[n] = v;
        }
        return;
    }
    const float* ws[6] = {w0, w1, w2, w3, w4, w5};
    int idx = blockIdx.x * 256 + threadIdx.x;   // 24576 threads
    int m = idx >> 12;
    int e = (idx & 4095) * 4;
    float4 v = *(const float4*)(ws[m] + e);
    if (m == 5) {
        float sc = so[e >> 7];
        v.x *= sc; v.y *= sc; v.z *= sc; v.w *= sc;
    }
    uint2 hv, lv;
    split4(v, hv, lv);
    *(uint2*)(g_wh + m * 16384 + e) = hv;
    *(uint2*)(g_wl + m * 16384 + e) = lv;
}

// ---------------------------------------------------------------------------
// Kernel 1: one LN pass, two gated projection phases (a, b) per 128-px tile.
// ---------------------------------------------------------------------------
__global__ void __launch_bounds__(NT, 1)
k1_all(const float* __restrict__ z, const float* __restrict__ mask,
       const float* __restrict__ ln_s, const float* __restrict__ ln_b,
       const float* __restrict__ b_lg, const float* __restrict__ b_l,
       const float* __restrict__ b_rg, const float* __restrict__ b_r)
{
    extern __shared__ char smraw[];
    __nv_bfloat16* znh = (__nv_bfloat16*)smraw;           // [p][k] pitch 136
    __nv_bfloat16* znl = znh + 128 * PIT;
    __nv_bfloat16* W0h = znl + 128 * PIT;                 // gate weights
    __nv_bfloat16* W0l = W0h + 128 * PIT;
    __nv_bfloat16* W1h = W0l + 128 * PIT;                 // value weights
    __nv_bfloat16* W1l = W1h + 128 * PIT;
    float* bs = (float*)(W1l + 128 * PIT);
    // bs: [0)lg [128)l [256)rg [384)r [512)mask

    const int tid = threadIdx.x, lane = tid & 31, wid = tid >> 5;
    const int pix0 = blockIdx.x * 128;

    const uint32_t w0hA = smem_u32(W0h), w0lA = smem_u32(W0l);
    const uint32_t w1hA = smem_u32(W1h), w1lA = smem_u32(W1l);

#define STAGE_W(mi, dsth, dstl)                                               \
    do {                                                                      \
        const __nv_bfloat16* SH = g_wh + (mi) * 16384;                        \
        const __nv_bfloat16* SL = g_wl + (mi) * 16384;                        \
        _Pragma("unroll")                                                     \
        for (int t = 0; t < 4; ++t) {                                         \
            int u = tid + t * NT;                                             \
            int r = u >> 4, c = u & 15;                                       \
            uint32_t doff = (uint32_t)(r * PITB + c * 16);                    \
            int goff = r * 128 + c * 8;                                       \
            cp16((dsth) + doff, SH + goff);                                   \
            cp16((dstl) + doff, SL + goff);                                   \
        }                                                                     \
    } while (0)

    STAGE_W(0, w0hA, w0lA);
    STAGE_W(1, w1hA, w1lA);
    CP_COMMIT();

    {
        int which = tid >> 7, r = tid & 127;
        const float* bp[4] = {b_lg, b_l, b_rg, b_r};
        bs[tid] = bp[which][r];
        if (tid < 128) bs[512 + tid] = mask[pix0 + tid];
    }

    // LayerNorm (overlaps with weight cp.async)
    {
        float4 s4 = ((const float4*)ln_s)[lane];
        float4 b4 = ((const float4*)ln_b)[lane];
        float4 v[8];
#pragma unroll
        for (int t = 0; t < 8; ++t)
            v[t] = ((const float4*)(z + (size_t)(pix0 + t * 16 + wid) * CDIM))[lane];
#pragma unroll
        for (int t = 0; t < 8; ++t) {
            int r = t * 16 + wid;
            float s  = v[t].x + v[t].y + v[t].z + v[t].w;
            float ss = v[t].x*v[t].x + v[t].y*v[t].y + v[t].z*v[t].z + v[t].w*v[t].w;
#pragma unroll
            for (int o = 16; o > 0; o >>= 1) {
                s  += __shfl_xor_sync(0xffffffffu, s,  o);
                ss += __shfl_xor_sync(0xffffffffu, ss, o);
            }
            float mu   = s * 0.0078125f;
            float rstd = rsqrtf(ss * 0.0078125f - mu * mu + 1e-5f);
            float4 o4;
            o4.x = (v[t].x - mu) * rstd * s4.x + b4.x;
            o4.y = (v[t].y - mu) * rstd * s4.y + b4.y;
            o4.z = (v[t].z - mu) * rstd * s4.z + b4.z;
            o4.w = (v[t].w - mu) * rstd * s4.w + b4.w;
            uint2 hv, lv;
            split4(o4, hv, lv);
            *(uint2*)(&znh[r * PIT + lane * 4]) = hv;
            *(uint2*)(&znl[r * PIT + lane * 4]) = lv;
        }
    }
    CP_WAIT0();
    __syncthreads();

    const int wm = wid & 3, wn = wid >> 2;   // 4 (M) x 4 (N) warp grid
    const uint32_t zh = smem_u32(znh), zl = smem_u32(znl);

    const int at_row = (lane & 7) + ((lane >> 4) << 3);      // trans A (W^T)
    const int at_col = ((lane >> 3) & 1) << 3;
    const int bp_row = wn * 32 + (lane & 7) + ((lane >> 4) << 3);  // non-trans B (zn)
    const uint32_t bko = ((lane >> 3) & 1) * 16;

#pragma unroll 1
    for (int ph = 0; ph < 2; ++ph) {
        float P[2][4][4], Q[2][4][4];
#pragma unroll
        for (int a = 0; a < 2; ++a)
#pragma unroll
            for (int b = 0; b < 4; ++b)
#pragma unroll
                for (int q = 0; q < 4; ++q) { P[a][b][q] = 0.f; Q[a][b][q] = 0.f; }

#pragma unroll
        for (int k16 = 0; k16 < 8; ++k16) {
            const int kb = k16 * 16;
            uint32_t bh[4][2], bl[4][2];
#pragma unroll
            for (int ng = 0; ng < 2; ++ng) {
                uint32_t r4[4];
                uint32_t boff = (uint32_t)((bp_row + ng * 16) * PITB) + kb * 2 + bko;
                ldsm4(zh + boff, r4);
                bh[ng*2][0] = r4[0]; bh[ng*2][1] = r4[1];
                bh[ng*2+1][0] = r4[2]; bh[ng*2+1][1] = r4[3];
                ldsm4(zl + boff, r4);
                bl[ng*2][0] = r4[0]; bl[ng*2][1] = r4[1];
                bl[ng*2+1][0] = r4[2]; bl[ng*2+1][1] = r4[3];
            }
            uint32_t aoff[2];
#pragma unroll
            for (int mt = 0; mt < 2; ++mt)
                aoff[mt] = (uint32_t)((kb + at_row) * PITB) +
                           (wm * 32 + mt * 16 + at_col) * 2;
            uint32_t a[2][4];
#pragma unroll
            for (int mt = 0; mt < 2; ++mt) ldsm4_t(w0hA + aoff[mt], a[mt]);
#pragma unroll
            for (int mt = 0; mt < 2; ++mt)
#pragma unroll
                for (int nt = 0; nt < 4; ++nt) {
                    mma_bf16(P[mt][nt], a[mt], bh[nt]);
                    mma_bf16(P[mt][nt], a[mt], bl[nt]);
                }
#pragma unroll
            for (int mt = 0; mt < 2; ++mt) ldsm4_t(w0lA + aoff[mt], a[mt]);
#pragma unroll
            for (int mt = 0; mt < 2; ++mt)
#pragma unroll
                for (int nt = 0; nt < 4; ++nt)
                    mma_bf16(P[mt][nt], a[mt], bh[nt]);
#pragma unroll
            for (int mt = 0; mt < 2; ++mt) ldsm4_t(w1hA + aoff[mt], a[mt]);
#pragma unroll
            for (int mt = 0; mt < 2; ++mt)
#pragma unroll
                for (int nt = 0; nt < 4; ++nt) {
                    mma_bf16(Q[mt][nt], a[mt], bh[nt]);
                    mma_bf16(Q[mt][nt], a[mt], bl[nt]);
                }
#pragma unroll
            for (int mt = 0; mt < 2; ++mt) ldsm4_t(w1lA + aoff[mt], a[mt]);
#pragma unroll
            for (int mt = 0; mt < 2; ++mt)
#pragma unroll
                for (int nt = 0; nt < 4; ++nt)
                    mma_bf16(Q[mt][nt], a[mt], bh[nt]);
        }

        __syncthreads();   // all warps done reading W0/W1
        if (ph == 0) { STAGE_W(2, w0hA, w0lA); STAGE_W(3, w1hA, w1lA); CP_COMMIT(); }

        const float* bgp = bs + ph * 256;
        const float* bvp = bs + ph * 256 + 128;
        const float* msm = bs + 512;
        __nv_bfloat16* oh = (ph == 0) ? g_a_hi : g_b_hi;
        __nv_bfloat16* ol = (ph == 0) ? g_a_lo : g_b_lo;
#pragma unroll
        for (int mt = 0; mt < 2; ++mt) {
            int ch = wm * 32 + mt * 16 + (lane >> 2);
            float bg0v = bgp[ch], bg1v = bgp[ch + 8];
            float bv0v = bvp[ch], bv1v = bvp[ch + 8];
            size_t r0 = (size_t)ch * NN + pix0;
            size_t r1 = (size_t)(ch + 8) * NN + pix0;
#pragma unroll
            for (int nt = 0; nt < 4; ++nt) {
                int p = wn * 32 + nt * 8 + (lane & 3) * 2;
                float m0 = msm[p], m1 = msm[p + 1];
                float v00 = m0 * sigmf(P[mt][nt][0] + bg0v) * (Q[mt][nt][0] + bv0v);
                float v01 = m1 * sigmf(P[mt][nt][1] + bg0v) * (Q[mt][nt][1] + bv0v);
                float v10 = m0 * sigmf(P[mt][nt][2] + bg1v) * (Q[mt][nt][2] + bv1v);
                float v11 = m1 * sigmf(P[mt][nt][3] + bg1v) * (Q[mt][nt][3] + bv1v);
                *(uint32_t*)(oh + r0 + p) = pk_bf16x2(v00, v01);
                *(uint32_t*)(ol + r0 + p) = pk_bf16x2(bf16_res(v00), bf16_res(v01));
                *(uint32_t*)(oh + r1 + p) = pk_bf16x2(v10, v11);
                *(uint32_t*)(ol + r1 + p) = pk_bf16x2(bf16_res(v10), bf16_res(v11));
            }
        }
        if (ph == 0) { CP_WAIT0(); __syncthreads(); }
    }
#undef STAGE_W
}

// ---------------------------------------------------------------------------
// Kernel 2: grid (4,4,160).
//  z%5 != 4 -> per-channel X_c = A_c @ B_c^T (3-stage cp.async pipeline),
//              epilogue writes x as bf16 hi/lo.
//  z%5 == 4 -> g = sig(zn @ Wg + bg) for 4 pixel tiles (overlapped work).
// ---------------------------------------------------------------------------
#define K2S 65536u

__global__ void __launch_bounds__(NT, 1)
k2_mma(const float* __restrict__ z, const float* __restrict__ ln_s,
       const float* __restrict__ ln_b, const float* __restrict__ b_g)
{
    extern __shared__ char sm2[];
    const uint32_t smb = smem_u32(sm2);
    const int tid  = threadIdx.x;
    const int lane = tid & 31, wid = tid >> 5;
    const int wm = wid & 3, wn = wid >> 2;

    if (blockIdx.z % 5 == 4) {
        // ---------------- g-projection path ----------------
        __nv_bfloat16* znh = (__nv_bfloat16*)sm2;
        __nv_bfloat16* znl = znh + 128 * PIT;
        __nv_bfloat16* Wh  = znl + 128 * PIT;
        __nv_bfloat16* Wl  = Wh + 128 * PIT;
        float* bsg = (float*)(Wl + 128 * PIT);   // 128

        const uint32_t zhA = smem_u32(znh), zlA = smem_u32(znl);
        const uint32_t whA = smem_u32(Wh), wlA = smem_u32(Wl);
        {
            const __nv_bfloat16* SH = g_wh + 4 * 16384;
            const __nv_bfloat16* SL = g_wl + 4 * 16384;
#pragma unroll
            for (int t = 0; t < 4; ++t) {
                int u = tid + t * NT;
                int r = u >> 4, c = u & 15;
                uint32_t doff = (uint32_t)(r * PITB + c * 16);
                int goff = r * 128 + c * 8;
                cp16(whA + doff, SH + goff);
                cp16(wlA + doff, SL + goff);
            }
            CP_COMMIT();
        }
        if (tid < 128) bsg[tid] = b_g[tid];

        const int gi = (blockIdx.z / 5) * 16 + blockIdx.y * 4 + blockIdx.x;
        const int a_row = wm * 32 + (lane & 15);
        const uint32_t ako = (lane >> 4) * 16;
        const int bt_row = (lane & 7) + (((lane >> 3) & 1) << 3);
        const int bt_col = (lane >> 4) << 3;

        float4 s4 = ((const float4*)ln_s)[lane];
        float4 b4 = ((const float4*)ln_b)[lane];

#pragma unroll 1
        for (int it = 0; it < 4; ++it) {
            const int pix0 = (gi * 4 + it) * 128;
            // LayerNorm into znh/znl
            {
                float4 v[8];
#pragma unroll
                for (int t = 0; t < 8; ++t)
                    v[t] = ((const float4*)(z + (size_t)(pix0 + t * 16 + wid) * CDIM))[lane];
#pragma unroll
                for (int t = 0; t < 8; ++t) {
                    int r = t * 16 + wid;
                    float s  = v[t].x + v[t].y + v[t].z + v[t].w;
                    float ss = v[t].x*v[t].x + v[t].y*v[t].y + v[t].z*v[t].z + v[t].w*v[t].w;
#pragma unroll
                    for (int o = 16; o > 0; o >>= 1) {
                        s  += __shfl_xor_sync(0xffffffffu, s,  o);
                        ss += __shfl_xor_sync(0xffffffffu, ss, o);
                    }
                    float mu   = s * 0.0078125f;
                    float rstd = rsqrtf(ss * 0.0078125f - mu * mu + 1e-5f);
                    float4 o4;
                    o4.x = (v[t].x - mu) * rstd * s4.x + b4.x;
                    o4.y = (v[t].y - mu) * rstd * s4.y + b4.y;
                    o4.z = (v[t].z - mu) * rstd * s4.z + b4.z;
                    o4.w = (v[t].w - mu) * rstd * s4.w + b4.w;
                    uint2 hv, lv;
                    split4(o4, hv, lv);
                    *(uint2*)(&znh[r * PIT + lane * 4]) = hv;
                    *(uint2*)(&znl[r * PIT + lane * 4]) = lv;
                }
            }
            if (it == 0) CP_WAIT0();
            __syncthreads();

            float P[2][4][4];
#pragma unroll
            for (int a = 0; a < 2; ++a)
#pragma unroll
                for (int b = 0; b < 4; ++b)
#pragma unroll
                    for (int q = 0; q < 4; ++q) P[a][b][q] = 0.f;

#pragma unroll
            for (int k16 = 0; k16 < 8; ++k16) {
                const int kb = k16 * 16;
                uint32_t bh[4][2], bl[4][2];
#pragma unroll
                for (int ng = 0; ng < 2; ++ng) {
                    uint32_t r4[4];
                    uint32_t boff = (uint32_t)((kb + bt_row) * PITB) +
                                    (wn * 32 + ng * 16 + bt_col) * 2;
                    ldsm4_t(whA + boff, r4);
                    bh[ng*2][0] = r4[0]; bh[ng*2][1] = r4[1];
                    bh[ng*2+1][0] = r4[2]; bh[ng*2+1][1] = r4[3];
                    ldsm4_t(wlA + boff, r4);
                    bl[ng*2][0] = r4[0]; bl[ng*2][1] = r4[1];
                    bl[ng*2+1][0] = r4[2]; bl[ng*2+1][1] = r4[3];
                }
                uint32_t ah[2][4], al[2][4];
#pragma unroll
                for (int mt = 0; mt < 2; ++mt) {
                    uint32_t aoff = (uint32_t)((a_row + mt * 16) * PITB) + kb * 2 + ako;
                    ldsm4(zhA + aoff, ah[mt]);
                    ldsm4(zlA + aoff, al[mt]);
                }
#pragma unroll
                for (int mt = 0; mt < 2; ++mt)
#pragma unroll
                    for (int nt = 0; nt < 4; ++nt) {
                        mma_bf16(P[mt][nt], ah[mt], bh[nt]);
                        mma_bf16(P[mt][nt], ah[mt], bl[nt]);
                        mma_bf16(P[mt][nt], al[mt], bh[nt]);
                    }
            }

#pragma unroll
            for (int mt = 0; mt < 2; ++mt) {
                int p0 = pix0 + wm * 32 + mt * 16 + (lane >> 2);
#pragma unroll
                for (int nt = 0; nt < 4; ++nt) {
                    int ch = wn * 32 + nt * 8 + (lane & 3) * 2;
                    float b0 = bsg[ch], b1 = bsg[ch + 1];
                    float2 v0 = make_float2(sigmf(P[mt][nt][0] + b0),
                                            sigmf(P[mt][nt][1] + b1));
                    float2 v1 = make_float2(sigmf(P[mt][nt][2] + b0),
                                            sigmf(P[mt][nt][3] + b1));
                    *(float2*)(g_g + (size_t)p0 * CDIM + ch) = v0;
                    *(float2*)(g_g + (size_t)(p0 + 8) * CDIM + ch) = v1;
                }
            }
            __syncthreads();
        }
        return;
    }

    // ---------------- triangular einsum path ----------------
    const int chan = (blockIdx.z / 5) * 4 + (blockIdx.z % 5);
    const int i0 = blockIdx.x * 128, j0 = blockIdx.y * 128;
    const size_t cbase = (size_t)chan * NN;

    const __nv_bfloat16* Ah = g_a_hi + cbase + (size_t)i0 * NSEQ;
    const __nv_bfloat16* Al = g_a_lo + cbase + (size_t)i0 * NSEQ;
    const __nv_bfloat16* Bh = g_b_hi + cbase + (size_t)j0 * NSEQ;
    const __nv_bfloat16* Bl = g_b_lo + cbase + (size_t)j0 * NSEQ;

    float acc[2][4][4];
#pragma unroll
    for (int mt = 0; mt < 2; ++mt)
#pragma unroll
        for (int nt = 0; nt < 4; ++nt)
#pragma unroll
            for (int q = 0; q < 4; ++q) acc[mt][nt][q] = 0.f;

    const int arow = wm * 32 + (lane & 15);
    const int bnr  = wn * 32 + (lane & 7) + ((lane >> 4) << 3);
    const uint32_t a_koff = (uint32_t)((lane >> 4) << 4);
    const uint32_t b_koff = (uint32_t)(((lane >> 3) & 1) << 4);

#define K2_LOAD(kc, stg)                                                      \
    do {                                                                      \
        const int ke = (kc) * 64;                                             \
        _Pragma("unroll")                                                     \
        for (int t = 0; t < 2; ++t) {                                         \
            int v = tid + t * NT; int r = v >> 3, cu = v & 7;                 \
            uint32_t so = SWZ((uint32_t)(r * 128 + cu * 16));                 \
            const size_t go = (size_t)r * NSEQ + ke + cu * 8;                 \
            cp16((stg) + so,           Ah + go);                              \
            cp16((stg) + 16384u + so,  Al + go);                              \
            cp16((stg) + 32768u + so,  Bh + go);                              \
            cp16((stg) + 49152u + so,  Bl + go);                              \
        }                                                                     \
        asm volatile("cp.async.commit_group;" ::: "memory");                  \
    } while (0)

    K2_LOAD(0, smb);
    K2_LOAD(1, smb + K2S);

#pragma unroll 1
    for (int kc = 0; kc < 8; ++kc) {
        if (kc + 2 < 8) K2_LOAD(kc + 2, smb + (uint32_t)((kc + 2) % 3) * K2S);
        if (kc < 6)      asm volatile("cp.async.wait_group 2;" ::: "memory");
        else if (kc == 6) asm volatile("cp.async.wait_group 1;" ::: "memory");
        else              asm volatile("cp.async.wait_group 0;" ::: "memory");
        __syncthreads();
        const uint32_t stg = smb + (uint32_t)(kc % 3) * K2S;

#pragma unroll
        for (int k16 = 0; k16 < 4; ++k16) {
            const uint32_t kbA = (uint32_t)(k16 * 32) + a_koff;
            const uint32_t kbB = (uint32_t)(k16 * 32) + b_koff;
            uint32_t bh[4][2], bl[4][2];
#pragma unroll
            for (int ng = 0; ng < 2; ++ng) {
                uint32_t r4[4];
                uint32_t off = SWZ((uint32_t)((bnr + ng * 16) * 128) + kbB);
                ldsm4(stg + 32768u + off, r4);
                bh[ng * 2 + 0][0] = r4[0]; bh[ng * 2 + 0][1] = r4[1];
                bh[ng * 2 + 1][0] = r4[2]; bh[ng * 2 + 1][1] = r4[3];
                ldsm4(stg + 49152u + off, r4);
                bl[ng * 2 + 0][0] = r4[0]; bl[ng * 2 + 0][1] = r4[1];
                bl[ng * 2 + 1][0] = r4[2]; bl[ng * 2 + 1][1] = r4[3];
            }
#pragma unroll
            for (int mt = 0; mt < 2; ++mt) {
                uint32_t ah[4], al[4];
                uint32_t off = SWZ((uint32_t)((arow + mt * 16) * 128) + kbA);
                ldsm4(stg + off, ah);
                ldsm4(stg + 16384u + off, al);
#pragma unroll
                for (int nt = 0; nt < 4; ++nt) {
                    mma_bf16(acc[mt][nt], ah, bh[nt]);
                    mma_bf16(acc[mt][nt], ah, bl[nt]);
                    mma_bf16(acc[mt][nt], al, bh[nt]);
                }
            }
        }
        __syncthreads();
    }

    // epilogue: split to bf16 hi/lo -> g_xh/g_xl [c][i][j]
    __nv_bfloat16* Xh = g_xh + cbase + (size_t)(i0 + wm * 32) * NSEQ + j0 + wn * 32;
    __nv_bfloat16* Xl = g_xl + cbase + (size_t)(i0 + wm * 32) * NSEQ + j0 + wn * 32;
    const int rr = lane >> 2, cc = (lane & 3) * 2;
#pragma unroll
    for (int mt = 0; mt < 2; ++mt)
#pragma unroll
        for (int nt = 0; nt < 4; ++nt) {
            size_t o0 = (size_t)(mt * 16 + rr) * NSEQ + nt * 8 + cc;
            size_t o1 = o0 + 8 * NSEQ;
            float v0 = acc[mt][nt][0], v1 = acc[mt][nt][1];
            float v2 = acc[mt][nt][2], v3 = acc[mt][nt][3];
            *(uint32_t*)(Xh + o0) = pk_bf16x2(v0, v1);
            *(uint32_t*)(Xl + o0) = pk_bf16x2(bf16_res(v0), bf16_res(v1));
            *(uint32_t*)(Xh + o1) = pk_bf16x2(v2, v3);
            *(uint32_t*)(Xl + o1) = pk_bf16x2(bf16_res(v2), bf16_res(v3));
        }
#undef K2_LOAD
}

// ---------------------------------------------------------------------------
// Kernel 3: folded-LN out projection:
//   y[p][n] = rs[p]*(x@W')[p][n] - rs[p]*mu[p]*u[n] + (v[n]+b_out[n]);
//   out = y * g.
// ---------------------------------------------------------------------------
__global__ void __launch_bounds__(NT, 1)
k3_mma(const float* __restrict__ b_out, float* __restrict__ out)
{
    extern __shared__ char smraw[];
    __nv_bfloat16* Xh = (__nv_bfloat16*)smraw;          // [c][p] pitch 136
    __nv_bfloat16* Xl = Xh + 128 * PIT;
    __nv_bfloat16* Wh = Xl + 128 * PIT;                 // [k][n] pitch 136
    __nv_bfloat16* Wl = Wh + 128 * PIT;
    float* uS   = (float*)(Wl + 128 * PIT);   // 128
    float* wS   = uS + 128;                   // v + b_out, 128
    float* redS = wS + 128;                   // 512
    float* redQ = redS + 512;                 // 512
    float* rsS  = redQ + 512;                 // 128
    float* tS   = rsS + 128;                  // 128 (mu*rs)

    const int tid = threadIdx.x, lane = tid & 31, wid = tid >> 5;
    const int pix0 = blockIdx.x * 128;

    // async stage: x hi/lo tile + pre-split scaled w_out
    {
        const uint32_t xhA = smem_u32(Xh), xlA = smem_u32(Xl);
        const uint32_t whA = smem_u32(Wh), wlA = smem_u32(Wl);
        const __nv_bfloat16* GH = g_wh + 5 * 16384;
        const __nv_bfloat16* GL = g_wl + 5 * 16384;
#pragma unroll
        for (int t = 0; t < 4; ++t) {
            int u = tid + t * NT;
            int c = u >> 4, q = u & 15;
            uint32_t doff = (uint32_t)(c * PITB + q * 16);
            size_t goff = (size_t)c * NN + pix0 + q * 8;
            cp16(xhA + doff, g_xh + goff);
            cp16(xlA + doff, g_xl + goff);
        }
#pragma unroll
        for (int t = 0; t < 4; ++t) {
            int u = tid + t * NT;
            int r = u >> 4, c = u & 15;
            uint32_t doff = (uint32_t)(r * PITB + c * 16);
            int goff = r * 128 + c * 8;
            cp16(whA + doff, GH + goff);
            cp16(wlA + doff, GL + goff);
        }
        CP_COMMIT();
    }
    if (tid < 128) { uS[tid] = g_u[tid]; wS[tid] = g_v[tid] + b_out[tid]; }
    CP_WAIT0();
    __syncthreads();

    // stats over c (four threads per pixel, 32 channels each)
    const int p = tid & 127, quarter = tid >> 7;
    {
        float s = 0.f, ss = 0.f;
#pragma unroll 8
        for (int c = quarter * 32; c < quarter * 32 + 32; ++c) {
            float v = __bfloat162float(Xh[c * PIT + p]) +
                      __bfloat162float(Xl[c * PIT + p]);
            s += v; ss += v * v;
        }
        redS[tid] = s; redQ[tid] = ss;
    }
    __syncthreads();
    if (tid < 128) {
        float S  = redS[tid] + redS[tid + 128] + redS[tid + 256] + redS[tid + 384];
        float Qv = redQ[tid] + redQ[tid + 128] + redQ[tid + 256] + redQ[tid + 384];
        float mu = S * 0.0078125f;
        float rs = rsqrtf(Qv * 0.0078125f - mu * mu + 1e-5f);
        rsS[tid] = rs;
        tS[tid]  = mu * rs;
    }
    __syncthreads();

    const int wm = wid & 3, wn = wid >> 2;
    const uint32_t xh = smem_u32(Xh), xl = smem_u32(Xl);
    const uint32_t wh = smem_u32(Wh), wl = smem_u32(Wl);

    float acc[2][4][4];
#pragma unroll
    for (int a = 0; a < 2; ++a)
#pragma unroll
        for (int b = 0; b < 4; ++b)
#pragma unroll
            for (int q = 0; q < 4; ++q) acc[a][b][q] = 0.f;

    const int at_row = (lane & 7) + ((lane >> 4) << 3);
    const int at_col = ((lane >> 3) & 1) << 3;
    const int bt_row = (lane & 7) + (((lane >> 3) & 1) << 3);
    const int bt_col = (lane >> 4) << 3;

#pragma unroll
    for (int k16 = 0; k16 < 8; ++k16) {
        const int kb = k16 * 16;
        uint32_t bh[4][2], bl[4][2];
#pragma unroll
        for (int ng = 0; ng < 2; ++ng) {
            uint32_t r4[4];
            uint32_t boff = (uint32_t)((kb + bt_row) * PITB) +
                            (wn * 32 + ng * 16 + bt_col) * 2;
            ldsm4_t(wh + boff, r4);
            bh[ng*2][0] = r4[0]; bh[ng*2][1] = r4[1];
            bh[ng*2+1][0] = r4[2]; bh[ng*2+1][1] = r4[3];
            ldsm4_t(wl + boff, r4);
            bl[ng*2][0] = r4[0]; bl[ng*2][1] = r4[1];
            bl[ng*2+1][0] = r4[2]; bl[ng*2+1][1] = r4[3];
        }
        uint32_t ah[2][4], al[2][4];
#pragma unroll
        for (int mt = 0; mt < 2; ++mt) {
            uint32_t aoff = (uint32_t)((kb + at_row) * PITB) +
                            (wm * 32 + mt * 16 + at_col) * 2;
            ldsm4_t(xh + aoff, ah[mt]);
            ldsm4_t(xl + aoff, al[mt]);
        }
#pragma unroll
        for (int mt = 0; mt < 2; ++mt)
#pragma unroll
            for (int nt = 0; nt < 4; ++nt) {
                mma_bf16(acc[mt][nt], ah[mt], bh[nt]);
                mma_bf16(acc[mt][nt], ah[mt], bl[nt]);
                mma_bf16(acc[mt][nt], al[mt], bh[nt]);
            }
    }

    // epilogue: y = rs*acc - t*u + w ; out = y * g
#pragma unroll
    for (int mt = 0; mt < 2; ++mt) {
        int pl = wm * 32 + mt * 16 + (lane >> 2);
        int p0 = pix0 + pl;
        float rs0 = rsS[pl],     t0 = tS[pl];
        float rs1 = rsS[pl + 8], t1 = tS[pl + 8];
#pragma unroll
        for (int nt = 0; nt < 4; ++nt) {
            int ch = wn * 32 + nt * 8 + (lane & 3) * 2;
            float u0 = uS[ch], u1 = uS[ch + 1];
            float w0 = wS[ch], w1 = wS[ch + 1];
            float2 g0 = *(const float2*)(g_g + (size_t)p0 * CDIM + ch);
            float2 g1 = *(const float2*)(g_g + (size_t)(p0 + 8) * CDIM + ch);
            float2 v0 = make_float2((rs0 * acc[mt][nt][0] - t0 * u0 + w0) * g0.x,
                                    (rs0 * acc[mt][nt][1] - t0 * u1 + w1) * g0.y);
            float2 v1 = make_float2((rs1 * acc[mt][nt][2] - t1 * u0 + w0) * g1.x,
                                    (rs1 * acc[mt][nt][3] - t1 * u1 + w1) * g1.y);
            *(float2*)(out + (size_t)p0 * CDIM + ch) = v0;
            *(float2*)(out + (size_t)(p0 + 8) * CDIM + ch) = v1;
        }
    }
}

// ---------------------------------------------------------------------------
extern "C" void kernel_launch(void* const* d_in, const int* in_sizes, int n_in,
                              void* d_out, int out_size)
{
    const float* z        = (const float*)d_in[0];
    const float* mask     = (const float*)d_in[1];
    const float* ln_in_s  = (const float*)d_in[2];
    const float* ln_in_b  = (const float*)d_in[3];
    const float* w_left   = (const float*)d_in[4];
    const float* b_left   = (const float*)d_in[5];
    const float* w_right  = (const float*)d_in[6];
    const float* b_right  = (const float*)d_in[7];
    const float* w_lgate  = (const float*)d_in[8];
    const float* b_lgate  = (const float*)d_in[9];
    const float* w_rgate  = (const float*)d_in[10];
    const float* b_rgate  = (const float*)d_in[11];
    const float* ln_out_s = (const float*)d_in[12];
    const float* ln_out_b = (const float*)d_in[13];
    const float* w_out    = (const float*)d_in[14];
    const float* b_out    = (const float*)d_in[15];
    const float* w_gate   = (const float*)d_in[16];
    const float* b_gate   = (const float*)d_in[17];
    float* out = (float*)d_out;

    const int smem1 = 6 * 128 * PIT * 2 + 768 * 4;           // ~212 KB
    const int smem2 = 3 * (int)K2S;                          // 196608
    const int smem3 = 4 * 128 * PIT * 2 + 1536 * 4;          // ~145 KB

    cudaFuncSetAttribute(k1_all, cudaFuncAttributeMaxDynamicSharedMemorySize, smem1);
    cudaFuncSetAttribute(k2_mma, cudaFuncAttributeMaxDynamicSharedMemorySize, smem2);
    cudaFuncSetAttribute(k3_mma, cudaFuncAttributeMaxDynamicSharedMemorySize, smem3);

    // 0) pre-split weights (w_out scaled by ln_out_scale) + u/v fold vectors
    k0_split<<<97, 256>>>(w_lgate, w_left, w_rgate, w_right, w_gate, w_out,
                          ln_out_s, ln_out_b);

    // 1) a, b projections from a single LN pass
    k1_all<<<NN / 128, NT, smem1>>>(
        z, mask, ln_in_s, ln_in_b,
        b_lgate, b_left, b_rgate, b_right);

    // 2) triangular einsum per channel + interleaved g projection
    k2_mma<<<dim3(4, 4, 160), NT, smem2>>>(z, ln_in_s, ln_in_b, b_gate);

    // 3) folded-LN out projection + gating
    k3_mma<<<NN / 128, NT, smem3>>>(b_out, out);
}

// round 9
// speedup vs baseline: 1.0435x; 1.0435x over previous
#include <cuda_runtime.h>
#include <cuda_bf16.h>
#include <math.h>
#include <stddef.h>
#include <stdint.h>

// Triangle multiplicative update (outgoing), N=512, cz=ch=128, fp32 in/out.
// All GEMMs on tensor cores via mma.sync bf16 hi/lo split (3 passes, fp32 acc).
// Round 9: round-7 k1 (3-phase a/b/g) + round-8 k3 LN-fold + pure einsum k2
//          with bf16 hi/lo x output.

#define NSEQ 512
#define CDIM 128
#define NN   (NSEQ*NSEQ)          // 262144
#define PIT  136                  // bf16 smem pitch (elements)
#define PITB 272                  // bytes
#define NT   512                  // threads per CTA

__device__ __nv_bfloat16 g_a_hi[(size_t)CDIM * NN];
__device__ __nv_bfloat16 g_a_lo[(size_t)CDIM * NN];
__device__ __nv_bfloat16 g_b_hi[(size_t)CDIM * NN];
__device__ __nv_bfloat16 g_b_lo[(size_t)CDIM * NN];
__device__ float g_g[(size_t)NN * CDIM];            // g[pix][c]
__device__ __nv_bfloat16 g_xh[(size_t)CDIM * NN];   // x hi [c][i][j]
__device__ __nv_bfloat16 g_xl[(size_t)CDIM * NN];   // x lo
// pre-split weights: 0=lgate 1=left 2=rgate 3=right 4=gate 5=out(.scaled)
__device__ __align__(16) __nv_bfloat16 g_wh[6 * 16384];
__device__ __align__(16) __nv_bfloat16 g_wl[6 * 16384];
__device__ float g_u[128];   // sum_c s[c]*w_out[c][n]
__device__ float g_v[128];   // sum_c b_ln[c]*w_out[c][n]

__device__ __forceinline__ float sigmf(float x) {
    return 1.0f / (1.0f + __expf(-x));
}
__device__ __forceinline__ unsigned pk_bf16x2(float a, float b) {
    __nv_bfloat162 t = __floats2bfloat162_rn(a, b);
    return *reinterpret_cast<unsigned*>(&t);
}
__device__ __forceinline__ float bf16_res(float v) {   // v - bf16(v)
    return v - __bfloat162float(__float2bfloat16(v));
}
__device__ __forceinline__ uint32_t smem_u32(const void* p) {
    uint32_t a;
    asm("{ .reg .u64 t; cvta.to.shared.u64 t, %1; cvt.u32.u64 %0, t; }"
        : "=r"(a) : "l"(p));
    return a;
}
__device__ __forceinline__ void cp16(uint32_t dst, const void* src) {
    asm volatile("cp.async.cg.shared.global [%0], [%1], 16;"
                 :: "r"(dst), "l"(src) : "memory");
}
#define CP_COMMIT() asm volatile("cp.async.commit_group;" ::: "memory")
#define CP_WAIT0()  asm volatile("cp.async.wait_group 0;" ::: "memory")
#define SWZ(o) ((o) ^ (((o) >> 3) & 0x70))

__device__ __forceinline__ void ldsm4(uint32_t addr, uint32_t* r) {
    asm volatile("ldmatrix.sync.aligned.m8n8.x4.shared.b16 {%0,%1,%2,%3}, [%4];"
                 : "=r"(r[0]), "=r"(r[1]), "=r"(r[2]), "=r"(r[3]) : "r"(addr));
}
__device__ __forceinline__ void ldsm4_t(uint32_t addr, uint32_t* r) {
    asm volatile("ldmatrix.sync.aligned.m8n8.x4.trans.shared.b16 {%0,%1,%2,%3}, [%4];"
                 : "=r"(r[0]), "=r"(r[1]), "=r"(r[2]), "=r"(r[3]) : "r"(addr));
}
__device__ __forceinline__ void mma_bf16(float* c, const uint32_t* a,
                                         const uint32_t* b) {
    asm volatile(
        "mma.sync.aligned.m16n8k16.row.col.f32.bf16.bf16.f32 "
        "{%0,%1,%2,%3}, {%4,%5,%6,%7}, {%8,%9}, {%0,%1,%2,%3};"
        : "+f"(c[0]), "+f"(c[1]), "+f"(c[2]), "+f"(c[3])
        : "r"(a[0]), "r"(a[1]), "r"(a[2]), "r"(a[3]), "r"(b[0]), "r"(b[1]));
}

__device__ __forceinline__ void split4(float4 v, uint2& hv, uint2& lv) {
    hv.x = pk_bf16x2(v.x, v.y);
    hv.y = pk_bf16x2(v.z, v.w);
    lv.x = pk_bf16x2(bf16_res(v.x), bf16_res(v.y));
    lv.y = pk_bf16x2(bf16_res(v.z), bf16_res(v.w));
}

// ---------------------------------------------------------------------------
// Kernel 0: pre-split 6 weight matrices (w_out pre-scaled by ln_out_scale),
// plus u/v fold vectors. Grid 97 x 256.
// ---------------------------------------------------------------------------
__global__ void __launch_bounds__(256)
k0_split(const float* __restrict__ w0, const float* __restrict__ w1,
         const float* __restrict__ w2, const float* __restrict__ w3,
         const float* __restrict__ w4, const float* __restrict__ w5,
         const float* __restrict__ so, const float* __restrict__ bo)
{
    if (blockIdx.x == 96) {
        int n = threadIdx.x;
        if (n < 128) {
            float u = 0.f, v = 0.f;
            for (int c = 0; c < 128; ++c) {
                float w = w5[c * 128 + n];
                u += so[c] * w;
                v += bo[c] * w;
            }
            g_u[n] = u; g_v[n] = v;
        }
        return;
    }
    const float* ws[6] = {w0, w1, w2, w3, w4, w5};
    int idx = blockIdx.x * 256 + threadIdx.x;   // 24576 threads
    int m = idx >> 12;
    int e = (idx & 4095) * 4;
    float4 v = *(const float4*)(ws[m] + e);
    if (m == 5) {
        float sc = so[e >> 7];
        v.x *= sc; v.y *= sc; v.z *= sc; v.w *= sc;
    }
    uint2 hv, lv;
    split4(v, hv, lv);
    *(uint2*)(g_wh + m * 16384 + e) = hv;
    *(uint2*)(g_wl + m * 16384 + e) = lv;
}

// ---------------------------------------------------------------------------
// Kernel 1: one LN pass, three projection phases (a, b, g) per 128-px tile.
// Weight restaging for the next phase is overlapped with the current epilogue.
// 16 warps: 4 (M) x 4 (N); warp tile 32x32.
// ---------------------------------------------------------------------------
__global__ void __launch_bounds__(NT, 1)
k1_all(const float* __restrict__ z, const float* __restrict__ mask,
       const float* __restrict__ ln_s, const float* __restrict__ ln_b,
       const float* __restrict__ b_lg, const float* __restrict__ b_l,
       const float* __restrict__ b_rg, const float* __restrict__ b_r,
       const float* __restrict__ b_g)
{
    extern __shared__ char smraw[];
    __nv_bfloat16* znh = (__nv_bfloat16*)smraw;           // [p][k] pitch 136
    __nv_bfloat16* znl = znh + 128 * PIT;
    __nv_bfloat16* W0h = znl + 128 * PIT;                 // gate weights
    __nv_bfloat16* W0l = W0h + 128 * PIT;
    __nv_bfloat16* W1h = W0l + 128 * PIT;                 // value weights
    __nv_bfloat16* W1l = W1h + 128 * PIT;
    float* bs = (float*)(W1l + 128 * PIT);
    // bs: [0)lg [128)l [256)rg [384)r [512)g [640)mask

    const int tid = threadIdx.x, lane = tid & 31, wid = tid >> 5;
    const int pix0 = blockIdx.x * 128;

    const uint32_t w0hA = smem_u32(W0h), w0lA = smem_u32(W0l);
    const uint32_t w1hA = smem_u32(W1h), w1lA = smem_u32(W1l);

#define STAGE_W(mi, dsth, dstl)                                               \
    do {                                                                      \
        const __nv_bfloat16* SH = g_wh + (mi) * 16384;                        \
        const __nv_bfloat16* SL = g_wl + (mi) * 16384;                        \
        _Pragma("unroll")                                                     \
        for (int t = 0; t < 4; ++t) {                                         \
            int u = tid + t * NT;                                             \
            int r = u >> 4, c = u & 15;                                       \
            uint32_t doff = (uint32_t)(r * PITB + c * 16);                    \
            int goff = r * 128 + c * 8;                                       \
            cp16((dsth) + doff, SH + goff);                                   \
            cp16((dstl) + doff, SL + goff);                                   \
        }                                                                     \
    } while (0)

    STAGE_W(0, w0hA, w0lA);
    STAGE_W(1, w1hA, w1lA);
    CP_COMMIT();

    {
        int which = tid >> 7, r = tid & 127;
        const float* bp[4] = {b_lg, b_l, b_rg, b_r};
        bs[tid] = bp[which][r];
        if (tid < 128) { bs[512 + tid] = b_g[tid]; bs[640 + tid] = mask[pix0 + tid]; }
    }

    // LayerNorm (overlaps with weight cp.async)
    {
        float4 s4 = ((const float4*)ln_s)[lane];
        float4 b4 = ((const float4*)ln_b)[lane];
        float4 v[8];
#pragma unroll
        for (int t = 0; t < 8; ++t)
            v[t] = ((const float4*)(z + (size_t)(pix0 + t * 16 + wid) * CDIM))[lane];
#pragma unroll
        for (int t = 0; t < 8; ++t) {
            int r = t * 16 + wid;
            float s  = v[t].x + v[t].y + v[t].z + v[t].w;
            float ss = v[t].x*v[t].x + v[t].y*v[t].y + v[t].z*v[t].z + v[t].w*v[t].w;
#pragma unroll
            for (int o = 16; o > 0; o >>= 1) {
                s  += __shfl_xor_sync(0xffffffffu, s,  o);
                ss += __shfl_xor_sync(0xffffffffu, ss, o);
            }
            float mu   = s * 0.0078125f;
            float rstd = rsqrtf(ss * 0.0078125f - mu * mu + 1e-5f);
            float4 o4;
            o4.x = (v[t].x - mu) * rstd * s4.x + b4.x;
            o4.y = (v[t].y - mu) * rstd * s4.y + b4.y;
            o4.z = (v[t].z - mu) * rstd * s4.z + b4.z;
            o4.w = (v[t].w - mu) * rstd * s4.w + b4.w;
            uint2 hv, lv;
            split4(o4, hv, lv);
            *(uint2*)(&znh[r * PIT + lane * 4]) = hv;
            *(uint2*)(&znl[r * PIT + lane * 4]) = lv;
        }
    }
    CP_WAIT0();
    __syncthreads();

    const int wm = wid & 3, wn = wid >> 2;   // 4 (M) x 4 (N) warp grid
    const uint32_t zh = smem_u32(znh), zl = smem_u32(znl);

    // ldmatrix lane mappings
    const int at_row = (lane & 7) + ((lane >> 4) << 3);      // trans A (W^T)
    const int at_col = ((lane >> 3) & 1) << 3;
    const int bp_row = wn * 32 + (lane & 7) + ((lane >> 4) << 3);  // non-trans B (zn)
    const uint32_t bko = ((lane >> 3) & 1) * 16;

    // ---- phases A (a) and B (b): gated, C[ch][p] orientation ----
#pragma unroll 1
    for (int ph = 0; ph < 2; ++ph) {
        float P[2][4][4], Q[2][4][4];
#pragma unroll
        for (int a = 0; a < 2; ++a)
#pragma unroll
            for (int b = 0; b < 4; ++b)
#pragma unroll
                for (int q = 0; q < 4; ++q) { P[a][b][q] = 0.f; Q[a][b][q] = 0.f; }

#pragma unroll
        for (int k16 = 0; k16 < 8; ++k16) {
            const int kb = k16 * 16;
            uint32_t bh[4][2], bl[4][2];
#pragma unroll
            for (int ng = 0; ng < 2; ++ng) {
                uint32_t r4[4];
                uint32_t boff = (uint32_t)((bp_row + ng * 16) * PITB) + kb * 2 + bko;
                ldsm4(zh + boff, r4);
                bh[ng*2][0] = r4[0]; bh[ng*2][1] = r4[1];
                bh[ng*2+1][0] = r4[2]; bh[ng*2+1][1] = r4[3];
                ldsm4(zl + boff, r4);
                bl[ng*2][0] = r4[0]; bl[ng*2][1] = r4[1];
                bl[ng*2+1][0] = r4[2]; bl[ng*2+1][1] = r4[3];
            }
            uint32_t aoff[2];
#pragma unroll
            for (int mt = 0; mt < 2; ++mt)
                aoff[mt] = (uint32_t)((kb + at_row) * PITB) +
                           (wm * 32 + mt * 16 + at_col) * 2;
            uint32_t a[2][4];
#pragma unroll
            for (int mt = 0; mt < 2; ++mt) ldsm4_t(w0hA + aoff[mt], a[mt]);
#pragma unroll
            for (int mt = 0; mt < 2; ++mt)
#pragma unroll
                for (int nt = 0; nt < 4; ++nt) {
                    mma_bf16(P[mt][nt], a[mt], bh[nt]);
                    mma_bf16(P[mt][nt], a[mt], bl[nt]);
                }
#pragma unroll
            for (int mt = 0; mt < 2; ++mt) ldsm4_t(w0lA + aoff[mt], a[mt]);
#pragma unroll
            for (int mt = 0; mt < 2; ++mt)
#pragma unroll
                for (int nt = 0; nt < 4; ++nt)
                    mma_bf16(P[mt][nt], a[mt], bh[nt]);
#pragma unroll
            for (int mt = 0; mt < 2; ++mt) ldsm4_t(w1hA + aoff[mt], a[mt]);
#pragma unroll
            for (int mt = 0; mt < 2; ++mt)
#pragma unroll
                for (int nt = 0; nt < 4; ++nt) {
                    mma_bf16(Q[mt][nt], a[mt], bh[nt]);
                    mma_bf16(Q[mt][nt], a[mt], bl[nt]);
                }
#pragma unroll
            for (int mt = 0; mt < 2; ++mt) ldsm4_t(w1lA + aoff[mt], a[mt]);
#pragma unroll
            for (int mt = 0; mt < 2; ++mt)
#pragma unroll
                for (int nt = 0; nt < 4; ++nt)
                    mma_bf16(Q[mt][nt], a[mt], bh[nt]);
        }

        __syncthreads();   // all warps done reading W0/W1
        if (ph == 0) { STAGE_W(2, w0hA, w0lA); STAGE_W(3, w1hA, w1lA); CP_COMMIT(); }
        else         { STAGE_W(4, w0hA, w0lA); CP_COMMIT(); }

        const float* bgp = bs + ph * 256;
        const float* bvp = bs + ph * 256 + 128;
        const float* msm = bs + 640;
        __nv_bfloat16* oh = (ph == 0) ? g_a_hi : g_b_hi;
        __nv_bfloat16* ol = (ph == 0) ? g_a_lo : g_b_lo;
#pragma unroll
        for (int mt = 0; mt < 2; ++mt) {
            int ch = wm * 32 + mt * 16 + (lane >> 2);
            float bg0v = bgp[ch], bg1v = bgp[ch + 8];
            float bv0v = bvp[ch], bv1v = bvp[ch + 8];
            size_t r0 = (size_t)ch * NN + pix0;
            size_t r1 = (size_t)(ch + 8) * NN + pix0;
#pragma unroll
            for (int nt = 0; nt < 4; ++nt) {
                int p = wn * 32 + nt * 8 + (lane & 3) * 2;
                float m0 = msm[p], m1 = msm[p + 1];
                float v00 = m0 * sigmf(P[mt][nt][0] + bg0v) * (Q[mt][nt][0] + bv0v);
                float v01 = m1 * sigmf(P[mt][nt][1] + bg0v) * (Q[mt][nt][1] + bv0v);
                float v10 = m0 * sigmf(P[mt][nt][2] + bg1v) * (Q[mt][nt][2] + bv1v);
                float v11 = m1 * sigmf(P[mt][nt][3] + bg1v) * (Q[mt][nt][3] + bv1v);
                *(uint32_t*)(oh + r0 + p) = pk_bf16x2(v00, v01);
                *(uint32_t*)(ol + r0 + p) = pk_bf16x2(bf16_res(v00), bf16_res(v01));
                *(uint32_t*)(oh + r1 + p) = pk_bf16x2(v10, v11);
                *(uint32_t*)(ol + r1 + p) = pk_bf16x2(bf16_res(v10), bf16_res(v11));
            }
        }
        CP_WAIT0();
        __syncthreads();
    }

    // ---- phase C: g = sig(zn @ Wg + bg), C[p][ch] orientation ----
    {
        const int a_row = wm * 32 + (lane & 15);
        const uint32_t ako = (lane >> 4) * 16;
        const int bt_row = (lane & 7) + (((lane >> 3) & 1) << 3);
        const int bt_col = (lane >> 4) << 3;

        float P[2][4][4];
#pragma unroll
        for (int a = 0; a < 2; ++a)
#pragma unroll
            for (int b = 0; b < 4; ++b)
#pragma unroll
                for (int q = 0; q < 4; ++q) P[a][b][q] = 0.f;

#pragma unroll
        for (int k16 = 0; k16 < 8; ++k16) {
            const int kb = k16 * 16;
            uint32_t bh[4][2], bl[4][2];
#pragma unroll
            for (int ng = 0; ng < 2; ++ng) {
                uint32_t r4[4];
                uint32_t boff = (uint32_t)((kb + bt_row) * PITB) +
                                (wn * 32 + ng * 16 + bt_col) * 2;
                ldsm4_t(w0hA + boff, r4);
                bh[ng*2][0] = r4[0]; bh[ng*2][1] = r4[1];
                bh[ng*2+1][0] = r4[2]; bh[ng*2+1][1] = r4[3];
                ldsm4_t(w0lA + boff, r4);
                bl[ng*2][0] = r4[0]; bl[ng*2][1] = r4[1];
                bl[ng*2+1][0] = r4[2]; bl[ng*2+1][1] = r4[3];
            }
            uint32_t ah[2][4], al[2][4];
#pragma unroll
            for (int mt = 0; mt < 2; ++mt) {
                uint32_t aoff = (uint32_t)((a_row + mt * 16) * PITB) + kb * 2 + ako;
                ldsm4(zh + aoff, ah[mt]);
                ldsm4(zl + aoff, al[mt]);
            }
#pragma unroll
            for (int mt = 0; mt < 2; ++mt)
#pragma unroll
                for (int nt = 0; nt < 4; ++nt) {
                    mma_bf16(P[mt][nt], ah[mt], bh[nt]);
                    mma_bf16(P[mt][nt], ah[mt], bl[nt]);
                    mma_bf16(P[mt][nt], al[mt], bh[nt]);
                }
        }

        const float* bgp = bs + 512;
#pragma unroll
        for (int mt = 0; mt < 2; ++mt) {
            int p0 = pix0 + wm * 32 + mt * 16 + (lane >> 2);
#pragma unroll
            for (int nt = 0; nt < 4; ++nt) {
                int ch = wn * 32 + nt * 8 + (lane & 3) * 2;
                float b0 = bgp[ch], b1 = bgp[ch + 1];
                float2 v0 = make_float2(sigmf(P[mt][nt][0] + b0),
                                        sigmf(P[mt][nt][1] + b1));
                float2 v1 = make_float2(sigmf(P[mt][nt][2] + b0),
                                        sigmf(P[mt][nt][3] + b1));
                *(float2*)(g_g + (size_t)p0 * CDIM + ch) = v0;
                *(float2*)(g_g + (size_t)(p0 + 8) * CDIM + ch) = v1;
            }
        }
    }
#undef STAGE_W
}

// ---------------------------------------------------------------------------
// Kernel 2: per-channel X_c = A_c @ B_c^T via mma.sync bf16 hi/lo split.
// 3-stage cp.async pipeline; epilogue writes x as bf16 hi/lo.
// ---------------------------------------------------------------------------
#define K2S 65536u

__global__ void __launch_bounds__(NT, 1)
k2_mma()
{
    extern __shared__ char sm2[];
    const uint32_t smb = smem_u32(sm2);
    const int tid  = threadIdx.x;
    const int lane = tid & 31, wid = tid >> 5;
    const int wm = wid & 3, wn = wid >> 2;
    const int i0 = blockIdx.x * 128, j0 = blockIdx.y * 128;
    const size_t cbase = (size_t)blockIdx.z * NN;

    const __nv_bfloat16* Ah = g_a_hi + cbase + (size_t)i0 * NSEQ;
    const __nv_bfloat16* Al = g_a_lo + cbase + (size_t)i0 * NSEQ;
    const __nv_bfloat16* Bh = g_b_hi + cbase + (size_t)j0 * NSEQ;
    const __nv_bfloat16* Bl = g_b_lo + cbase + (size_t)j0 * NSEQ;

    float acc[2][4][4];
#pragma unroll
    for (int mt = 0; mt < 2; ++mt)
#pragma unroll
        for (int nt = 0; nt < 4; ++nt)
#pragma unroll
            for (int q = 0; q < 4; ++q) acc[mt][nt][q] = 0.f;

    const int arow = wm * 32 + (lane & 15);
    const int bnr  = wn * 32 + (lane & 7) + ((lane >> 4) << 3);
    const uint32_t a_koff = (uint32_t)((lane >> 4) << 4);
    const uint32_t b_koff = (uint32_t)(((lane >> 3) & 1) << 4);

#define K2_LOAD(kc, stg)                                                      \
    do {                                                                      \
        const int ke = (kc) * 64;                                             \
        _Pragma("unroll")                                                     \
        for (int t = 0; t < 2; ++t) {                                         \
            int v = tid + t * NT; int r = v >> 3, cu = v & 7;                 \
            uint32_t so = SWZ((uint32_t)(r * 128 + cu * 16));                 \
            const size_t go = (size_t)r * NSEQ + ke + cu * 8;                 \
            cp16((stg) + so,           Ah + go);                              \
            cp16((stg) + 16384u + so,  Al + go);                              \
            cp16((stg) + 32768u + so,  Bh + go);                              \
            cp16((stg) + 49152u + so,  Bl + go);                              \
        }                                                                     \
        asm volatile("cp.async.commit_group;" ::: "memory");                  \
    } while (0)

    K2_LOAD(0, smb);
    K2_LOAD(1, smb + K2S);

#pragma unroll 1
    for (int kc = 0; kc < 8; ++kc) {
        if (kc + 2 < 8) K2_LOAD(kc + 2, smb + (uint32_t)((kc + 2) % 3) * K2S);
        if (kc < 6)      asm volatile("cp.async.wait_group 2;" ::: "memory");
        else if (kc == 6) asm volatile("cp.async.wait_group 1;" ::: "memory");
        else              asm volatile("cp.async.wait_group 0;" ::: "memory");
        __syncthreads();
        const uint32_t stg = smb + (uint32_t)(kc % 3) * K2S;

#pragma unroll
        for (int k16 = 0; k16 < 4; ++k16) {
            const uint32_t kbA = (uint32_t)(k16 * 32) + a_koff;
            const uint32_t kbB = (uint32_t)(k16 * 32) + b_koff;
            uint32_t bh[4][2], bl[4][2];
#pragma unroll
            for (int ng = 0; ng < 2; ++ng) {
                uint32_t r4[4];
                uint32_t off = SWZ((uint32_t)((bnr + ng * 16) * 128) + kbB);
                ldsm4(stg + 32768u + off, r4);
                bh[ng * 2 + 0][0] = r4[0]; bh[ng * 2 + 0][1] = r4[1];
                bh[ng * 2 + 1][0] = r4[2]; bh[ng * 2 + 1][1] = r4[3];
                ldsm4(stg + 49152u + off, r4);
                bl[ng * 2 + 0][0] = r4[0]; bl[ng * 2 + 0][1] = r4[1];
                bl[ng * 2 + 1][0] = r4[2]; bl[ng * 2 + 1][1] = r4[3];
            }
#pragma unroll
            for (int mt = 0; mt < 2; ++mt) {
                uint32_t ah[4], al[4];
                uint32_t off = SWZ((uint32_t)((arow + mt * 16) * 128) + kbA);
                ldsm4(stg + off, ah);
                ldsm4(stg + 16384u + off, al);
#pragma unroll
                for (int nt = 0; nt < 4; ++nt) {
                    mma_bf16(acc[mt][nt], ah, bh[nt]);
                    mma_bf16(acc[mt][nt], ah, bl[nt]);
                    mma_bf16(acc[mt][nt], al, bh[nt]);
                }
            }
        }
        __syncthreads();
    }

    // epilogue: split to bf16 hi/lo -> g_xh/g_xl [c][i][j]
    __nv_bfloat16* Xh = g_xh + cbase + (size_t)(i0 + wm * 32) * NSEQ + j0 + wn * 32;
    __nv_bfloat16* Xl = g_xl + cbase + (size_t)(i0 + wm * 32) * NSEQ + j0 + wn * 32;
    const int rr = lane >> 2, cc = (lane & 3) * 2;
#pragma unroll
    for (int mt = 0; mt < 2; ++mt)
#pragma unroll
        for (int nt = 0; nt < 4; ++nt) {
            size_t o0 = (size_t)(mt * 16 + rr) * NSEQ + nt * 8 + cc;
            size_t o1 = o0 + 8 * NSEQ;
            float v0 = acc[mt][nt][0], v1 = acc[mt][nt][1];
            float v2 = acc[mt][nt][2], v3 = acc[mt][nt][3];
            *(uint32_t*)(Xh + o0) = pk_bf16x2(v0, v1);
            *(uint32_t*)(Xl + o0) = pk_bf16x2(bf16_res(v0), bf16_res(v1));
            *(uint32_t*)(Xh + o1) = pk_bf16x2(v2, v3);
            *(uint32_t*)(Xl + o1) = pk_bf16x2(bf16_res(v2), bf16_res(v3));
        }
#undef K2_LOAD
}

// ---------------------------------------------------------------------------
// Kernel 3: folded-LN out projection:
//   y[p][n] = rs[p]*(x@W')[p][n] - rs[p]*mu[p]*u[n] + (v[n]+b_out[n]);
//   out = y * g.
// ---------------------------------------------------------------------------
__global__ void __launch_bounds__(NT, 1)
k3_mma(const float* __restrict__ b_out, float* __restrict__ out)
{
    extern __shared__ char smraw[];
    __nv_bfloat16* Xh = (__nv_bfloat16*)smraw;          // [c][p] pitch 136
    __nv_bfloat16* Xl = Xh + 128 * PIT;
    __nv_bfloat16* Wh = Xl + 128 * PIT;                 // [k][n] pitch 136
    __nv_bfloat16* Wl = Wh + 128 * PIT;
    float* uS   = (float*)(Wl + 128 * PIT);   // 128
    float* wS   = uS + 128;                   // v + b_out, 128
    float* redS = wS + 128;                   // 512
    float* redQ = redS + 512;                 // 512
    float* rsS  = redQ + 512;                 // 128
    float* tS   = rsS + 128;                  // 128 (mu*rs)

    const int tid = threadIdx.x, lane = tid & 31, wid = tid >> 5;
    const int pix0 = blockIdx.x * 128;

    // async stage: x hi/lo tile + pre-split scaled w_out
    {
        const uint32_t xhA = smem_u32(Xh), xlA = smem_u32(Xl);
        const uint32_t whA = smem_u32(Wh), wlA = smem_u32(Wl);
        const __nv_bfloat16* GH = g_wh + 5 * 16384;
        const __nv_bfloat16* GL = g_wl + 5 * 16384;
#pragma unroll
        for (int t = 0; t < 4; ++t) {
            int u = tid + t * NT;
            int c = u >> 4, q = u & 15;
            uint32_t doff = (uint32_t)(c * PITB + q * 16);
            size_t goff = (size_t)c * NN + pix0 + q * 8;
            cp16(xhA + doff, g_xh + goff);
            cp16(xlA + doff, g_xl + goff);
        }
#pragma unroll
        for (int t = 0; t < 4; ++t) {
            int u = tid + t * NT;
            int r = u >> 4, c = u & 15;
            uint32_t doff = (uint32_t)(r * PITB + c * 16);
            int goff = r * 128 + c * 8;
            cp16(whA + doff, GH + goff);
            cp16(wlA + doff, GL + goff);
        }
        CP_COMMIT();
    }
    if (tid < 128) { uS[tid] = g_u[tid]; wS[tid] = g_v[tid] + b_out[tid]; }
    CP_WAIT0();
    __syncthreads();

    // stats over c (four threads per pixel, 32 channels each)
    const int p = tid & 127, quarter = tid >> 7;
    {
        float s = 0.f, ss = 0.f;
#pragma unroll 8
        for (int c = quarter * 32; c < quarter * 32 + 32; ++c) {
            float v = __bfloat162float(Xh[c * PIT + p]) +
                      __bfloat162float(Xl[c * PIT + p]);
            s += v; ss += v * v;
        }
        redS[tid] = s; redQ[tid] = ss;
    }
    __syncthreads();
    if (tid < 128) {
        float S  = redS[tid] + redS[tid + 128] + redS[tid + 256] + redS[tid + 384];
        float Qv = redQ[tid] + redQ[tid + 128] + redQ[tid + 256] + redQ[tid + 384];
        float mu = S * 0.0078125f;
        float rs = rsqrtf(Qv * 0.0078125f - mu * mu + 1e-5f);
        rsS[tid] = rs;
        tS[tid]  = mu * rs;
    }
    __syncthreads();

    const int wm = wid & 3, wn = wid >> 2;
    const uint32_t xh = smem_u32(Xh), xl = smem_u32(Xl);
    const uint32_t wh = smem_u32(Wh), wl = smem_u32(Wl);

    float acc[2][4][4];
#pragma unroll
    for (int a = 0; a < 2; ++a)
#pragma unroll
        for (int b = 0; b < 4; ++b)
#pragma unroll
            for (int q = 0; q < 4; ++q) acc[a][b][q] = 0.f;

    const int at_row = (lane & 7) + ((lane >> 4) << 3);
    const int at_col = ((lane >> 3) & 1) << 3;
    const int bt_row = (lane & 7) + (((lane >> 3) & 1) << 3);
    const int bt_col = (lane >> 4) << 3;

#pragma unroll
    for (int k16 = 0; k16 < 8; ++k16) {
        const int kb = k16 * 16;
        uint32_t bh[4][2], bl[4][2];
#pragma unroll
        for (int ng = 0; ng < 2; ++ng) {
            uint32_t r4[4];
            uint32_t boff = (uint32_t)((kb + bt_row) * PITB) +
                            (wn * 32 + ng * 16 + bt_col) * 2;
            ldsm4_t(wh + boff, r4);
            bh[ng*2][0] = r4[0]; bh[ng*2][1] = r4[1];
            bh[ng*2+1][0] = r4[2]; bh[ng*2+1][1] = r4[3];
            ldsm4_t(wl + boff, r4);
            bl[ng*2][0] = r4[0]; bl[ng*2][1] = r4[1];
            bl[ng*2+1][0] = r4[2]; bl[ng*2+1][1] = r4[3];
        }
        uint32_t ah[2][4], al[2][4];
#pragma unroll
        for (int mt = 0; mt < 2; ++mt) {
            uint32_t aoff = (uint32_t)((kb + at_row) * PITB) +
                            (wm * 32 + mt * 16 + at_col) * 2;
            ldsm4_t(xh + aoff, ah[mt]);
            ldsm4_t(xl + aoff, al[mt]);
        }
#pragma unroll
        for (int mt = 0; mt < 2; ++mt)
#pragma unroll
            for (int nt = 0; nt < 4; ++nt) {
                mma_bf16(acc[mt][nt], ah[mt], bh[nt]);
                mma_bf16(acc[mt][nt], ah[mt], bl[nt]);
                mma_bf16(acc[mt][nt], al[mt], bh[nt]);
            }
    }

    // epilogue: y = rs*acc - t*u + w ; out = y * g
#pragma unroll
    for (int mt = 0; mt < 2; ++mt) {
        int pl = wm * 32 + mt * 16 + (lane >> 2);
        int p0 = pix0 + pl;
        float rs0 = rsS[pl],     t0 = tS[pl];
        float rs1 = rsS[pl + 8], t1 = tS[pl + 8];
#pragma unroll
        for (int nt = 0; nt < 4; ++nt) {
            int ch = wn * 32 + nt * 8 + (lane & 3) * 2;
            float u0 = uS[ch], u1 = uS[ch + 1];
            float w0 = wS[ch], w1 = wS[ch + 1];
            float2 g0 = *(const float2*)(g_g + (size_t)p0 * CDIM + ch);
            float2 g1 = *(const float2*)(g_g + (size_t)(p0 + 8) * CDIM + ch);
            float2 v0 = make_float2((rs0 * acc[mt][nt][0] - t0 * u0 + w0) * g0.x,
                                    (rs0 * acc[mt][nt][1] - t0 * u1 + w1) * g0.y);
            float2 v1 = make_float2((rs1 * acc[mt][nt][2] - t1 * u0 + w0) * g1.x,
                                    (rs1 * acc[mt][nt][3] - t1 * u1 + w1) * g1.y);
            *(float2*)(out + (size_t)p0 * CDIM + ch) = v0;
            *(float2*)(out + (size_t)(p0 + 8) * CDIM + ch) = v1;
        }
    }
}

// ---------------------------------------------------------------------------
extern "C" void kernel_launch(void* const* d_in, const int* in_sizes, int n_in,
                              void* d_out, int out_size)
{
    const float* z        = (const float*)d_in[0];
    const float* mask     = (const float*)d_in[1];
    const float* ln_in_s  = (const float*)d_in[2];
    const float* ln_in_b  = (const float*)d_in[3];
    const float* w_left   = (const float*)d_in[4];
    const float* b_left   = (const float*)d_in[5];
    const float* w_right  = (const float*)d_in[6];
    const float* b_right  = (const float*)d_in[7];
    const float* w_lgate  = (const float*)d_in[8];
    const float* b_lgate  = (const float*)d_in[9];
    const float* w_rgate  = (const float*)d_in[10];
    const float* b_rgate  = (const float*)d_in[11];
    const float* ln_out_s = (const float*)d_in[12];
    const float* ln_out_b = (const float*)d_in[13];
    const float* w_out    = (const float*)d_in[14];
    const float* b_out    = (const float*)d_in[15];
    const float* w_gate   = (const float*)d_in[16];
    const float* b_gate   = (const float*)d_in[17];
    float* out = (float*)d_out;

    const int smem1 = 6 * 128 * PIT * 2 + 768 * 4;           // ~212 KB
    const int smem2 = 3 * (int)K2S;                          // 196608
    const int smem3 = 4 * 128 * PIT * 2 + 1536 * 4;          // ~145 KB

    cudaFuncSetAttribute(k1_all, cudaFuncAttributeMaxDynamicSharedMemorySize, smem1);
    cudaFuncSetAttribute(k2_mma, cudaFuncAttributeMaxDynamicSharedMemorySize, smem2);
    cudaFuncSetAttribute(k3_mma, cudaFuncAttributeMaxDynamicSharedMemorySize, smem3);

    // 0) pre-split weights (w_out scaled by ln_out_scale) + u/v fold vectors
    k0_split<<<97, 256>>>(w_lgate, w_left, w_rgate, w_right, w_gate, w_out,
                          ln_out_s, ln_out_b);

    // 1) a, b, g projections from a single LN pass
    k1_all<<<NN / 128, NT, smem1>>>(
        z, mask, ln_in_s, ln_in_b,
        b_lgate, b_left, b_rgate, b_right, b_gate);

    // 2) triangular einsum per channel
    k2_mma<<<dim3(4, 4, CDIM), NT, smem2>>>();

    // 3) folded-LN out projection + gating
    k3_mma<<<NN / 128, NT, smem3>>>(b_out, out);
}

// round 10
// speedup vs baseline: 1.0562x; 1.0122x over previous
#include <cuda_runtime.h>
#include <cuda_bf16.h>
#include <cuda_fp16.h>
#include <math.h>
#include <stddef.h>
#include <stdint.h>

// Triangle multiplicative update (outgoing), N=512, cz=ch=128, fp32 in/out.
// All GEMMs on tensor cores via mma.sync bf16 hi/lo split (3 passes, fp32 acc).
// Round 10: MMA sweep-reordering (independent dep chains), g stored fp16,
//           k3 prefetches g via cp.async.

#define NSEQ 512
#define CDIM 128
#define NN   (NSEQ*NSEQ)          // 262144
#define PIT  136                  // bf16 smem pitch (elements)
#define PITB 272                  // bytes
#define NT   512                  // threads per CTA

__device__ __nv_bfloat16 g_a_hi[(size_t)CDIM * NN];
__device__ __nv_bfloat16 g_a_lo[(size_t)CDIM * NN];
__device__ __nv_bfloat16 g_b_hi[(size_t)CDIM * NN];
__device__ __nv_bfloat16 g_b_lo[(size_t)CDIM * NN];
__device__ __half g_g[(size_t)NN * CDIM];           // g[pix][c] fp16
__device__ __nv_bfloat16 g_xh[(size_t)CDIM * NN];   // x hi [c][i][j]
__device__ __nv_bfloat16 g_xl[(size_t)CDIM * NN];   // x lo
// pre-split weights: 0=lgate 1=left 2=rgate 3=right 4=gate 5=out(.scaled)
__device__ __align__(16) __nv_bfloat16 g_wh[6 * 16384];
__device__ __align__(16) __nv_bfloat16 g_wl[6 * 16384];
__device__ float g_u[128];   // sum_c s[c]*w_out[c][n]
__device__ float g_v[128];   // sum_c b_ln[c]*w_out[c][n]

__device__ __forceinline__ float sigmf(float x) {
    return 1.0f / (1.0f + __expf(-x));
}
__device__ __forceinline__ unsigned pk_bf16x2(float a, float b) {
    __nv_bfloat162 t = __floats2bfloat162_rn(a, b);
    return *reinterpret_cast<unsigned*>(&t);
}
__device__ __forceinline__ float bf16_res(float v) {   // v - bf16(v)
    return v - __bfloat162float(__float2bfloat16(v));
}
__device__ __forceinline__ uint32_t smem_u32(const void* p) {
    uint32_t a;
    asm("{ .reg .u64 t; cvta.to.shared.u64 t, %1; cvt.u32.u64 %0, t; }"
        : "=r"(a) : "l"(p));
    return a;
}
__device__ __forceinline__ void cp16(uint32_t dst, const void* src) {
    asm volatile("cp.async.cg.shared.global [%0], [%1], 16;"
                 :: "r"(dst), "l"(src) : "memory");
}
#define CP_COMMIT() asm volatile("cp.async.commit_group;" ::: "memory")
#define CP_WAIT0()  asm volatile("cp.async.wait_group 0;" ::: "memory")
#define SWZ(o) ((o) ^ (((o) >> 3) & 0x70))

__device__ __forceinline__ void ldsm4(uint32_t addr, uint32_t* r) {
    asm volatile("ldmatrix.sync.aligned.m8n8.x4.shared.b16 {%0,%1,%2,%3}, [%4];"
                 : "=r"(r[0]), "=r"(r[1]), "=r"(r[2]), "=r"(r[3]) : "r"(addr));
}
__device__ __forceinline__ void ldsm4_t(uint32_t addr, uint32_t* r) {
    asm volatile("ldmatrix.sync.aligned.m8n8.x4.trans.shared.b16 {%0,%1,%2,%3}, [%4];"
                 : "=r"(r[0]), "=r"(r[1]), "=r"(r[2]), "=r"(r[3]) : "r"(addr));
}
__device__ __forceinline__ void mma_bf16(float* c, const uint32_t* a,
                                         const uint32_t* b) {
    asm volatile(
        "mma.sync.aligned.m16n8k16.row.col.f32.bf16.bf16.f32 "
        "{%0,%1,%2,%3}, {%4,%5,%6,%7}, {%8,%9}, {%0,%1,%2,%3};"
        : "+f"(c[0]), "+f"(c[1]), "+f"(c[2]), "+f"(c[3])
        : "r"(a[0]), "r"(a[1]), "r"(a[2]), "r"(a[3]), "r"(b[0]), "r"(b[1]));
}

__device__ __forceinline__ void split4(float4 v, uint2& hv, uint2& lv) {
    hv.x = pk_bf16x2(v.x, v.y);
    hv.y = pk_bf16x2(v.z, v.w);
    lv.x = pk_bf16x2(bf16_res(v.x), bf16_res(v.y));
    lv.y = pk_bf16x2(bf16_res(v.z), bf16_res(v.w));
}

// ---------------------------------------------------------------------------
// Kernel 0: pre-split 6 weight matrices (w_out pre-scaled by ln_out_scale),
// plus u/v fold vectors. Grid 97 x 256.
// ---------------------------------------------------------------------------
__global__ void __launch_bounds__(256)
k0_split(const float* __restrict__ w0, const float* __restrict__ w1,
         const float* __restrict__ w2, const float* __restrict__ w3,
         const float* __restrict__ w4, const float* __restrict__ w5,
         const float* __restrict__ so, const float* __restrict__ bo)
{
    if (blockIdx.x == 96) {
        int n = threadIdx.x;
        if (n < 128) {
            float u = 0.f, v = 0.f;
            for (int c = 0; c < 128; ++c) {
                float w = w5[c * 128 + n];
                u += so[c] * w;
                v += bo[c] * w;
            }
            g_u[n] = u; g_v[n] = v;
        }
        return;
    }
    const float* ws[6] = {w0, w1, w2, w3, w4, w5};
    int idx = blockIdx.x * 256 + threadIdx.x;   // 24576 threads
    int m = idx >> 12;
    int e = (idx & 4095) * 4;
    float4 v = *(const float4*)(ws[m] + e);
    if (m == 5) {
        float sc = so[e >> 7];
        v.x *= sc; v.y *= sc; v.z *= sc; v.w *= sc;
    }
    uint2 hv, lv;
    split4(v, hv, lv);
    *(uint2*)(g_wh + m * 16384 + e) = hv;
    *(uint2*)(g_wl + m * 16384 + e) = lv;
}

// ---------------------------------------------------------------------------
// Kernel 1: one LN pass, three projection phases (a, b, g) per 128-px tile.
// MMA passes sweep all panels before revisiting an accumulator.
// ---------------------------------------------------------------------------
__global__ void __launch_bounds__(NT, 1)
k1_all(const float* __restrict__ z, const float* __restrict__ mask,
       const float* __restrict__ ln_s, const float* __restrict__ ln_b,
       const float* __restrict__ b_lg, const float* __restrict__ b_l,
       const float* __restrict__ b_rg, const float* __restrict__ b_r,
       const float* __restrict__ b_g)
{
    extern __shared__ char smraw[];
    __nv_bfloat16* znh = (__nv_bfloat16*)smraw;           // [p][k] pitch 136
    __nv_bfloat16* znl = znh + 128 * PIT;
    __nv_bfloat16* W0h = znl + 128 * PIT;                 // gate weights
    __nv_bfloat16* W0l = W0h + 128 * PIT;
    __nv_bfloat16* W1h = W0l + 128 * PIT;                 // value weights
    __nv_bfloat16* W1l = W1h + 128 * PIT;
    float* bs = (float*)(W1l + 128 * PIT);
    // bs: [0)lg [128)l [256)rg [384)r [512)g [640)mask

    const int tid = threadIdx.x, lane = tid & 31, wid = tid >> 5;
    const int pix0 = blockIdx.x * 128;

    const uint32_t w0hA = smem_u32(W0h), w0lA = smem_u32(W0l);
    const uint32_t w1hA = smem_u32(W1h), w1lA = smem_u32(W1l);

#define STAGE_W(mi, dsth, dstl)                                               \
    do {                                                                      \
        const __nv_bfloat16* SH = g_wh + (mi) * 16384;                        \
        const __nv_bfloat16* SL = g_wl + (mi) * 16384;                        \
        _Pragma("unroll")                                                     \
        for (int t = 0; t < 4; ++t) {                                         \
            int u = tid + t * NT;                                             \
            int r = u >> 4, c = u & 15;                                       \
            uint32_t doff = (uint32_t)(r * PITB + c * 16);                    \
            int goff = r * 128 + c * 8;                                       \
            cp16((dsth) + doff, SH + goff);                                   \
            cp16((dstl) + doff, SL + goff);                                   \
        }                                                                     \
    } while (0)

    STAGE_W(0, w0hA, w0lA);
    STAGE_W(1, w1hA, w1lA);
    CP_COMMIT();

    {
        int which = tid >> 7, r = tid & 127;
        const float* bp[4] = {b_lg, b_l, b_rg, b_r};
        bs[tid] = bp[which][r];
        if (tid < 128) { bs[512 + tid] = b_g[tid]; bs[640 + tid] = mask[pix0 + tid]; }
    }

    // LayerNorm (overlaps with weight cp.async)
    {
        float4 s4 = ((const float4*)ln_s)[lane];
        float4 b4 = ((const float4*)ln_b)[lane];
        float4 v[8];
#pragma unroll
        for (int t = 0; t < 8; ++t)
            v[t] = ((const float4*)(z + (size_t)(pix0 + t * 16 + wid) * CDIM))[lane];
#pragma unroll
        for (int t = 0; t < 8; ++t) {
            int r = t * 16 + wid;
            float s  = v[t].x + v[t].y + v[t].z + v[t].w;
            float ss = v[t].x*v[t].x + v[t].y*v[t].y + v[t].z*v[t].z + v[t].w*v[t].w;
#pragma unroll
            for (int o = 16; o > 0; o >>= 1) {
                s  += __shfl_xor_sync(0xffffffffu, s,  o);
                ss += __shfl_xor_sync(0xffffffffu, ss, o);
            }
            float mu   = s * 0.0078125f;
            float rstd = rsqrtf(ss * 0.0078125f - mu * mu + 1e-5f);
            float4 o4;
            o4.x = (v[t].x - mu) * rstd * s4.x + b4.x;
            o4.y = (v[t].y - mu) * rstd * s4.y + b4.y;
            o4.z = (v[t].z - mu) * rstd * s4.z + b4.z;
            o4.w = (v[t].w - mu) * rstd * s4.w + b4.w;
            uint2 hv, lv;
            split4(o4, hv, lv);
            *(uint2*)(&znh[r * PIT + lane * 4]) = hv;
            *(uint2*)(&znl[r * PIT + lane * 4]) = lv;
        }
    }
    CP_WAIT0();
    __syncthreads();

    const int wm = wid & 3, wn = wid >> 2;   // 4 (M) x 4 (N) warp grid
    const uint32_t zh = smem_u32(znh), zl = smem_u32(znl);

    // ldmatrix lane mappings
    const int at_row = (lane & 7) + ((lane >> 4) << 3);      // trans A (W^T)
    const int at_col = ((lane >> 3) & 1) << 3;
    const int bp_row = wn * 32 + (lane & 7) + ((lane >> 4) << 3);  // non-trans B (zn)
    const uint32_t bko = ((lane >> 3) & 1) * 16;

    // ---- phases A (a) and B (b): gated, C[ch][p] orientation ----
#pragma unroll 1
    for (int ph = 0; ph < 2; ++ph) {
        float P[2][4][4], Q[2][4][4];
#pragma unroll
        for (int a = 0; a < 2; ++a)
#pragma unroll
            for (int b = 0; b < 4; ++b)
#pragma unroll
                for (int q = 0; q < 4; ++q) { P[a][b][q] = 0.f; Q[a][b][q] = 0.f; }

#pragma unroll
        for (int k16 = 0; k16 < 8; ++k16) {
            const int kb = k16 * 16;
            uint32_t bh[4][2], bl[4][2];
#pragma unroll
            for (int ng = 0; ng < 2; ++ng) {
                uint32_t r4[4];
                uint32_t boff = (uint32_t)((bp_row + ng * 16) * PITB) + kb * 2 + bko;
                ldsm4(zh + boff, r4);
                bh[ng*2][0] = r4[0]; bh[ng*2][1] = r4[1];
                bh[ng*2+1][0] = r4[2]; bh[ng*2+1][1] = r4[3];
                ldsm4(zl + boff, r4);
                bl[ng*2][0] = r4[0]; bl[ng*2][1] = r4[1];
                bl[ng*2+1][0] = r4[2]; bl[ng*2+1][1] = r4[3];
            }
            uint32_t aoff[2];
#pragma unroll
            for (int mt = 0; mt < 2; ++mt)
                aoff[mt] = (uint32_t)((kb + at_row) * PITB) +
                           (wm * 32 + mt * 16 + at_col) * 2;
            uint32_t a[2][4];
            // --- P: 3 sweeps (hi*bh, hi*bl, lo*bh), 8 indep panels each ---
#pragma unroll
            for (int mt = 0; mt < 2; ++mt) ldsm4_t(w0hA + aoff[mt], a[mt]);
#pragma unroll
            for (int mt = 0; mt < 2; ++mt)
#pragma unroll
                for (int nt = 0; nt < 4; ++nt)
                    mma_bf16(P[mt][nt], a[mt], bh[nt]);
#pragma unroll
            for (int mt = 0; mt < 2; ++mt)
#pragma unroll
                for (int nt = 0; nt < 4; ++nt)
                    mma_bf16(P[mt][nt], a[mt], bl[nt]);
#pragma unroll
            for (int mt = 0; mt < 2; ++mt) ldsm4_t(w0lA + aoff[mt], a[mt]);
#pragma unroll
            for (int mt = 0; mt < 2; ++mt)
#pragma unroll
                for (int nt = 0; nt < 4; ++nt)
                    mma_bf16(P[mt][nt], a[mt], bh[nt]);
            // --- Q: 3 sweeps ---
#pragma unroll
            for (int mt = 0; mt < 2; ++mt) ldsm4_t(w1hA + aoff[mt], a[mt]);
#pragma unroll
            for (int mt = 0; mt < 2; ++mt)
#pragma unroll
                for (int nt = 0; nt < 4; ++nt)
                    mma_bf16(Q[mt][nt], a[mt], bh[nt]);
#pragma unroll
            for (int mt = 0; mt < 2; ++mt)
#pragma unroll
                for (int nt = 0; nt < 4; ++nt)
                    mma_bf16(Q[mt][nt], a[mt], bl[nt]);
#pragma unroll
            for (int mt = 0; mt < 2; ++mt) ldsm4_t(w1lA + aoff[mt], a[mt]);
#pragma unroll
            for (int mt = 0; mt < 2; ++mt)
#pragma unroll
                for (int nt = 0; nt < 4; ++nt)
                    mma_bf16(Q[mt][nt], a[mt], bh[nt]);
        }

        __syncthreads();   // all warps done reading W0/W1
        if (ph == 0) { STAGE_W(2, w0hA, w0lA); STAGE_W(3, w1hA, w1lA); CP_COMMIT(); }
        else         { STAGE_W(4, w0hA, w0lA); CP_COMMIT(); }

        const float* bgp = bs + ph * 256;
        const float* bvp = bs + ph * 256 + 128;
        const float* msm = bs + 640;
        __nv_bfloat16* oh = (ph == 0) ? g_a_hi : g_b_hi;
        __nv_bfloat16* ol = (ph == 0) ? g_a_lo : g_b_lo;
#pragma unroll
        for (int mt = 0; mt < 2; ++mt) {
            int ch = wm * 32 + mt * 16 + (lane >> 2);
            float bg0v = bgp[ch], bg1v = bgp[ch + 8];
            float bv0v = bvp[ch], bv1v = bvp[ch + 8];
            size_t r0 = (size_t)ch * NN + pix0;
            size_t r1 = (size_t)(ch + 8) * NN + pix0;
#pragma unroll
            for (int nt = 0; nt < 4; ++nt) {
                int p = wn * 32 + nt * 8 + (lane & 3) * 2;
                float m0 = msm[p], m1 = msm[p + 1];
                float v00 = m0 * sigmf(P[mt][nt][0] + bg0v) * (Q[mt][nt][0] + bv0v);
                float v01 = m1 * sigmf(P[mt][nt][1] + bg0v) * (Q[mt][nt][1] + bv0v);
                float v10 = m0 * sigmf(P[mt][nt][2] + bg1v) * (Q[mt][nt][2] + bv1v);
                float v11 = m1 * sigmf(P[mt][nt][3] + bg1v) * (Q[mt][nt][3] + bv1v);
                *(uint32_t*)(oh + r0 + p) = pk_bf16x2(v00, v01);
                *(uint32_t*)(ol + r0 + p) = pk_bf16x2(bf16_res(v00), bf16_res(v01));
                *(uint32_t*)(oh + r1 + p) = pk_bf16x2(v10, v11);
                *(uint32_t*)(ol + r1 + p) = pk_bf16x2(bf16_res(v10), bf16_res(v11));
            }
        }
        CP_WAIT0();
        __syncthreads();
    }

    // ---- phase C: g = sig(zn @ Wg + bg), C[p][ch] orientation, fp16 out ----
    {
        const int a_row = wm * 32 + (lane & 15);
        const uint32_t ako = (lane >> 4) * 16;
        const int bt_row = (lane & 7) + (((lane >> 3) & 1) << 3);
        const int bt_col = (lane >> 4) << 3;

        float P[2][4][4];
#pragma unroll
        for (int a = 0; a < 2; ++a)
#pragma unroll
            for (int b = 0; b < 4; ++b)
#pragma unroll
                for (int q = 0; q < 4; ++q) P[a][b][q] = 0.f;

#pragma unroll
        for (int k16 = 0; k16 < 8; ++k16) {
            const int kb = k16 * 16;
            uint32_t bh[4][2], bl[4][2];
#pragma unroll
            for (int ng = 0; ng < 2; ++ng) {
                uint32_t r4[4];
                uint32_t boff = (uint32_t)((kb + bt_row) * PITB) +
                                (wn * 32 + ng * 16 + bt_col) * 2;
                ldsm4_t(w0hA + boff, r4);
                bh[ng*2][0] = r4[0]; bh[ng*2][1] = r4[1];
                bh[ng*2+1][0] = r4[2]; bh[ng*2+1][1] = r4[3];
                ldsm4_t(w0lA + boff, r4);
                bl[ng*2][0] = r4[0]; bl[ng*2][1] = r4[1];
                bl[ng*2+1][0] = r4[2]; bl[ng*2+1][1] = r4[3];
            }
            uint32_t ah[2][4], al[2][4];
#pragma unroll
            for (int mt = 0; mt < 2; ++mt) {
                uint32_t aoff = (uint32_t)((a_row + mt * 16) * PITB) + kb * 2 + ako;
                ldsm4(zh + aoff, ah[mt]);
                ldsm4(zl + aoff, al[mt]);
            }
            // 3 sweeps, 8 indep panels each
#pragma unroll
            for (int mt = 0; mt < 2; ++mt)
#pragma unroll
                for (int nt = 0; nt < 4; ++nt)
                    mma_bf16(P[mt][nt], ah[mt], bh[nt]);
#pragma unroll
            for (int mt = 0; mt < 2; ++mt)
#pragma unroll
                for (int nt = 0; nt < 4; ++nt)
                    mma_bf16(P[mt][nt], ah[mt], bl[nt]);
#pragma unroll
            for (int mt = 0; mt < 2; ++mt)
#pragma unroll
                for (int nt = 0; nt < 4; ++nt)
                    mma_bf16(P[mt][nt], al[mt], bh[nt]);
        }

        const float* bgp = bs + 512;
#pragma unroll
        for (int mt = 0; mt < 2; ++mt) {
            int p0 = pix0 + wm * 32 + mt * 16 + (lane >> 2);
#pragma unroll
            for (int nt = 0; nt < 4; ++nt) {
                int ch = wn * 32 + nt * 8 + (lane & 3) * 2;
                float b0 = bgp[ch], b1 = bgp[ch + 1];
                __half2 v0 = __floats2half2_rn(sigmf(P[mt][nt][0] + b0),
                                               sigmf(P[mt][nt][1] + b1));
                __half2 v1 = __floats2half2_rn(sigmf(P[mt][nt][2] + b0),
                                               sigmf(P[mt][nt][3] + b1));
                *(__half2*)(g_g + (size_t)p0 * CDIM + ch) = v0;
                *(__half2*)(g_g + (size_t)(p0 + 8) * CDIM + ch) = v1;
            }
        }
    }
#undef STAGE_W
}

// ---------------------------------------------------------------------------
// Kernel 2: per-channel X_c = A_c @ B_c^T via mma.sync bf16 hi/lo split.
// 3-stage cp.async pipeline; sweep-ordered MMAs; bf16 hi/lo x output.
// ---------------------------------------------------------------------------
#define K2S 65536u

__global__ void __launch_bounds__(NT, 1)
k2_mma()
{
    extern __shared__ char sm2[];
    const uint32_t smb = smem_u32(sm2);
    const int tid  = threadIdx.x;
    const int lane = tid & 31, wid = tid >> 5;
    const int wm = wid & 3, wn = wid >> 2;
    const int i0 = blockIdx.x * 128, j0 = blockIdx.y * 128;
    const size_t cbase = (size_t)blockIdx.z * NN;

    const __nv_bfloat16* Ah = g_a_hi + cbase + (size_t)i0 * NSEQ;
    const __nv_bfloat16* Al = g_a_lo + cbase + (size_t)i0 * NSEQ;
    const __nv_bfloat16* Bh = g_b_hi + cbase + (size_t)j0 * NSEQ;
    const __nv_bfloat16* Bl = g_b_lo + cbase + (size_t)j0 * NSEQ;

    float acc[2][4][4];
#pragma unroll
    for (int mt = 0; mt < 2; ++mt)
#pragma unroll
        for (int nt = 0; nt < 4; ++nt)
#pragma unroll
            for (int q = 0; q < 4; ++q) acc[mt][nt][q] = 0.f;

    const int arow = wm * 32 + (lane & 15);
    const int bnr  = wn * 32 + (lane & 7) + ((lane >> 4) << 3);
    const uint32_t a_koff = (uint32_t)((lane >> 4) << 4);
    const uint32_t b_koff = (uint32_t)(((lane >> 3) & 1) << 4);

#define K2_LOAD(kc, stg)                                                      \
    do {                                                                      \
        const int ke = (kc) * 64;                                             \
        _Pragma("unroll")                                                     \
        for (int t = 0; t < 2; ++t) {                                         \
            int v = tid + t * NT; int r = v >> 3, cu = v & 7;                 \
            uint32_t so = SWZ((uint32_t)(r * 128 + cu * 16));                 \
            const size_t go = (size_t)r * NSEQ + ke + cu * 8;                 \
            cp16((stg) + so,           Ah + go);                              \
            cp16((stg) + 16384u + so,  Al + go);                              \
            cp16((stg) + 32768u + so,  Bh + go);                              \
            cp16((stg) + 49152u + so,  Bl + go);                              \
        }                                                                     \
        asm volatile("cp.async.commit_group;" ::: "memory");                  \
    } while (0)

    K2_LOAD(0, smb);
    K2_LOAD(1, smb + K2S);

#pragma unroll 1
    for (int kc = 0; kc < 8; ++kc) {
        if (kc + 2 < 8) K2_LOAD(kc + 2, smb + (uint32_t)((kc + 2) % 3) * K2S);
        if (kc < 6)      asm volatile("cp.async.wait_group 2;" ::: "memory");
        else if (kc == 6) asm volatile("cp.async.wait_group 1;" ::: "memory");
        else              asm volatile("cp.async.wait_group 0;" ::: "memory");
        __syncthreads();
        const uint32_t stg = smb + (uint32_t)(kc % 3) * K2S;

#pragma unroll
        for (int k16 = 0; k16 < 4; ++k16) {
            const uint32_t kbA = (uint32_t)(k16 * 32) + a_koff;
            const uint32_t kbB = (uint32_t)(k16 * 32) + b_koff;
            uint32_t bh[4][2], bl[4][2];
#pragma unroll
            for (int ng = 0; ng < 2; ++ng) {
                uint32_t r4[4];
                uint32_t off = SWZ((uint32_t)((bnr + ng * 16) * 128) + kbB);
                ldsm4(stg + 32768u + off, r4);
                bh[ng * 2 + 0][0] = r4[0]; bh[ng * 2 + 0][1] = r4[1];
                bh[ng * 2 + 1][0] = r4[2]; bh[ng * 2 + 1][1] = r4[3];
                ldsm4(stg + 49152u + off, r4);
                bl[ng * 2 + 0][0] = r4[0]; bl[ng * 2 + 0][1] = r4[1];
                bl[ng * 2 + 1][0] = r4[2]; bl[ng * 2 + 1][1] = r4[3];
            }
            uint32_t ah[2][4], al[2][4];
#pragma unroll
            for (int mt = 0; mt < 2; ++mt) {
                uint32_t off = SWZ((uint32_t)((arow + mt * 16) * 128) + kbA);
                ldsm4(stg + off, ah[mt]);
                ldsm4(stg + 16384u + off, al[mt]);
            }
            // 3 sweeps across 8 independent panels
#pragma unroll
            for (int mt = 0; mt < 2; ++mt)
#pragma unroll
                for (int nt = 0; nt < 4; ++nt)
                    mma_bf16(acc[mt][nt], ah[mt], bh[nt]);
#pragma unroll
            for (int mt = 0; mt < 2; ++mt)
#pragma unroll
                for (int nt = 0; nt < 4; ++nt)
                    mma_bf16(acc[mt][nt], ah[mt], bl[nt]);
#pragma unroll
            for (int mt = 0; mt < 2; ++mt)
#pragma unroll
                for (int nt = 0; nt < 4; ++nt)
                    mma_bf16(acc[mt][nt], al[mt], bh[nt]);
        }
        __syncthreads();
    }

    // epilogue: split to bf16 hi/lo -> g_xh/g_xl [c][i][j]
    __nv_bfloat16* Xh = g_xh + cbase + (size_t)(i0 + wm * 32) * NSEQ + j0 + wn * 32;
    __nv_bfloat16* Xl = g_xl + cbase + (size_t)(i0 + wm * 32) * NSEQ + j0 + wn * 32;
    const int rr = lane >> 2, cc = (lane & 3) * 2;
#pragma unroll
    for (int mt = 0; mt < 2; ++mt)
#pragma unroll
        for (int nt = 0; nt < 4; ++nt) {
            size_t o0 = (size_t)(mt * 16 + rr) * NSEQ + nt * 8 + cc;
            size_t o1 = o0 + 8 * NSEQ;
            float v0 = acc[mt][nt][0], v1 = acc[mt][nt][1];
            float v2 = acc[mt][nt][2], v3 = acc[mt][nt][3];
            *(uint32_t*)(Xh + o0) = pk_bf16x2(v0, v1);
            *(uint32_t*)(Xl + o0) = pk_bf16x2(bf16_res(v0), bf16_res(v1));
            *(uint32_t*)(Xh + o1) = pk_bf16x2(v2, v3);
            *(uint32_t*)(Xl + o1) = pk_bf16x2(bf16_res(v2), bf16_res(v3));
        }
#undef K2_LOAD
}

// ---------------------------------------------------------------------------
// Kernel 3: folded-LN out projection:
//   y[p][n] = rs[p]*(x@W')[p][n] - rs[p]*mu[p]*u[n] + (v[n]+b_out[n]);
//   out = y * g. g prefetched to smem (fp16).
// ---------------------------------------------------------------------------
#define GPIT 136   // fp16 smem pitch for g tile (elements)

__global__ void __launch_bounds__(NT, 1)
k3_mma(const float* __restrict__ b_out, float* __restrict__ out)
{
    extern __shared__ char smraw[];
    __nv_bfloat16* Xh = (__nv_bfloat16*)smraw;          // [c][p] pitch 136
    __nv_bfloat16* Xl = Xh + 128 * PIT;
    __nv_bfloat16* Wh = Xl + 128 * PIT;                 // [k][n] pitch 136
    __nv_bfloat16* Wl = Wh + 128 * PIT;
    __half* gS  = (__half*)(Wl + 128 * PIT);            // [p][c] pitch 136
    float* uS   = (float*)(gS + 128 * GPIT);  // 128
    float* wS   = uS + 128;                   // v + b_out, 128
    float* redS = wS + 128;                   // 512
    float* redQ = redS + 512;                 // 512
    float* rsS  = redQ + 512;                 // 128
    float* tS   = rsS + 128;                  // 128 (mu*rs)

    const int tid = threadIdx.x, lane = tid & 31, wid = tid >> 5;
    const int pix0 = blockIdx.x * 128;

    // async stage: x hi/lo tile + pre-split scaled w_out + g tile (fp16)
    {
        const uint32_t xhA = smem_u32(Xh), xlA = smem_u32(Xl);
        const uint32_t whA = smem_u32(Wh), wlA = smem_u32(Wl);
        const uint32_t gA  = smem_u32(gS);
        const __nv_bfloat16* GH = g_wh + 5 * 16384;
        const __nv_bfloat16* GL = g_wl + 5 * 16384;
#pragma unroll
        for (int t = 0; t < 4; ++t) {
            int u = tid + t * NT;
            int c = u >> 4, q = u & 15;
            uint32_t doff = (uint32_t)(c * PITB + q * 16);
            size_t goff = (size_t)c * NN + pix0 + q * 8;
            cp16(xhA + doff, g_xh + goff);
            cp16(xlA + doff, g_xl + goff);
        }
#pragma unroll
        for (int t = 0; t < 4; ++t) {
            int u = tid + t * NT;
            int r = u >> 4, c = u & 15;
            uint32_t doff = (uint32_t)(r * PITB + c * 16);
            int goff = r * 128 + c * 8;
            cp16(whA + doff, GH + goff);
            cp16(wlA + doff, GL + goff);
        }
#pragma unroll
        for (int t = 0; t < 4; ++t) {
            int u = tid + t * NT;              // 2048 chunks of g (fp16)
            int p = u >> 4, q = u & 15;
            cp16(gA + (uint32_t)(p * GPIT * 2 + q * 16),
                 g_g + (size_t)(pix0 + p) * CDIM + q * 8);
        }
        CP_COMMIT();
    }
    if (tid < 128) { uS[tid] = g_u[tid]; wS[tid] = g_v[tid] + b_out[tid]; }
    CP_WAIT0();
    __syncthreads();

    // stats over c (four threads per pixel, 32 channels each)
    const int p = tid & 127, quarter = tid >> 7;
    {
        float s = 0.f, ss = 0.f;
#pragma unroll 8
        for (int c = quarter * 32; c < quarter * 32 + 32; ++c) {
            float v = __bfloat162float(Xh[c * PIT + p]) +
                      __bfloat162float(Xl[c * PIT + p]);
            s += v; ss += v * v;
        }
        redS[tid] = s; redQ[tid] = ss;
    }
    __syncthreads();
    if (tid < 128) {
        float S  = redS[tid] + redS[tid + 128] + redS[tid + 256] + redS[tid + 384];
        float Qv = redQ[tid] + redQ[tid + 128] + redQ[tid + 256] + redQ[tid + 384];
        float mu = S * 0.0078125f;
        float rs = rsqrtf(Qv * 0.0078125f - mu * mu + 1e-5f);
        rsS[tid] = rs;
        tS[tid]  = mu * rs;
    }
    __syncthreads();

    const int wm = wid & 3, wn = wid >> 2;
    const uint32_t xh = smem_u32(Xh), xl = smem_u32(Xl);
    const uint32_t wh = smem_u32(Wh), wl = smem_u32(Wl);

    float acc[2][4][4];
#pragma unroll
    for (int a = 0; a < 2; ++a)
#pragma unroll
        for (int b = 0; b < 4; ++b)
#pragma unroll
            for (int q = 0; q < 4; ++q) acc[a][b][q] = 0.f;

    const int at_row = (lane & 7) + ((lane >> 4) << 3);
    const int at_col = ((lane >> 3) & 1) << 3;
    const int bt_row = (lane & 7) + (((lane >> 3) & 1) << 3);
    const int bt_col = (lane >> 4) << 3;

#pragma unroll
    for (int k16 = 0; k16 < 8; ++k16) {
        const int kb = k16 * 16;
        uint32_t bh[4][2], bl[4][2];
#pragma unroll
        for (int ng = 0; ng < 2; ++ng) {
            uint32_t r4[4];
            uint32_t boff = (uint32_t)((kb + bt_row) * PITB) +
                            (wn * 32 + ng * 16 + bt_col) * 2;
            ldsm4_t(wh + boff, r4);
            bh[ng*2][0] = r4[0]; bh[ng*2][1] = r4[1];
            bh[ng*2+1][0] = r4[2]; bh[ng*2+1][1] = r4[3];
            ldsm4_t(wl + boff, r4);
            bl[ng*2][0] = r4[0]; bl[ng*2][1] = r4[1];
            bl[ng*2+1][0] = r4[2]; bl[ng*2+1][1] = r4[3];
        }
        uint32_t ah[2][4], al[2][4];
#pragma unroll
        for (int mt = 0; mt < 2; ++mt) {
            uint32_t aoff = (uint32_t)((kb + at_row) * PITB) +
                            (wm * 32 + mt * 16 + at_col) * 2;
            ldsm4_t(xh + aoff, ah[mt]);
            ldsm4_t(xl + aoff, al[mt]);
        }
        // 3 sweeps across 8 independent panels
#pragma unroll
        for (int mt = 0; mt < 2; ++mt)
#pragma unroll
            for (int nt = 0; nt < 4; ++nt)
                mma_bf16(acc[mt][nt], ah[mt], bh[nt]);
#pragma unroll
        for (int mt = 0; mt < 2; ++mt)
#pragma unroll
            for (int nt = 0; nt < 4; ++nt)
                mma_bf16(acc[mt][nt], ah[mt], bl[nt]);
#pragma unroll
        for (int mt = 0; mt < 2; ++mt)
#pragma unroll
            for (int nt = 0; nt < 4; ++nt)
                mma_bf16(acc[mt][nt], al[mt], bh[nt]);
    }

    // epilogue: y = rs*acc - t*u + w ; out = y * g (g from smem, fp16)
#pragma unroll
    for (int mt = 0; mt < 2; ++mt) {
        int pl = wm * 32 + mt * 16 + (lane >> 2);
        int p0 = pix0 + pl;
        float rs0 = rsS[pl],     t0 = tS[pl];
        float rs1 = rsS[pl + 8], t1 = tS[pl + 8];
#pragma unroll
        for (int nt = 0; nt < 4; ++nt) {
            int ch = wn * 32 + nt * 8 + (lane & 3) * 2;
            float u0 = uS[ch], u1 = uS[ch + 1];
            float w0 = wS[ch], w1 = wS[ch + 1];
            float2 g0 = __half22float2(*(const __half2*)(gS + pl * GPIT + ch));
            float2 g1 = __half22float2(*(const __half2*)(gS + (pl + 8) * GPIT + ch));
            float2 v0 = make_float2((rs0 * acc[mt][nt][0] - t0 * u0 + w0) * g0.x,
                                    (rs0 * acc[mt][nt][1] - t0 * u1 + w1) * g0.y);
            float2 v1 = make_float2((rs1 * acc[mt][nt][2] - t1 * u0 + w0) * g1.x,
                                    (rs1 * acc[mt][nt][3] - t1 * u1 + w1) * g1.y);
            *(float2*)(out + (size_t)p0 * CDIM + ch) = v0;
            *(float2*)(out + (size_t)(p0 + 8) * CDIM + ch) = v1;
        }
    }
}

// ---------------------------------------------------------------------------
extern "C" void kernel_launch(void* const* d_in, const int* in_sizes, int n_in,
                              void* d_out, int out_size)
{
    const float* z        = (const float*)d_in[0];
    const float* mask     = (const float*)d_in[1];
    const float* ln_in_s  = (const float*)d_in[2];
    const float* ln_in_b  = (const float*)d_in[3];
    const float* w_left   = (const float*)d_in[4];
    const float* b_left   = (const float*)d_in[5];
    const float* w_right  = (const float*)d_in[6];
    const float* b_right  = (const float*)d_in[7];
    const float* w_lgate  = (const float*)d_in[8];
    const float* b_lgate  = (const float*)d_in[9];
    const float* w_rgate  = (const float*)d_in[10];
    const float* b_rgate  = (const float*)d_in[11];
    const float* ln_out_s = (const float*)d_in[12];
    const float* ln_out_b = (const float*)d_in[13];
    const float* w_out    = (const float*)d_in[14];
    const float* b_out    = (const float*)d_in[15];
    const float* w_gate   = (const float*)d_in[16];
    const float* b_gate   = (const float*)d_in[17];
    float* out = (float*)d_out;

    const int smem1 = 6 * 128 * PIT * 2 + 768 * 4;               // ~212 KB
    const int smem2 = 3 * (int)K2S;                              // 196608
    const int smem3 = 4 * 128 * PIT * 2 + 128 * GPIT * 2 + 1536 * 4; // ~180 KB

    cudaFuncSetAttribute(k1_all, cudaFuncAttributeMaxDynamicSharedMemorySize, smem1);
    cudaFuncSetAttribute(k2_mma, cudaFuncAttributeMaxDynamicSharedMemorySize, smem2);
    cudaFuncSetAttribute(k3_mma, cudaFuncAttributeMaxDynamicSharedMemorySize, smem3);

    // 0) pre-split weights (w_out scaled by ln_out_scale) + u/v fold vectors
    k0_split<<<97, 256>>>(w_lgate, w_left, w_rgate, w_right, w_gate, w_out,
                          ln_out_s, ln_out_b);

    // 1) a, b, g projections from a single LN pass
    k1_all<<<NN / 128, NT, smem1>>>(
        z, mask, ln_in_s, ln_in_b,
        b_lgate, b_left, b_rgate, b_right, b_gate);

    // 2) triangular einsum per channel
    k2_mma<<<dim3(4, 4, CDIM), NT, smem2>>>();

    // 3) folded-LN out projection + gating
    k3_mma<<<NN / 128, NT, smem3>>>(b_out, out);
}

// round 11
// speedup vs baseline: 1.1155x; 1.0562x over previous
#include <cuda_runtime.h>
#include <cuda_bf16.h>
#include <cuda_fp16.h>
#include <math.h>
#include <stddef.h>
#include <stdint.h>

// Triangle multiplicative update (outgoing), N=512, cz=ch=128, fp32 in/out.
// All GEMMs on tensor cores via mma.sync bf16 hi/lo split (3 passes, fp32 acc).
// Round 11: k2 rebuilt for 2 CTAs/SM (256 thr, Kc=32, 3x32KB stages, SW64
//           swizzle, single sync per stage).

#define NSEQ 512
#define CDIM 128
#define NN   (NSEQ*NSEQ)          // 262144
#define PIT  136                  // bf16 smem pitch (elements)
#define PITB 272                  // bytes
#define NT   512                  // threads per CTA (k1/k3)

__device__ __nv_bfloat16 g_a_hi[(size_t)CDIM * NN];
__device__ __nv_bfloat16 g_a_lo[(size_t)CDIM * NN];
__device__ __nv_bfloat16 g_b_hi[(size_t)CDIM * NN];
__device__ __nv_bfloat16 g_b_lo[(size_t)CDIM * NN];
__device__ __half g_g[(size_t)NN * CDIM];           // g[pix][c] fp16
__device__ __nv_bfloat16 g_xh[(size_t)CDIM * NN];   // x hi [c][i][j]
__device__ __nv_bfloat16 g_xl[(size_t)CDIM * NN];   // x lo
// pre-split weights: 0=lgate 1=left 2=rgate 3=right 4=gate 5=out(.scaled)
__device__ __align__(16) __nv_bfloat16 g_wh[6 * 16384];
__device__ __align__(16) __nv_bfloat16 g_wl[6 * 16384];
__device__ float g_u[128];   // sum_c s[c]*w_out[c][n]
__device__ float g_v[128];   // sum_c b_ln[c]*w_out[c][n]

__device__ __forceinline__ float sigmf(float x) {
    return 1.0f / (1.0f + __expf(-x));
}
__device__ __forceinline__ unsigned pk_bf16x2(float a, float b) {
    __nv_bfloat162 t = __floats2bfloat162_rn(a, b);
    return *reinterpret_cast<unsigned*>(&t);
}
__device__ __forceinline__ float bf16_res(float v) {   // v - bf16(v)
    return v - __bfloat162float(__float2bfloat16(v));
}
__device__ __forceinline__ uint32_t smem_u32(const void* p) {
    uint32_t a;
    asm("{ .reg .u64 t; cvta.to.shared.u64 t, %1; cvt.u32.u64 %0, t; }"
        : "=r"(a) : "l"(p));
    return a;
}
__device__ __forceinline__ void cp16(uint32_t dst, const void* src) {
    asm volatile("cp.async.cg.shared.global [%0], [%1], 16;"
                 :: "r"(dst), "l"(src) : "memory");
}
#define CP_COMMIT() asm volatile("cp.async.commit_group;" ::: "memory")
#define CP_WAIT0()  asm volatile("cp.async.wait_group 0;" ::: "memory")
#define SWZ(o)   ((o) ^ (((o) >> 3) & 0x70))
#define SWZ64(o) ((o) ^ (((o) >> 3) & 0x30))

__device__ __forceinline__ void ldsm4(uint32_t addr, uint32_t* r) {
    asm volatile("ldmatrix.sync.aligned.m8n8.x4.shared.b16 {%0,%1,%2,%3}, [%4];"
                 : "=r"(r[0]), "=r"(r[1]), "=r"(r[2]), "=r"(r[3]) : "r"(addr));
}
__device__ __forceinline__ void ldsm4_t(uint32_t addr, uint32_t* r) {
    asm volatile("ldmatrix.sync.aligned.m8n8.x4.trans.shared.b16 {%0,%1,%2,%3}, [%4];"
                 : "=r"(r[0]), "=r"(r[1]), "=r"(r[2]), "=r"(r[3]) : "r"(addr));
}
__device__ __forceinline__ void mma_bf16(float* c, const uint32_t* a,
                                         const uint32_t* b) {
    asm volatile(
        "mma.sync.aligned.m16n8k16.row.col.f32.bf16.bf16.f32 "
        "{%0,%1,%2,%3}, {%4,%5,%6,%7}, {%8,%9}, {%0,%1,%2,%3};"
        : "+f"(c[0]), "+f"(c[1]), "+f"(c[2]), "+f"(c[3])
        : "r"(a[0]), "r"(a[1]), "r"(a[2]), "r"(a[3]), "r"(b[0]), "r"(b[1]));
}

__device__ __forceinline__ void split4(float4 v, uint2& hv, uint2& lv) {
    hv.x = pk_bf16x2(v.x, v.y);
    hv.y = pk_bf16x2(v.z, v.w);
    lv.x = pk_bf16x2(bf16_res(v.x), bf16_res(v.y));
    lv.y = pk_bf16x2(bf16_res(v.z), bf16_res(v.w));
}

// ---------------------------------------------------------------------------
// Kernel 0: pre-split 6 weight matrices (w_out pre-scaled by ln_out_scale),
// plus u/v fold vectors. Grid 97 x 256.
// ---------------------------------------------------------------------------
__global__ void __launch_bounds__(256)
k0_split(const float* __restrict__ w0, const float* __restrict__ w1,
         const float* __restrict__ w2, const float* __restrict__ w3,
         const float* __restrict__ w4, const float* __restrict__ w5,
         const float* __restrict__ so, const float* __restrict__ bo)
{
    if (blockIdx.x == 96) {
        int n = threadIdx.x;
        if (n < 128) {
            float u = 0.f, v = 0.f;
            for (int c = 0; c < 128; ++c) {
                float w = w5[c * 128 + n];
                u += so[c] * w;
                v += bo[c] * w;
            }
            g_u[n] = u; g_v[n] = v;
        }
        return;
    }
    const float* ws[6] = {w0, w1, w2, w3, w4, w5};
    int idx = blockIdx.x * 256 + threadIdx.x;   // 24576 threads
    int m = idx >> 12;
    int e = (idx & 4095) * 4;
    float4 v = *(const float4*)(ws[m] + e);
    if (m == 5) {
        float sc = so[e >> 7];
        v.x *= sc; v.y *= sc; v.z *= sc; v.w *= sc;
    }
    uint2 hv, lv;
    split4(v, hv, lv);
    *(uint2*)(g_wh + m * 16384 + e) = hv;
    *(uint2*)(g_wl + m * 16384 + e) = lv;
}

// ---------------------------------------------------------------------------
// Kernel 1: one LN pass, three projection phases (a, b, g) per 128-px tile.
// (unchanged from round 10)
// ---------------------------------------------------------------------------
__global__ void __launch_bounds__(NT, 1)
k1_all(const float* __restrict__ z, const float* __restrict__ mask,
       const float* __restrict__ ln_s, const float* __restrict__ ln_b,
       const float* __restrict__ b_lg, const float* __restrict__ b_l,
       const float* __restrict__ b_rg, const float* __restrict__ b_r,
       const float* __restrict__ b_g)
{
    extern __shared__ char smraw[];
    __nv_bfloat16* znh = (__nv_bfloat16*)smraw;           // [p][k] pitch 136
    __nv_bfloat16* znl = znh + 128 * PIT;
    __nv_bfloat16* W0h = znl + 128 * PIT;                 // gate weights
    __nv_bfloat16* W0l = W0h + 128 * PIT;
    __nv_bfloat16* W1h = W0l + 128 * PIT;                 // value weights
    __nv_bfloat16* W1l = W1h + 128 * PIT;
    float* bs = (float*)(W1l + 128 * PIT);
    // bs: [0)lg [128)l [256)rg [384)r [512)g [640)mask

    const int tid = threadIdx.x, lane = tid & 31, wid = tid >> 5;
    const int pix0 = blockIdx.x * 128;

    const uint32_t w0hA = smem_u32(W0h), w0lA = smem_u32(W0l);
    const uint32_t w1hA = smem_u32(W1h), w1lA = smem_u32(W1l);

#define STAGE_W(mi, dsth, dstl)                                               \
    do {                                                                      \
        const __nv_bfloat16* SH = g_wh + (mi) * 16384;                        \
        const __nv_bfloat16* SL = g_wl + (mi) * 16384;                        \
        _Pragma("unroll")                                                     \
        for (int t = 0; t < 4; ++t) {                                         \
            int u = tid + t * NT;                                             \
            int r = u >> 4, c = u & 15;                                       \
            uint32_t doff = (uint32_t)(r * PITB + c * 16);                    \
            int goff = r * 128 + c * 8;                                       \
            cp16((dsth) + doff, SH + goff);                                   \
            cp16((dstl) + doff, SL + goff);                                   \
        }                                                                     \
    } while (0)

    STAGE_W(0, w0hA, w0lA);
    STAGE_W(1, w1hA, w1lA);
    CP_COMMIT();

    {
        int which = tid >> 7, r = tid & 127;
        const float* bp[4] = {b_lg, b_l, b_rg, b_r};
        bs[tid] = bp[which][r];
        if (tid < 128) { bs[512 + tid] = b_g[tid]; bs[640 + tid] = mask[pix0 + tid]; }
    }

    // LayerNorm (overlaps with weight cp.async)
    {
        float4 s4 = ((const float4*)ln_s)[lane];
        float4 b4 = ((const float4*)ln_b)[lane];
        float4 v[8];
#pragma unroll
        for (int t = 0; t < 8; ++t)
            v[t] = ((const float4*)(z + (size_t)(pix0 + t * 16 + wid) * CDIM))[lane];
#pragma unroll
        for (int t = 0; t < 8; ++t) {
            int r = t * 16 + wid;
            float s  = v[t].x + v[t].y + v[t].z + v[t].w;
            float ss = v[t].x*v[t].x + v[t].y*v[t].y + v[t].z*v[t].z + v[t].w*v[t].w;
#pragma unroll
            for (int o = 16; o > 0; o >>= 1) {
                s  += __shfl_xor_sync(0xffffffffu, s,  o);
                ss += __shfl_xor_sync(0xffffffffu, ss, o);
            }
            float mu   = s * 0.0078125f;
            float rstd = rsqrtf(ss * 0.0078125f - mu * mu + 1e-5f);
            float4 o4;
            o4.x = (v[t].x - mu) * rstd * s4.x + b4.x;
            o4.y = (v[t].y - mu) * rstd * s4.y + b4.y;
            o4.z = (v[t].z - mu) * rstd * s4.z + b4.z;
            o4.w = (v[t].w - mu) * rstd * s4.w + b4.w;
            uint2 hv, lv;
            split4(o4, hv, lv);
            *(uint2*)(&znh[r * PIT + lane * 4]) = hv;
            *(uint2*)(&znl[r * PIT + lane * 4]) = lv;
        }
    }
    CP_WAIT0();
    __syncthreads();

    const int wm = wid & 3, wn = wid >> 2;   // 4 (M) x 4 (N) warp grid
    const uint32_t zh = smem_u32(znh), zl = smem_u32(znl);

    const int at_row = (lane & 7) + ((lane >> 4) << 3);      // trans A (W^T)
    const int at_col = ((lane >> 3) & 1) << 3;
    const int bp_row = wn * 32 + (lane & 7) + ((lane >> 4) << 3);  // non-trans B (zn)
    const uint32_t bko = ((lane >> 3) & 1) * 16;

#pragma unroll 1
    for (int ph = 0; ph < 2; ++ph) {
        float P[2][4][4], Q[2][4][4];
#pragma unroll
        for (int a = 0; a < 2; ++a)
#pragma unroll
            for (int b = 0; b < 4; ++b)
#pragma unroll
                for (int q = 0; q < 4; ++q) { P[a][b][q] = 0.f; Q[a][b][q] = 0.f; }

#pragma unroll
        for (int k16 = 0; k16 < 8; ++k16) {
            const int kb = k16 * 16;
            uint32_t bh[4][2], bl[4][2];
#pragma unroll
            for (int ng = 0; ng < 2; ++ng) {
                uint32_t r4[4];
                uint32_t boff = (uint32_t)((bp_row + ng * 16) * PITB) + kb * 2 + bko;
                ldsm4(zh + boff, r4);
                bh[ng*2][0] = r4[0]; bh[ng*2][1] = r4[1];
                bh[ng*2+1][0] = r4[2]; bh[ng*2+1][1] = r4[3];
                ldsm4(zl + boff, r4);
                bl[ng*2][0] = r4[0]; bl[ng*2][1] = r4[1];
                bl[ng*2+1][0] = r4[2]; bl[ng*2+1][1] = r4[3];
            }
            uint32_t aoff[2];
#pragma unroll
            for (int mt = 0; mt < 2; ++mt)
                aoff[mt] = (uint32_t)((kb + at_row) * PITB) +
                           (wm * 32 + mt * 16 + at_col) * 2;
            uint32_t a[2][4];
#pragma unroll
            for (int mt = 0; mt < 2; ++mt) ldsm4_t(w0hA + aoff[mt], a[mt]);
#pragma unroll
            for (int mt = 0; mt < 2; ++mt)
#pragma unroll
                for (int nt = 0; nt < 4; ++nt)
                    mma_bf16(P[mt][nt], a[mt], bh[nt]);
#pragma unroll
            for (int mt = 0; mt < 2; ++mt)
#pragma unroll
                for (int nt = 0; nt < 4; ++nt)
                    mma_bf16(P[mt][nt], a[mt], bl[nt]);
#pragma unroll
            for (int mt = 0; mt < 2; ++mt) ldsm4_t(w0lA + aoff[mt], a[mt]);
#pragma unroll
            for (int mt = 0; mt < 2; ++mt)
#pragma unroll
                for (int nt = 0; nt < 4; ++nt)
                    mma_bf16(P[mt][nt], a[mt], bh[nt]);
#pragma unroll
            for (int mt = 0; mt < 2; ++mt) ldsm4_t(w1hA + aoff[mt], a[mt]);
#pragma unroll
            for (int mt = 0; mt < 2; ++mt)
#pragma unroll
                for (int nt = 0; nt < 4; ++nt)
                    mma_bf16(Q[mt][nt], a[mt], bh[nt]);
#pragma unroll
            for (int mt = 0; mt < 2; ++mt)
#pragma unroll
                for (int nt = 0; nt < 4; ++nt)
                    mma_bf16(Q[mt][nt], a[mt], bl[nt]);
#pragma unroll
            for (int mt = 0; mt < 2; ++mt) ldsm4_t(w1lA + aoff[mt], a[mt]);
#pragma unroll
            for (int mt = 0; mt < 2; ++mt)
#pragma unroll
                for (int nt = 0; nt < 4; ++nt)
                    mma_bf16(Q[mt][nt], a[mt], bh[nt]);
        }

        __syncthreads();   // all warps done reading W0/W1
        if (ph == 0) { STAGE_W(2, w0hA, w0lA); STAGE_W(3, w1hA, w1lA); CP_COMMIT(); }
        else         { STAGE_W(4, w0hA, w0lA); CP_COMMIT(); }

        const float* bgp = bs + ph * 256;
        const float* bvp = bs + ph * 256 + 128;
        const float* msm = bs + 640;
        __nv_bfloat16* oh = (ph == 0) ? g_a_hi : g_b_hi;
        __nv_bfloat16* ol = (ph == 0) ? g_a_lo : g_b_lo;
#pragma unroll
        for (int mt = 0; mt < 2; ++mt) {
            int ch = wm * 32 + mt * 16 + (lane >> 2);
            float bg0v = bgp[ch], bg1v = bgp[ch + 8];
            float bv0v = bvp[ch], bv1v = bvp[ch + 8];
            size_t r0 = (size_t)ch * NN + pix0;
            size_t r1 = (size_t)(ch + 8) * NN + pix0;
#pragma unroll
            for (int nt = 0; nt < 4; ++nt) {
                int p = wn * 32 + nt * 8 + (lane & 3) * 2;
                float m0 = msm[p], m1 = msm[p + 1];
                float v00 = m0 * sigmf(P[mt][nt][0] + bg0v) * (Q[mt][nt][0] + bv0v);
                float v01 = m1 * sigmf(P[mt][nt][1] + bg0v) * (Q[mt][nt][1] + bv0v);
                float v10 = m0 * sigmf(P[mt][nt][2] + bg1v) * (Q[mt][nt][2] + bv1v);
                float v11 = m1 * sigmf(P[mt][nt][3] + bg1v) * (Q[mt][nt][3] + bv1v);
                *(uint32_t*)(oh + r0 + p) = pk_bf16x2(v00, v01);
                *(uint32_t*)(ol + r0 + p) = pk_bf16x2(bf16_res(v00), bf16_res(v01));
                *(uint32_t*)(oh + r1 + p) = pk_bf16x2(v10, v11);
                *(uint32_t*)(ol + r1 + p) = pk_bf16x2(bf16_res(v10), bf16_res(v11));
            }
        }
        CP_WAIT0();
        __syncthreads();
    }

    // ---- phase C: g = sig(zn @ Wg + bg), C[p][ch] orientation, fp16 out ----
    {
        const int a_row = wm * 32 + (lane & 15);
        const uint32_t ako = (lane >> 4) * 16;
        const int bt_row = (lane & 7) + (((lane >> 3) & 1) << 3);
        const int bt_col = (lane >> 4) << 3;

        float P[2][4][4];
#pragma unroll
        for (int a = 0; a < 2; ++a)
#pragma unroll
            for (int b = 0; b < 4; ++b)
#pragma unroll
                for (int q = 0; q < 4; ++q) P[a][b][q] = 0.f;

#pragma unroll
        for (int k16 = 0; k16 < 8; ++k16) {
            const int kb = k16 * 16;
            uint32_t bh[4][2], bl[4][2];
#pragma unroll
            for (int ng = 0; ng < 2; ++ng) {
                uint32_t r4[4];
                uint32_t boff = (uint32_t)((kb + bt_row) * PITB) +
                                (wn * 32 + ng * 16 + bt_col) * 2;
                ldsm4_t(w0hA + boff, r4);
                bh[ng*2][0] = r4[0]; bh[ng*2][1] = r4[1];
                bh[ng*2+1][0] = r4[2]; bh[ng*2+1][1] = r4[3];
                ldsm4_t(w0lA + boff, r4);
                bl[ng*2][0] = r4[0]; bl[ng*2][1] = r4[1];
                bl[ng*2+1][0] = r4[2]; bl[ng*2+1][1] = r4[3];
            }
            uint32_t ah[2][4], al[2][4];
#pragma unroll
            for (int mt = 0; mt < 2; ++mt) {
                uint32_t aoff = (uint32_t)((a_row + mt * 16) * PITB) + kb * 2 + ako;
                ldsm4(zh + aoff, ah[mt]);
                ldsm4(zl + aoff, al[mt]);
            }
#pragma unroll
            for (int mt = 0; mt < 2; ++mt)
#pragma unroll
                for (int nt = 0; nt < 4; ++nt)
                    mma_bf16(P[mt][nt], ah[mt], bh[nt]);
#pragma unroll
            for (int mt = 0; mt < 2; ++mt)
#pragma unroll
                for (int nt = 0; nt < 4; ++nt)
                    mma_bf16(P[mt][nt], ah[mt], bl[nt]);
#pragma unroll
            for (int mt = 0; mt < 2; ++mt)
#pragma unroll
                for (int nt = 0; nt < 4; ++nt)
                    mma_bf16(P[mt][nt], al[mt], bh[nt]);
        }

        const float* bgp = bs + 512;
#pragma unroll
        for (int mt = 0; mt < 2; ++mt) {
            int p0 = pix0 + wm * 32 + mt * 16 + (lane >> 2);
#pragma unroll
            for (int nt = 0; nt < 4; ++nt) {
                int ch = wn * 32 + nt * 8 + (lane & 3) * 2;
                float b0 = bgp[ch], b1 = bgp[ch + 1];
                __half2 v0 = __floats2half2_rn(sigmf(P[mt][nt][0] + b0),
                                               sigmf(P[mt][nt][1] + b1));
                __half2 v1 = __floats2half2_rn(sigmf(P[mt][nt][2] + b0),
                                               sigmf(P[mt][nt][3] + b1));
                *(__half2*)(g_g + (size_t)p0 * CDIM + ch) = v0;
                *(__half2*)(g_g + (size_t)(p0 + 8) * CDIM + ch) = v1;
            }
        }
    }
#undef STAGE_W
}

// ---------------------------------------------------------------------------
// Kernel 2: per-channel X_c = A_c @ B_c^T. 256 threads, 2 CTAs/SM.
// Kc=32, 3 stages x 32KB (SW64, 64B rows), single sync per stage; loads for
// stage kc+2 issued after compute(kc). Warp tile 64x32 (2M x 4N warps).
// ---------------------------------------------------------------------------
#define K2S 32768u

__global__ void __launch_bounds__(256, 2)
k2_mma()
{
    extern __shared__ char sm2[];
    const uint32_t smb = smem_u32(sm2);
    const int tid  = threadIdx.x;
    const int lane = tid & 31, wid = tid >> 5;
    const int wm = wid & 1, wn = wid >> 1;     // 2 (M) x 4 (N)
    const int i0 = blockIdx.x * 128, j0 = blockIdx.y * 128;
    const size_t cbase = (size_t)blockIdx.z * NN;

    const __nv_bfloat16* Ah = g_a_hi + cbase + (size_t)i0 * NSEQ;
    const __nv_bfloat16* Al = g_a_lo + cbase + (size_t)i0 * NSEQ;
    const __nv_bfloat16* Bh = g_b_hi + cbase + (size_t)j0 * NSEQ;
    const __nv_bfloat16* Bl = g_b_lo + cbase + (size_t)j0 * NSEQ;

    float acc[4][4][4];
#pragma unroll
    for (int mt = 0; mt < 4; ++mt)
#pragma unroll
        for (int nt = 0; nt < 4; ++nt)
#pragma unroll
            for (int q = 0; q < 4; ++q) acc[mt][nt][q] = 0.f;

    const int arow = wm * 64 + (lane & 15);
    const int bnr  = wn * 32 + (lane & 7) + ((lane >> 4) << 3);
    const uint32_t a_koff = (uint32_t)((lane >> 4) << 4);
    const uint32_t b_koff = (uint32_t)(((lane >> 3) & 1) << 4);

    // stage: [Ah 8K][Al 8K][Bh 8K][Bl 8K], rows of 64B, SW64 swizzle
#define K2_LOAD(kc, stg)                                                      \
    do {                                                                      \
        const int ke = (kc) * 32;                                             \
        _Pragma("unroll")                                                     \
        for (int t = 0; t < 2; ++t) {                                         \
            int v = tid + t * 256; int r = v >> 2, cu = v & 3;                \
            uint32_t so = SWZ64((uint32_t)(r * 64 + cu * 16));                \
            const size_t go = (size_t)r * NSEQ + ke + cu * 8;                 \
            cp16((stg) + so,           Ah + go);                              \
            cp16((stg) + 8192u + so,   Al + go);                              \
            cp16((stg) + 16384u + so,  Bh + go);                              \
            cp16((stg) + 24576u + so,  Bl + go);                              \
        }                                                                     \
        asm volatile("cp.async.commit_group;" ::: "memory");                  \
    } while (0)

    K2_LOAD(0, smb);
    K2_LOAD(1, smb + K2S);

#pragma unroll 1
    for (int kc = 0; kc < 16; ++kc) {
        if (kc < 15) asm volatile("cp.async.wait_group 1;" ::: "memory");
        else         asm volatile("cp.async.wait_group 0;" ::: "memory");
        __syncthreads();
        const uint32_t stg = smb + (uint32_t)(kc % 3) * K2S;

#pragma unroll
        for (int k16 = 0; k16 < 2; ++k16) {
            const uint32_t kbA = (uint32_t)(k16 * 32) + a_koff;
            const uint32_t kbB = (uint32_t)(k16 * 32) + b_koff;
            uint32_t bh[4][2], bl[4][2];
#pragma unroll
            for (int ng = 0; ng < 2; ++ng) {
                uint32_t r4[4];
                uint32_t off = SWZ64((uint32_t)((bnr + ng * 16) * 64) + kbB);
                ldsm4(stg + 16384u + off, r4);
                bh[ng * 2 + 0][0] = r4[0]; bh[ng * 2 + 0][1] = r4[1];
                bh[ng * 2 + 1][0] = r4[2]; bh[ng * 2 + 1][1] = r4[3];
                ldsm4(stg + 24576u + off, r4);
                bl[ng * 2 + 0][0] = r4[0]; bl[ng * 2 + 0][1] = r4[1];
                bl[ng * 2 + 1][0] = r4[2]; bl[ng * 2 + 1][1] = r4[3];
            }
            uint32_t aoff[4];
#pragma unroll
            for (int mt = 0; mt < 4; ++mt)
                aoff[mt] = SWZ64((uint32_t)((arow + mt * 16) * 64) + kbA);
            uint32_t a4[4][4];
            // sweep 1: Ah x Bh
#pragma unroll
            for (int mt = 0; mt < 4; ++mt) ldsm4(stg + aoff[mt], a4[mt]);
#pragma unroll
            for (int mt = 0; mt < 4; ++mt)
#pragma unroll
                for (int nt = 0; nt < 4; ++nt)
                    mma_bf16(acc[mt][nt], a4[mt], bh[nt]);
            // sweep 2: Ah x Bl
#pragma unroll
            for (int mt = 0; mt < 4; ++mt)
#pragma unroll
                for (int nt = 0; nt < 4; ++nt)
                    mma_bf16(acc[mt][nt], a4[mt], bl[nt]);
            // sweep 3: Al x Bh (reuse a4 registers)
#pragma unroll
            for (int mt = 0; mt < 4; ++mt) ldsm4(stg + 8192u + aoff[mt], a4[mt]);
#pragma unroll
            for (int mt = 0; mt < 4; ++mt)
#pragma unroll
                for (int nt = 0; nt < 4; ++nt)
                    mma_bf16(acc[mt][nt], a4[mt], bh[nt]);
        }
        if (kc + 2 < 16) K2_LOAD(kc + 2, smb + (uint32_t)((kc + 2) % 3) * K2S);
    }

    // epilogue: split to bf16 hi/lo -> g_xh/g_xl [c][i][j]
    __nv_bfloat16* Xh = g_xh + cbase + (size_t)(i0 + wm * 64) * NSEQ + j0 + wn * 32;
    __nv_bfloat16* Xl = g_xl + cbase + (size_t)(i0 + wm * 64) * NSEQ + j0 + wn * 32;
    const int rr = lane >> 2, cc = (lane & 3) * 2;
#pragma unroll
    for (int mt = 0; mt < 4; ++mt)
#pragma unroll
        for (int nt = 0; nt < 4; ++nt) {
            size_t o0 = (size_t)(mt * 16 + rr) * NSEQ + nt * 8 + cc;
            size_t o1 = o0 + 8 * NSEQ;
            float v0 = acc[mt][nt][0], v1 = acc[mt][nt][1];
            float v2 = acc[mt][nt][2], v3 = acc[mt][nt][3];
            *(uint32_t*)(Xh + o0) = pk_bf16x2(v0, v1);
            *(uint32_t*)(Xl + o0) = pk_bf16x2(bf16_res(v0), bf16_res(v1));
            *(uint32_t*)(Xh + o1) = pk_bf16x2(v2, v3);
            *(uint32_t*)(Xl + o1) = pk_bf16x2(bf16_res(v2), bf16_res(v3));
        }
#undef K2_LOAD
}

// ---------------------------------------------------------------------------
// Kernel 3: folded-LN out projection (unchanged from round 10).
// ---------------------------------------------------------------------------
#define GPIT 136   // fp16 smem pitch for g tile (elements)

__global__ void __launch_bounds__(NT, 1)
k3_mma(const float* __restrict__ b_out, float* __restrict__ out)
{
    extern __shared__ char smraw[];
    __nv_bfloat16* Xh = (__nv_bfloat16*)smraw;          // [c][p] pitch 136
    __nv_bfloat16* Xl = Xh + 128 * PIT;
    __nv_bfloat16* Wh = Xl + 128 * PIT;                 // [k][n] pitch 136
    __nv_bfloat16* Wl = Wh + 128 * PIT;
    __half* gS  = (__half*)(Wl + 128 * PIT);            // [p][c] pitch 136
    float* uS   = (float*)(gS + 128 * GPIT);  // 128
    float* wS   = uS + 128;                   // v + b_out, 128
    float* redS = wS + 128;                   // 512
    float* redQ = redS + 512;                 // 512
    float* rsS  = redQ + 512;                 // 128
    float* tS   = rsS + 128;                  // 128 (mu*rs)

    const int tid = threadIdx.x, lane = tid & 31, wid = tid >> 5;
    const int pix0 = blockIdx.x * 128;

    {
        const uint32_t xhA = smem_u32(Xh), xlA = smem_u32(Xl);
        const uint32_t whA = smem_u32(Wh), wlA = smem_u32(Wl);
        const uint32_t gA  = smem_u32(gS);
        const __nv_bfloat16* GH = g_wh + 5 * 16384;
        const __nv_bfloat16* GL = g_wl + 5 * 16384;
#pragma unroll
        for (int t = 0; t < 4; ++t) {
            int u = tid + t * NT;
            int c = u >> 4, q = u & 15;
            uint32_t doff = (uint32_t)(c * PITB + q * 16);
            size_t goff = (size_t)c * NN + pix0 + q * 8;
            cp16(xhA + doff, g_xh + goff);
            cp16(xlA + doff, g_xl + goff);
        }
#pragma unroll
        for (int t = 0; t < 4; ++t) {
            int u = tid + t * NT;
            int r = u >> 4, c = u & 15;
            uint32_t doff = (uint32_t)(r * PITB + c * 16);
            int goff = r * 128 + c * 8;
            cp16(whA + doff, GH + goff);
            cp16(wlA + doff, GL + goff);
        }
#pragma unroll
        for (int t = 0; t < 4; ++t) {
            int u = tid + t * NT;
            int p = u >> 4, q = u & 15;
            cp16(gA + (uint32_t)(p * GPIT * 2 + q * 16),
                 g_g + (size_t)(pix0 + p) * CDIM + q * 8);
        }
        CP_COMMIT();
    }
    if (tid < 128) { uS[tid] = g_u[tid]; wS[tid] = g_v[tid] + b_out[tid]; }
    CP_WAIT0();
    __syncthreads();

    const int p = tid & 127, quarter = tid >> 7;
    {
        float s = 0.f, ss = 0.f;
#pragma unroll 8
        for (int c = quarter * 32; c < quarter * 32 + 32; ++c) {
            float v = __bfloat162float(Xh[c * PIT + p]) +
                      __bfloat162float(Xl[c * PIT + p]);
            s += v; ss += v * v;
        }
        redS[tid] = s; redQ[tid] = ss;
    }
    __syncthreads();
    if (tid < 128) {
        float S  = redS[tid] + redS[tid + 128] + redS[tid + 256] + redS[tid + 384];
        float Qv = redQ[tid] + redQ[tid + 128] + redQ[tid + 256] + redQ[tid + 384];
        float mu = S * 0.0078125f;
        float rs = rsqrtf(Qv * 0.0078125f - mu * mu + 1e-5f);
        rsS[tid] = rs;
        tS[tid]  = mu * rs;
    }
    __syncthreads();

    const int wm = wid & 3, wn = wid >> 2;
    const uint32_t xh = smem_u32(Xh), xl = smem_u32(Xl);
    const uint32_t wh = smem_u32(Wh), wl = smem_u32(Wl);

    float acc[2][4][4];
#pragma unroll
    for (int a = 0; a < 2; ++a)
#pragma unroll
        for (int b = 0; b < 4; ++b)
#pragma unroll
            for (int q = 0; q < 4; ++q) acc[a][b][q] = 0.f;

    const int at_row = (lane & 7) + ((lane >> 4) << 3);
    const int at_col = ((lane >> 3) & 1) << 3;
    const int bt_row = (lane & 7) + (((lane >> 3) & 1) << 3);
    const int bt_col = (lane >> 4) << 3;

#pragma unroll
    for (int k16 = 0; k16 < 8; ++k16) {
        const int kb = k16 * 16;
        uint32_t bh[4][2], bl[4][2];
#pragma unroll
        for (int ng = 0; ng < 2; ++ng) {
            uint32_t r4[4];
            uint32_t boff = (uint32_t)((kb + bt_row) * PITB) +
                            (wn * 32 + ng * 16 + bt_col) * 2;
            ldsm4_t(wh + boff, r4);
            bh[ng*2][0] = r4[0]; bh[ng*2][1] = r4[1];
            bh[ng*2+1][0] = r4[2]; bh[ng*2+1][1] = r4[3];
            ldsm4_t(wl + boff, r4);
            bl[ng*2][0] = r4[0]; bl[ng*2][1] = r4[1];
            bl[ng*2+1][0] = r4[2]; bl[ng*2+1][1] = r4[3];
        }
        uint32_t ah[2][4], al[2][4];
#pragma unroll
        for (int mt = 0; mt < 2; ++mt) {
            uint32_t aoff = (uint32_t)((kb + at_row) * PITB) +
                            (wm * 32 + mt * 16 + at_col) * 2;
            ldsm4_t(xh + aoff, ah[mt]);
            ldsm4_t(xl + aoff, al[mt]);
        }
#pragma unroll
        for (int mt = 0; mt < 2; ++mt)
#pragma unroll
            for (int nt = 0; nt < 4; ++nt)
                mma_bf16(acc[mt][nt], ah[mt], bh[nt]);
#pragma unroll
        for (int mt = 0; mt < 2; ++mt)
#pragma unroll
            for (int nt = 0; nt < 4; ++nt)
                mma_bf16(acc[mt][nt], ah[mt], bl[nt]);
#pragma unroll
        for (int mt = 0; mt < 2; ++mt)
#pragma unroll
            for (int nt = 0; nt < 4; ++nt)
                mma_bf16(acc[mt][nt], al[mt], bh[nt]);
    }

#pragma unroll
    for (int mt = 0; mt < 2; ++mt) {
        int pl = wm * 32 + mt * 16 + (lane >> 2);
        int p0 = pix0 + pl;
        float rs0 = rsS[pl],     t0 = tS[pl];
        float rs1 = rsS[pl + 8], t1 = tS[pl + 8];
#pragma unroll
        for (int nt = 0; nt < 4; ++nt) {
            int ch = wn * 32 + nt * 8 + (lane & 3) * 2;
            float u0 = uS[ch], u1 = uS[ch + 1];
            float w0 = wS[ch], w1 = wS[ch + 1];
            float2 g0 = __half22float2(*(const __half2*)(gS + pl * GPIT + ch));
            float2 g1 = __half22float2(*(const __half2*)(gS + (pl + 8) * GPIT + ch));
            float2 v0 = make_float2((rs0 * acc[mt][nt][0] - t0 * u0 + w0) * g0.x,
                                    (rs0 * acc[mt][nt][1] - t0 * u1 + w1) * g0.y);
            float2 v1 = make_float2((rs1 * acc[mt][nt][2] - t1 * u0 + w0) * g1.x,
                                    (rs1 * acc[mt][nt][3] - t1 * u1 + w1) * g1.y);
            *(float2*)(out + (size_t)p0 * CDIM + ch) = v0;
            *(float2*)(out + (size_t)(p0 + 8) * CDIM + ch) = v1;
        }
    }
}

// ---------------------------------------------------------------------------
extern "C" void kernel_launch(void* const* d_in, const int* in_sizes, int n_in,
                              void* d_out, int out_size)
{
    const float* z        = (const float*)d_in[0];
    const float* mask     = (const float*)d_in[1];
    const float* ln_in_s  = (const float*)d_in[2];
    const float* ln_in_b  = (const float*)d_in[3];
    const float* w_left   = (const float*)d_in[4];
    const float* b_left   = (const float*)d_in[5];
    const float* w_right  = (const float*)d_in[6];
    const float* b_right  = (const float*)d_in[7];
    const float* w_lgate  = (const float*)d_in[8];
    const float* b_lgate  = (const float*)d_in[9];
    const float* w_rgate  = (const float*)d_in[10];
    const float* b_rgate  = (const float*)d_in[11];
    const float* ln_out_s = (const float*)d_in[12];
    const float* ln_out_b = (const float*)d_in[13];
    const float* w_out    = (const float*)d_in[14];
    const float* b_out    = (const float*)d_in[15];
    const float* w_gate   = (const float*)d_in[16];
    const float* b_gate   = (const float*)d_in[17];
    float* out = (float*)d_out;

    const int smem1 = 6 * 128 * PIT * 2 + 768 * 4;               // ~212 KB
    const int smem2 = 3 * (int)K2S;                              // 98304
    const int smem3 = 4 * 128 * PIT * 2 + 128 * GPIT * 2 + 1536 * 4; // ~180 KB

    cudaFuncSetAttribute(k1_all, cudaFuncAttributeMaxDynamicSharedMemorySize, smem1);
    cudaFuncSetAttribute(k2_mma, cudaFuncAttributeMaxDynamicSharedMemorySize, smem2);
    cudaFuncSetAttribute(k3_mma, cudaFuncAttributeMaxDynamicSharedMemorySize, smem3);

    // 0) pre-split weights (w_out scaled by ln_out_scale) + u/v fold vectors
    k0_split<<<97, 256>>>(w_lgate, w_left, w_rgate, w_right, w_gate, w_out,
                          ln_out_s, ln_out_b);

    // 1) a, b, g projections from a single LN pass
    k1_all<<<NN / 128, NT, smem1>>>(
        z, mask, ln_in_s, ln_in_b,
        b_lgate, b_left, b_rgate, b_right, b_gate);

    // 2) triangular einsum per channel (2 CTAs/SM)
    k2_mma<<<dim3(4, 4, CDIM), 256, smem2>>>();

    // 3) folded-LN out projection + gating
    k3_mma<<<NN / 128, NT, smem3>>>(b_out, out);
}

// round 12
// speedup vs baseline: 1.1845x; 1.0618x over previous
#include <cuda_runtime.h>
#include <cuda_bf16.h>
#include <cuda_fp16.h>
#include <math.h>
#include <stddef.h>
#include <stdint.h>

// Triangle multiplicative update (outgoing), N=512, cz=ch=128, fp32 in/out.
// All GEMMs on tensor cores via mma.sync bf16 hi/lo split (3 passes, fp32 acc).
// Round 12: k1 rebuilt for 2 CTAs/SM (256 thr, 64-pixel tiles, one weight
//           pair resident, phases serialized with cp.async restaging).

#define NSEQ 512
#define CDIM 128
#define NN   (NSEQ*NSEQ)          // 262144
#define PIT  136                  // bf16 smem pitch (elements)
#define PITB 272                  // bytes
#define NT   512                  // threads per CTA (k3)

__device__ __nv_bfloat16 g_a_hi[(size_t)CDIM * NN];
__device__ __nv_bfloat16 g_a_lo[(size_t)CDIM * NN];
__device__ __nv_bfloat16 g_b_hi[(size_t)CDIM * NN];
__device__ __nv_bfloat16 g_b_lo[(size_t)CDIM * NN];
__device__ __half g_g[(size_t)NN * CDIM];           // g[pix][c] fp16
__device__ __nv_bfloat16 g_xh[(size_t)CDIM * NN];   // x hi [c][i][j]
__device__ __nv_bfloat16 g_xl[(size_t)CDIM * NN];   // x lo
// pre-split weights: 0=lgate 1=left 2=rgate 3=right 4=gate 5=out(.scaled)
__device__ __align__(16) __nv_bfloat16 g_wh[6 * 16384];
__device__ __align__(16) __nv_bfloat16 g_wl[6 * 16384];
__device__ float g_u[128];   // sum_c s[c]*w_out[c][n]
__device__ float g_v[128];   // sum_c b_ln[c]*w_out[c][n]

__device__ __forceinline__ float sigmf(float x) {
    return 1.0f / (1.0f + __expf(-x));
}
__device__ __forceinline__ unsigned pk_bf16x2(float a, float b) {
    __nv_bfloat162 t = __floats2bfloat162_rn(a, b);
    return *reinterpret_cast<unsigned*>(&t);
}
__device__ __forceinline__ float bf16_res(float v) {   // v - bf16(v)
    return v - __bfloat162float(__float2bfloat16(v));
}
__device__ __forceinline__ uint32_t smem_u32(const void* p) {
    uint32_t a;
    asm("{ .reg .u64 t; cvta.to.shared.u64 t, %1; cvt.u32.u64 %0, t; }"
        : "=r"(a) : "l"(p));
    return a;
}
__device__ __forceinline__ void cp16(uint32_t dst, const void* src) {
    asm volatile("cp.async.cg.shared.global [%0], [%1], 16;"
                 :: "r"(dst), "l"(src) : "memory");
}
#define CP_COMMIT() asm volatile("cp.async.commit_group;" ::: "memory")
#define CP_WAIT0()  asm volatile("cp.async.wait_group 0;" ::: "memory")
#define SWZ(o)   ((o) ^ (((o) >> 3) & 0x70))
#define SWZ64(o) ((o) ^ (((o) >> 3) & 0x30))

__device__ __forceinline__ void ldsm4(uint32_t addr, uint32_t* r) {
    asm volatile("ldmatrix.sync.aligned.m8n8.x4.shared.b16 {%0,%1,%2,%3}, [%4];"
                 : "=r"(r[0]), "=r"(r[1]), "=r"(r[2]), "=r"(r[3]) : "r"(addr));
}
__device__ __forceinline__ void ldsm4_t(uint32_t addr, uint32_t* r) {
    asm volatile("ldmatrix.sync.aligned.m8n8.x4.trans.shared.b16 {%0,%1,%2,%3}, [%4];"
                 : "=r"(r[0]), "=r"(r[1]), "=r"(r[2]), "=r"(r[3]) : "r"(addr));
}
__device__ __forceinline__ void mma_bf16(float* c, const uint32_t* a,
                                         const uint32_t* b) {
    asm volatile(
        "mma.sync.aligned.m16n8k16.row.col.f32.bf16.bf16.f32 "
        "{%0,%1,%2,%3}, {%4,%5,%6,%7}, {%8,%9}, {%0,%1,%2,%3};"
        : "+f"(c[0]), "+f"(c[1]), "+f"(c[2]), "+f"(c[3])
        : "r"(a[0]), "r"(a[1]), "r"(a[2]), "r"(a[3]), "r"(b[0]), "r"(b[1]));
}

__device__ __forceinline__ void split4(float4 v, uint2& hv, uint2& lv) {
    hv.x = pk_bf16x2(v.x, v.y);
    hv.y = pk_bf16x2(v.z, v.w);
    lv.x = pk_bf16x2(bf16_res(v.x), bf16_res(v.y));
    lv.y = pk_bf16x2(bf16_res(v.z), bf16_res(v.w));
}

// ---------------------------------------------------------------------------
// Kernel 0: pre-split 6 weight matrices (w_out pre-scaled by ln_out_scale),
// plus u/v fold vectors.
// ---------------------------------------------------------------------------
__global__ void __launch_bounds__(256)
k0_split(const float* __restrict__ w0, const float* __restrict__ w1,
         const float* __restrict__ w2, const float* __restrict__ w3,
         const float* __restrict__ w4, const float* __restrict__ w5,
         const float* __restrict__ so, const float* __restrict__ bo)
{
    if (blockIdx.x == 96) {
        int n = threadIdx.x;
        if (n < 128) {
            float u = 0.f, v = 0.f;
            for (int c = 0; c < 128; ++c) {
                float w = w5[c * 128 + n];
                u += so[c] * w;
                v += bo[c] * w;
            }
            g_u[n] = u; g_v[n] = v;
        }
        return;
    }
    const float* ws[6] = {w0, w1, w2, w3, w4, w5};
    int idx = blockIdx.x * 256 + threadIdx.x;
    int m = idx >> 12;
    int e = (idx & 4095) * 4;
    float4 v = *(const float4*)(ws[m] + e);
    if (m == 5) {
        float sc = so[e >> 7];
        v.x *= sc; v.y *= sc; v.z *= sc; v.w *= sc;
    }
    uint2 hv, lv;
    split4(v, hv, lv);
    *(uint2*)(g_wh + m * 16384 + e) = hv;
    *(uint2*)(g_wl + m * 16384 + e) = lv;
}

// ---------------------------------------------------------------------------
// Kernel 1: 256 threads, 64-pixel tiles, 2 CTAs/SM. One weight pair resident.
// Sequence: lgate->P_A | stage left -> Q_A | stage rgate -> epi(a) |
//           P_B | stage right -> Q_B | stage gate -> epi(b) | P_C -> epi(g).
// Gated warp grid: 4 (ch) x 2 (p); phase C: 2 (p) x 4 (ch).
// ---------------------------------------------------------------------------
__global__ void __launch_bounds__(256, 2)
k1_all(const float* __restrict__ z, const float* __restrict__ mask,
       const float* __restrict__ ln_s, const float* __restrict__ ln_b,
       const float* __restrict__ b_lg, const float* __restrict__ b_l,
       const float* __restrict__ b_rg, const float* __restrict__ b_r,
       const float* __restrict__ b_g)
{
    extern __shared__ char smraw[];
    __nv_bfloat16* znh = (__nv_bfloat16*)smraw;          // [p<64][k] pitch 136
    __nv_bfloat16* znl = znh + 64 * PIT;
    __nv_bfloat16* Wh  = znl + 64 * PIT;                 // [k][n] pitch 136
    __nv_bfloat16* Wl  = Wh + 128 * PIT;
    float* bs = (float*)(Wl + 128 * PIT);
    // bs: [0)lg [128)l [256)rg [384)r [512)g [640)mask(64)

    const int tid = threadIdx.x, lane = tid & 31, wid = tid >> 5;
    const int pix0 = blockIdx.x * 64;

    const uint32_t whA = smem_u32(Wh), wlA = smem_u32(Wl);
    const uint32_t zh = smem_u32(znh), zl = smem_u32(znl);

#define STAGE_W(mi)                                                           \
    do {                                                                      \
        const __nv_bfloat16* SH = g_wh + (mi) * 16384;                        \
        const __nv_bfloat16* SL = g_wl + (mi) * 16384;                        \
        _Pragma("unroll")                                                     \
        for (int t = 0; t < 8; ++t) {                                         \
            int u = tid + t * 256;                                            \
            int r = u >> 4, c = u & 15;                                       \
            uint32_t doff = (uint32_t)(r * PITB + c * 16);                    \
            int goff = r * 128 + c * 8;                                       \
            cp16(whA + doff, SH + goff);                                      \
            cp16(wlA + doff, SL + goff);                                      \
        }                                                                     \
        CP_COMMIT();                                                          \
    } while (0)

    STAGE_W(0);   // lgate

    bs[tid]       = (tid < 128) ? b_lg[tid] : b_l[tid - 128];
    bs[256 + tid] = (tid < 128) ? b_rg[tid] : b_r[tid - 128];
    if (tid < 128) bs[512 + tid] = b_g[tid];
    if (tid < 64)  bs[640 + tid] = mask[pix0 + tid];

    // LayerNorm: 8 warps, 8 rows each (overlaps with weight cp.async)
    {
        float4 s4 = ((const float4*)ln_s)[lane];
        float4 b4 = ((const float4*)ln_b)[lane];
        float4 v[8];
#pragma unroll
        for (int t = 0; t < 8; ++t)
            v[t] = ((const float4*)(z + (size_t)(pix0 + t * 8 + wid) * CDIM))[lane];
#pragma unroll
        for (int t = 0; t < 8; ++t) {
            int r = t * 8 + wid;
            float s  = v[t].x + v[t].y + v[t].z + v[t].w;
            float ss = v[t].x*v[t].x + v[t].y*v[t].y + v[t].z*v[t].z + v[t].w*v[t].w;
#pragma unroll
            for (int o = 16; o > 0; o >>= 1) {
                s  += __shfl_xor_sync(0xffffffffu, s,  o);
                ss += __shfl_xor_sync(0xffffffffu, ss, o);
            }
            float mu   = s * 0.0078125f;
            float rstd = rsqrtf(ss * 0.0078125f - mu * mu + 1e-5f);
            float4 o4;
            o4.x = (v[t].x - mu) * rstd * s4.x + b4.x;
            o4.y = (v[t].y - mu) * rstd * s4.y + b4.y;
            o4.z = (v[t].z - mu) * rstd * s4.z + b4.z;
            o4.w = (v[t].w - mu) * rstd * s4.w + b4.w;
            uint2 hv, lv;
            split4(o4, hv, lv);
            *(uint2*)(&znh[r * PIT + lane * 4]) = hv;
            *(uint2*)(&znl[r * PIT + lane * 4]) = lv;
        }
    }
    CP_WAIT0();
    __syncthreads();

    // gated warp grid: wm (ch) in [0,4), wn (p) in [0,2)
    const int wm = wid & 3, wn = wid >> 2;
    const int at_row = (lane & 7) + ((lane >> 4) << 3);      // trans A (W^T)
    const int at_col = ((lane >> 3) & 1) << 3;
    const int bp_row = wn * 32 + (lane & 7) + ((lane >> 4) << 3);  // B (zn)
    const uint32_t bko = ((lane >> 3) & 1) * 16;

    // 3-sweep GEMM over the resident weight pair into acc[2][4][4]
#define GEMM_W(ACC)                                                           \
    do {                                                                      \
        _Pragma("unroll")                                                     \
        for (int k16 = 0; k16 < 8; ++k16) {                                   \
            const int kb = k16 * 16;                                          \
            uint32_t bh[4][2], bl[4][2];                                      \
            _Pragma("unroll")                                                 \
            for (int ng = 0; ng < 2; ++ng) {                                  \
                uint32_t r4[4];                                               \
                uint32_t boff = (uint32_t)((bp_row + ng * 16) * PITB)         \
                                + kb * 2 + bko;                               \
                ldsm4(zh + boff, r4);                                         \
                bh[ng*2][0] = r4[0]; bh[ng*2][1] = r4[1];                     \
                bh[ng*2+1][0] = r4[2]; bh[ng*2+1][1] = r4[3];                 \
                ldsm4(zl + boff, r4);                                         \
                bl[ng*2][0] = r4[0]; bl[ng*2][1] = r4[1];                     \
                bl[ng*2+1][0] = r4[2]; bl[ng*2+1][1] = r4[3];                 \
            }                                                                 \
            uint32_t aoff[2];                                                 \
            _Pragma("unroll")                                                 \
            for (int mt = 0; mt < 2; ++mt)                                    \
                aoff[mt] = (uint32_t)((kb + at_row) * PITB) +                 \
                           (wm * 32 + mt * 16 + at_col) * 2;                  \
            uint32_t a4[2][4];                                                \
            _Pragma("unroll")                                                 \
            for (int mt = 0; mt < 2; ++mt) ldsm4_t(whA + aoff[mt], a4[mt]);   \
            _Pragma("unroll")                                                 \
            for (int mt = 0; mt < 2; ++mt)                                    \
                _Pragma("unroll")                                             \
                for (int nt = 0; nt < 4; ++nt)                                \
                    mma_bf16(ACC[mt][nt], a4[mt], bh[nt]);                    \
            _Pragma("unroll")                                                 \
            for (int mt = 0; mt < 2; ++mt)                                    \
                _Pragma("unroll")                                             \
                for (int nt = 0; nt < 4; ++nt)                                \
                    mma_bf16(ACC[mt][nt], a4[mt], bl[nt]);                    \
            _Pragma("unroll")                                                 \
            for (int mt = 0; mt < 2; ++mt) ldsm4_t(wlA + aoff[mt], a4[mt]);   \
            _Pragma("unroll")                                                 \
            for (int mt = 0; mt < 2; ++mt)                                    \
                _Pragma("unroll")                                             \
                for (int nt = 0; nt < 4; ++nt)                                \
                    mma_bf16(ACC[mt][nt], a4[mt], bh[nt]);                    \
        }                                                                     \
    } while (0)

    float P[2][4][4], Q[2][4][4];

#pragma unroll 1
    for (int ph = 0; ph < 2; ++ph) {
#pragma unroll
        for (int a = 0; a < 2; ++a)
#pragma unroll
            for (int b = 0; b < 4; ++b)
#pragma unroll
                for (int q = 0; q < 4; ++q) { P[a][b][q] = 0.f; Q[a][b][q] = 0.f; }

        GEMM_W(P);                       // gate projection
        __syncthreads();
        STAGE_W(ph == 0 ? 1 : 3);        // value weights
        CP_WAIT0();
        __syncthreads();
        GEMM_W(Q);                       // value projection
        __syncthreads();
        STAGE_W(ph == 0 ? 2 : 4);        // next phase's gate weights

        // epilogue: mask * sig(P + bg) * (Q + bv) -> channel-major hi/lo
        const float* bgp = bs + ph * 256;
        const float* bvp = bs + ph * 256 + 128;
        const float* msm = bs + 640;
        __nv_bfloat16* oh = (ph == 0) ? g_a_hi : g_b_hi;
        __nv_bfloat16* ol = (ph == 0) ? g_a_lo : g_b_lo;
#pragma unroll
        for (int mt = 0; mt < 2; ++mt) {
            int ch = wm * 32 + mt * 16 + (lane >> 2);
            float bg0v = bgp[ch], bg1v = bgp[ch + 8];
            float bv0v = bvp[ch], bv1v = bvp[ch + 8];
            size_t r0 = (size_t)ch * NN + pix0;
            size_t r1 = (size_t)(ch + 8) * NN + pix0;
#pragma unroll
            for (int nt = 0; nt < 4; ++nt) {
                int p = wn * 32 + nt * 8 + (lane & 3) * 2;
                float m0 = msm[p], m1 = msm[p + 1];
                float v00 = m0 * sigmf(P[mt][nt][0] + bg0v) * (Q[mt][nt][0] + bv0v);
                float v01 = m1 * sigmf(P[mt][nt][1] + bg0v) * (Q[mt][nt][1] + bv0v);
                float v10 = m0 * sigmf(P[mt][nt][2] + bg1v) * (Q[mt][nt][2] + bv1v);
                float v11 = m1 * sigmf(P[mt][nt][3] + bg1v) * (Q[mt][nt][3] + bv1v);
                *(uint32_t*)(oh + r0 + p) = pk_bf16x2(v00, v01);
                *(uint32_t*)(ol + r0 + p) = pk_bf16x2(bf16_res(v00), bf16_res(v01));
                *(uint32_t*)(oh + r1 + p) = pk_bf16x2(v10, v11);
                *(uint32_t*)(ol + r1 + p) = pk_bf16x2(bf16_res(v10), bf16_res(v11));
            }
        }
        CP_WAIT0();
        __syncthreads();
    }

    // ---- phase C: g = sig(zn @ Wg + bg), C[p][ch], fp16 out ----
    {
        const int wm2 = wid & 1, wn2 = wid >> 1;   // 2 (p) x 4 (ch)
        const int a_row = wm2 * 32 + (lane & 15);
        const uint32_t ako = (lane >> 4) * 16;
        const int bt_row = (lane & 7) + (((lane >> 3) & 1) << 3);
        const int bt_col = (lane >> 4) << 3;

#pragma unroll
        for (int a = 0; a < 2; ++a)
#pragma unroll
            for (int b = 0; b < 4; ++b)
#pragma unroll
                for (int q = 0; q < 4; ++q) P[a][b][q] = 0.f;

#pragma unroll
        for (int k16 = 0; k16 < 8; ++k16) {
            const int kb = k16 * 16;
            uint32_t bh[4][2], bl[4][2];
#pragma unroll
            for (int ng = 0; ng < 2; ++ng) {
                uint32_t r4[4];
                uint32_t boff = (uint32_t)((kb + bt_row) * PITB) +
                                (wn2 * 32 + ng * 16 + bt_col) * 2;
                ldsm4_t(whA + boff, r4);
                bh[ng*2][0] = r4[0]; bh[ng*2][1] = r4[1];
                bh[ng*2+1][0] = r4[2]; bh[ng*2+1][1] = r4[3];
                ldsm4_t(wlA + boff, r4);
                bl[ng*2][0] = r4[0]; bl[ng*2][1] = r4[1];
                bl[ng*2+1][0] = r4[2]; bl[ng*2+1][1] = r4[3];
            }
            uint32_t ah[2][4], al[2][4];
#pragma unroll
            for (int mt = 0; mt < 2; ++mt) {
                uint32_t aoff = (uint32_t)((a_row + mt * 16) * PITB) + kb * 2 + ako;
                ldsm4(zh + aoff, ah[mt]);
                ldsm4(zl + aoff, al[mt]);
            }
#pragma unroll
            for (int mt = 0; mt < 2; ++mt)
#pragma unroll
                for (int nt = 0; nt < 4; ++nt)
                    mma_bf16(P[mt][nt], ah[mt], bh[nt]);
#pragma unroll
            for (int mt = 0; mt < 2; ++mt)
#pragma unroll
                for (int nt = 0; nt < 4; ++nt)
                    mma_bf16(P[mt][nt], ah[mt], bl[nt]);
#pragma unroll
            for (int mt = 0; mt < 2; ++mt)
#pragma unroll
                for (int nt = 0; nt < 4; ++nt)
                    mma_bf16(P[mt][nt], al[mt], bh[nt]);
        }

        const float* bgp = bs + 512;
#pragma unroll
        for (int mt = 0; mt < 2; ++mt) {
            int p0 = pix0 + wm2 * 32 + mt * 16 + (lane >> 2);
#pragma unroll
            for (int nt = 0; nt < 4; ++nt) {
                int ch = wn2 * 32 + nt * 8 + (lane & 3) * 2;
                float b0 = bgp[ch], b1 = bgp[ch + 1];
                __half2 v0 = __floats2half2_rn(sigmf(P[mt][nt][0] + b0),
                                               sigmf(P[mt][nt][1] + b1));
                __half2 v1 = __floats2half2_rn(sigmf(P[mt][nt][2] + b0),
                                               sigmf(P[mt][nt][3] + b1));
                *(__half2*)(g_g + (size_t)p0 * CDIM + ch) = v0;
                *(__half2*)(g_g + (size_t)(p0 + 8) * CDIM + ch) = v1;
            }
        }
    }
#undef GEMM_W
#undef STAGE_W
}

// ---------------------------------------------------------------------------
// Kernel 2: per-channel X_c = A_c @ B_c^T. 256 threads, 2 CTAs/SM.
// (unchanged from round 11)
// ---------------------------------------------------------------------------
#define K2S 32768u

__global__ void __launch_bounds__(256, 2)
k2_mma()
{
    extern __shared__ char sm2[];
    const uint32_t smb = smem_u32(sm2);
    const int tid  = threadIdx.x;
    const int lane = tid & 31, wid = tid >> 5;
    const int wm = wid & 1, wn = wid >> 1;     // 2 (M) x 4 (N)
    const int i0 = blockIdx.x * 128, j0 = blockIdx.y * 128;
    const size_t cbase = (size_t)blockIdx.z * NN;

    const __nv_bfloat16* Ah = g_a_hi + cbase + (size_t)i0 * NSEQ;
    const __nv_bfloat16* Al = g_a_lo + cbase + (size_t)i0 * NSEQ;
    const __nv_bfloat16* Bh = g_b_hi + cbase + (size_t)j0 * NSEQ;
    const __nv_bfloat16* Bl = g_b_lo + cbase + (size_t)j0 * NSEQ;

    float acc[4][4][4];
#pragma unroll
    for (int mt = 0; mt < 4; ++mt)
#pragma unroll
        for (int nt = 0; nt < 4; ++nt)
#pragma unroll
            for (int q = 0; q < 4; ++q) acc[mt][nt][q] = 0.f;

    const int arow = wm * 64 + (lane & 15);
    const int bnr  = wn * 32 + (lane & 7) + ((lane >> 4) << 3);
    const uint32_t a_koff = (uint32_t)((lane >> 4) << 4);
    const uint32_t b_koff = (uint32_t)(((lane >> 3) & 1) << 4);

#define K2_LOAD(kc, stg)                                                      \
    do {                                                                      \
        const int ke = (kc) * 32;                                             \
        _Pragma("unroll")                                                     \
        for (int t = 0; t < 2; ++t) {                                         \
            int v = tid + t * 256; int r = v >> 2, cu = v & 3;                \
            uint32_t so = SWZ64((uint32_t)(r * 64 + cu * 16));                \
            const size_t go = (size_t)r * NSEQ + ke + cu * 8;                 \
            cp16((stg) + so,           Ah + go);                              \
            cp16((stg) + 8192u + so,   Al + go);                              \
            cp16((stg) + 16384u + so,  Bh + go);                              \
            cp16((stg) + 24576u + so,  Bl + go);                              \
        }                                                                     \
        asm volatile("cp.async.commit_group;" ::: "memory");                  \
    } while (0)

    K2_LOAD(0, smb);
    K2_LOAD(1, smb + K2S);

#pragma unroll 1
    for (int kc = 0; kc < 16; ++kc) {
        if (kc < 15) asm volatile("cp.async.wait_group 1;" ::: "memory");
        else         asm volatile("cp.async.wait_group 0;" ::: "memory");
        __syncthreads();
        const uint32_t stg = smb + (uint32_t)(kc % 3) * K2S;

#pragma unroll
        for (int k16 = 0; k16 < 2; ++k16) {
            const uint32_t kbA = (uint32_t)(k16 * 32) + a_koff;
            const uint32_t kbB = (uint32_t)(k16 * 32) + b_koff;
            uint32_t bh[4][2], bl[4][2];
#pragma unroll
            for (int ng = 0; ng < 2; ++ng) {
                uint32_t r4[4];
                uint32_t off = SWZ64((uint32_t)((bnr + ng * 16) * 64) + kbB);
                ldsm4(stg + 16384u + off, r4);
                bh[ng * 2 + 0][0] = r4[0]; bh[ng * 2 + 0][1] = r4[1];
                bh[ng * 2 + 1][0] = r4[2]; bh[ng * 2 + 1][1] = r4[3];
                ldsm4(stg + 24576u + off, r4);
                bl[ng * 2 + 0][0] = r4[0]; bl[ng * 2 + 0][1] = r4[1];
                bl[ng * 2 + 1][0] = r4[2]; bl[ng * 2 + 1][1] = r4[3];
            }
            uint32_t aoff[4];
#pragma unroll
            for (int mt = 0; mt < 4; ++mt)
                aoff[mt] = SWZ64((uint32_t)((arow + mt * 16) * 64) + kbA);
            uint32_t a4[4][4];
#pragma unroll
            for (int mt = 0; mt < 4; ++mt) ldsm4(stg + aoff[mt], a4[mt]);
#pragma unroll
            for (int mt = 0; mt < 4; ++mt)
#pragma unroll
                for (int nt = 0; nt < 4; ++nt)
                    mma_bf16(acc[mt][nt], a4[mt], bh[nt]);
#pragma unroll
            for (int mt = 0; mt < 4; ++mt)
#pragma unroll
                for (int nt = 0; nt < 4; ++nt)
                    mma_bf16(acc[mt][nt], a4[mt], bl[nt]);
#pragma unroll
            for (int mt = 0; mt < 4; ++mt) ldsm4(stg + 8192u + aoff[mt], a4[mt]);
#pragma unroll
            for (int mt = 0; mt < 4; ++mt)
#pragma unroll
                for (int nt = 0; nt < 4; ++nt)
                    mma_bf16(acc[mt][nt], a4[mt], bh[nt]);
        }
        if (kc + 2 < 16) K2_LOAD(kc + 2, smb + (uint32_t)((kc + 2) % 3) * K2S);
    }

    __nv_bfloat16* Xh = g_xh + cbase + (size_t)(i0 + wm * 64) * NSEQ + j0 + wn * 32;
    __nv_bfloat16* Xl = g_xl + cbase + (size_t)(i0 + wm * 64) * NSEQ + j0 + wn * 32;
    const int rr = lane >> 2, cc = (lane & 3) * 2;
#pragma unroll
    for (int mt = 0; mt < 4; ++mt)
#pragma unroll
        for (int nt = 0; nt < 4; ++nt) {
            size_t o0 = (size_t)(mt * 16 + rr) * NSEQ + nt * 8 + cc;
            size_t o1 = o0 + 8 * NSEQ;
            float v0 = acc[mt][nt][0], v1 = acc[mt][nt][1];
            float v2 = acc[mt][nt][2], v3 = acc[mt][nt][3];
            *(uint32_t*)(Xh + o0) = pk_bf16x2(v0, v1);
            *(uint32_t*)(Xl + o0) = pk_bf16x2(bf16_res(v0), bf16_res(v1));
            *(uint32_t*)(Xh + o1) = pk_bf16x2(v2, v3);
            *(uint32_t*)(Xl + o1) = pk_bf16x2(bf16_res(v2), bf16_res(v3));
        }
#undef K2_LOAD
}

// ---------------------------------------------------------------------------
// Kernel 3: folded-LN out projection (unchanged from round 10/11).
// ---------------------------------------------------------------------------
#define GPIT 136   // fp16 smem pitch for g tile (elements)

__global__ void __launch_bounds__(NT, 1)
k3_mma(const float* __restrict__ b_out, float* __restrict__ out)
{
    extern __shared__ char smraw[];
    __nv_bfloat16* Xh = (__nv_bfloat16*)smraw;          // [c][p] pitch 136
    __nv_bfloat16* Xl = Xh + 128 * PIT;
    __nv_bfloat16* Wh = Xl + 128 * PIT;                 // [k][n] pitch 136
    __nv_bfloat16* Wl = Wh + 128 * PIT;
    __half* gS  = (__half*)(Wl + 128 * PIT);            // [p][c] pitch 136
    float* uS   = (float*)(gS + 128 * GPIT);  // 128
    float* wS   = uS + 128;                   // v + b_out, 128
    float* redS = wS + 128;                   // 512
    float* redQ = redS + 512;                 // 512
    float* rsS  = redQ + 512;                 // 128
    float* tS   = rsS + 128;                  // 128 (mu*rs)

    const int tid = threadIdx.x, lane = tid & 31, wid = tid >> 5;
    const int pix0 = blockIdx.x * 128;

    {
        const uint32_t xhA = smem_u32(Xh), xlA = smem_u32(Xl);
        const uint32_t whA = smem_u32(Wh), wlA = smem_u32(Wl);
        const uint32_t gA  = smem_u32(gS);
        const __nv_bfloat16* GH = g_wh + 5 * 16384;
        const __nv_bfloat16* GL = g_wl + 5 * 16384;
#pragma unroll
        for (int t = 0; t < 4; ++t) {
            int u = tid + t * NT;
            int c = u >> 4, q = u & 15;
            uint32_t doff = (uint32_t)(c * PITB + q * 16);
            size_t goff = (size_t)c * NN + pix0 + q * 8;
            cp16(xhA + doff, g_xh + goff);
            cp16(xlA + doff, g_xl + goff);
        }
#pragma unroll
        for (int t = 0; t < 4; ++t) {
            int u = tid + t * NT;
            int r = u >> 4, c = u & 15;
            uint32_t doff = (uint32_t)(r * PITB + c * 16);
            int goff = r * 128 + c * 8;
            cp16(whA + doff, GH + goff);
            cp16(wlA + doff, GL + goff);
        }
#pragma unroll
        for (int t = 0; t < 4; ++t) {
            int u = tid + t * NT;
            int p = u >> 4, q = u & 15;
            cp16(gA + (uint32_t)(p * GPIT * 2 + q * 16),
                 g_g + (size_t)(pix0 + p) * CDIM + q * 8);
        }
        CP_COMMIT();
    }
    if (tid < 128) { uS[tid] = g_u[tid]; wS[tid] = g_v[tid] + b_out[tid]; }
    CP_WAIT0();
    __syncthreads();

    const int p = tid & 127, quarter = tid >> 7;
    {
        float s = 0.f, ss = 0.f;
#pragma unroll 8
        for (int c = quarter * 32; c < quarter * 32 + 32; ++c) {
            float v = __bfloat162float(Xh[c * PIT + p]) +
                      __bfloat162float(Xl[c * PIT + p]);
            s += v; ss += v * v;
        }
        redS[tid] = s; redQ[tid] = ss;
    }
    __syncthreads();
    if (tid < 128) {
        float S  = redS[tid] + redS[tid + 128] + redS[tid + 256] + redS[tid + 384];
        float Qv = redQ[tid] + redQ[tid + 128] + redQ[tid + 256] + redQ[tid + 384];
        float mu = S * 0.0078125f;
        float rs = rsqrtf(Qv * 0.0078125f - mu * mu + 1e-5f);
        rsS[tid] = rs;
        tS[tid]  = mu * rs;
    }
    __syncthreads();

    const int wm = wid & 3, wn = wid >> 2;
    const uint32_t xh = smem_u32(Xh), xl = smem_u32(Xl);
    const uint32_t wh = smem_u32(Wh), wl = smem_u32(Wl);

    float acc[2][4][4];
#pragma unroll
    for (int a = 0; a < 2; ++a)
#pragma unroll
        for (int b = 0; b < 4; ++b)
#pragma unroll
            for (int q = 0; q < 4; ++q) acc[a][b][q] = 0.f;

    const int at_row = (lane & 7) + ((lane >> 4) << 3);
    const int at_col = ((lane >> 3) & 1) << 3;
    const int bt_row = (lane & 7) + (((lane >> 3) & 1) << 3);
    const int bt_col = (lane >> 4) << 3;

#pragma unroll
    for (int k16 = 0; k16 < 8; ++k16) {
        const int kb = k16 * 16;
        uint32_t bh[4][2], bl[4][2];
#pragma unroll
        for (int ng = 0; ng < 2; ++ng) {
            uint32_t r4[4];
            uint32_t boff = (uint32_t)((kb + bt_row) * PITB) +
                            (wn * 32 + ng * 16 + bt_col) * 2;
            ldsm4_t(wh + boff, r4);
            bh[ng*2][0] = r4[0]; bh[ng*2][1] = r4[1];
            bh[ng*2+1][0] = r4[2]; bh[ng*2+1][1] = r4[3];
            ldsm4_t(wl + boff, r4);
            bl[ng*2][0] = r4[0]; bl[ng*2][1] = r4[1];
            bl[ng*2+1][0] = r4[2]; bl[ng*2+1][1] = r4[3];
        }
        uint32_t ah[2][4], al[2][4];
#pragma unroll
        for (int mt = 0; mt < 2; ++mt) {
            uint32_t aoff = (uint32_t)((kb + at_row) * PITB) +
                            (wm * 32 + mt * 16 + at_col) * 2;
            ldsm4_t(xh + aoff, ah[mt]);
            ldsm4_t(xl + aoff, al[mt]);
        }
#pragma unroll
        for (int mt = 0; mt < 2; ++mt)
#pragma unroll
            for (int nt = 0; nt < 4; ++nt)
                mma_bf16(acc[mt][nt], ah[mt], bh[nt]);
#pragma unroll
        for (int mt = 0; mt < 2; ++mt)
#pragma unroll
            for (int nt = 0; nt < 4; ++nt)
                mma_bf16(acc[mt][nt], ah[mt], bl[nt]);
#pragma unroll
        for (int mt = 0; mt < 2; ++mt)
#pragma unroll
            for (int nt = 0; nt < 4; ++nt)
                mma_bf16(acc[mt][nt], al[mt], bh[nt]);
    }

#pragma unroll
    for (int mt = 0; mt < 2; ++mt) {
        int pl = wm * 32 + mt * 16 + (lane >> 2);
        int p0 = pix0 + pl;
        float rs0 = rsS[pl],     t0 = tS[pl];
        float rs1 = rsS[pl + 8], t1 = tS[pl + 8];
#pragma unroll
        for (int nt = 0; nt < 4; ++nt) {
            int ch = wn * 32 + nt * 8 + (lane & 3) * 2;
            float u0 = uS[ch], u1 = uS[ch + 1];
            float w0 = wS[ch], w1 = wS[ch + 1];
            float2 g0 = __half22float2(*(const __half2*)(gS + pl * GPIT + ch));
            float2 g1 = __half22float2(*(const __half2*)(gS + (pl + 8) * GPIT + ch));
            float2 v0 = make_float2((rs0 * acc[mt][nt][0] - t0 * u0 + w0) * g0.x,
                                    (rs0 * acc[mt][nt][1] - t0 * u1 + w1) * g0.y);
            float2 v1 = make_float2((rs1 * acc[mt][nt][2] - t1 * u0 + w0) * g1.x,
                                    (rs1 * acc[mt][nt][3] - t1 * u1 + w1) * g1.y);
            *(float2*)(out + (size_t)p0 * CDIM + ch) = v0;
            *(float2*)(out + (size_t)(p0 + 8) * CDIM + ch) = v1;
        }
    }
}

// ---------------------------------------------------------------------------
extern "C" void kernel_launch(void* const* d_in, const int* in_sizes, int n_in,
                              void* d_out, int out_size)
{
    const float* z        = (const float*)d_in[0];
    const float* mask     = (const float*)d_in[1];
    const float* ln_in_s  = (const float*)d_in[2];
    const float* ln_in_b  = (const float*)d_in[3];
    const float* w_left   = (const float*)d_in[4];
    const float* b_left   = (const float*)d_in[5];
    const float* w_right  = (const float*)d_in[6];
    const float* b_right  = (const float*)d_in[7];
    const float* w_lgate  = (const float*)d_in[8];
    const float* b_lgate  = (const float*)d_in[9];
    const float* w_rgate  = (const float*)d_in[10];
    const float* b_rgate  = (const float*)d_in[11];
    const float* ln_out_s = (const float*)d_in[12];
    const float* ln_out_b = (const float*)d_in[13];
    const float* w_out    = (const float*)d_in[14];
    const float* b_out    = (const float*)d_in[15];
    const float* w_gate   = (const float*)d_in[16];
    const float* b_gate   = (const float*)d_in[17];
    float* out = (float*)d_out;

    const int smem1 = (64 * PIT + 64 * PIT + 2 * 128 * PIT) * 2 + 704 * 4; // ~107 KB
    const int smem2 = 3 * (int)K2S;                                        // 98304
    const int smem3 = 4 * 128 * PIT * 2 + 128 * GPIT * 2 + 1536 * 4;       // ~180 KB

    cudaFuncSetAttribute(k1_all, cudaFuncAttributeMaxDynamicSharedMemorySize, smem1);
    cudaFuncSetAttribute(k2_mma, cudaFuncAttributeMaxDynamicSharedMemorySize, smem2);
    cudaFuncSetAttribute(k3_mma, cudaFuncAttributeMaxDynamicSharedMemorySize, smem3);

    // 0) pre-split weights (w_out scaled by ln_out_scale) + u/v fold vectors
    k0_split<<<97, 256>>>(w_lgate, w_left, w_rgate, w_right, w_gate, w_out,
                          ln_out_s, ln_out_b);

    // 1) a, b, g projections from a single LN pass (2 CTAs/SM)
    k1_all<<<NN / 64, 256, smem1>>>(
        z, mask, ln_in_s, ln_in_b,
        b_lgate, b_left, b_rgate, b_right, b_gate);

    // 2) triangular einsum per channel (2 CTAs/SM)
    k2_mma<<<dim3(4, 4, CDIM), 256, smem2>>>();

    // 3) folded-LN out projection + gating
    k3_mma<<<NN / 128, NT, smem3>>>(b_out, out);
}

// round 13
// speedup vs baseline: 1.2031x; 1.0157x over previous
#include <cuda_runtime.h>
#include <cuda_bf16.h>
#include <cuda_fp16.h>
#include <math.h>
#include <stddef.h>
#include <stdint.h>

// Triangle multiplicative update (outgoing), N=512, cz=ch=128, fp32 in/out.
// All GEMMs on tensor cores via mma.sync bf16 hi/lo split (3 passes, fp32 acc).
// Round 13: k3 rebuilt for 2 CTAs/SM (256 thr, 64-pixel tiles, g read from L2).

#define NSEQ 512
#define CDIM 128
#define NN   (NSEQ*NSEQ)          // 262144
#define PIT  136                  // bf16 smem pitch (elements)
#define PITB 272                  // bytes
#define XPIT 72                   // k3 X tile pitch (elements), 144B = 9*16
#define NT   512

__device__ __nv_bfloat16 g_a_hi[(size_t)CDIM * NN];
__device__ __nv_bfloat16 g_a_lo[(size_t)CDIM * NN];
__device__ __nv_bfloat16 g_b_hi[(size_t)CDIM * NN];
__device__ __nv_bfloat16 g_b_lo[(size_t)CDIM * NN];
__device__ __half g_g[(size_t)NN * CDIM];           // g[pix][c] fp16
__device__ __nv_bfloat16 g_xh[(size_t)CDIM * NN];   // x hi [c][i][j]
__device__ __nv_bfloat16 g_xl[(size_t)CDIM * NN];   // x lo
// pre-split weights: 0=lgate 1=left 2=rgate 3=right 4=gate 5=out(.scaled)
__device__ __align__(16) __nv_bfloat16 g_wh[6 * 16384];
__device__ __align__(16) __nv_bfloat16 g_wl[6 * 16384];
__device__ float g_u[128];   // sum_c s[c]*w_out[c][n]
__device__ float g_v[128];   // sum_c b_ln[c]*w_out[c][n]

__device__ __forceinline__ float sigmf(float x) {
    return 1.0f / (1.0f + __expf(-x));
}
__device__ __forceinline__ unsigned pk_bf16x2(float a, float b) {
    __nv_bfloat162 t = __floats2bfloat162_rn(a, b);
    return *reinterpret_cast<unsigned*>(&t);
}
__device__ __forceinline__ float bf16_res(float v) {   // v - bf16(v)
    return v - __bfloat162float(__float2bfloat16(v));
}
__device__ __forceinline__ uint32_t smem_u32(const void* p) {
    uint32_t a;
    asm("{ .reg .u64 t; cvta.to.shared.u64 t, %1; cvt.u32.u64 %0, t; }"
        : "=r"(a) : "l"(p));
    return a;
}
__device__ __forceinline__ void cp16(uint32_t dst, const void* src) {
    asm volatile("cp.async.cg.shared.global [%0], [%1], 16;"
                 :: "r"(dst), "l"(src) : "memory");
}
#define CP_COMMIT() asm volatile("cp.async.commit_group;" ::: "memory")
#define CP_WAIT0()  asm volatile("cp.async.wait_group 0;" ::: "memory")
#define SWZ(o)   ((o) ^ (((o) >> 3) & 0x70))
#define SWZ64(o) ((o) ^ (((o) >> 3) & 0x30))

__device__ __forceinline__ void ldsm4(uint32_t addr, uint32_t* r) {
    asm volatile("ldmatrix.sync.aligned.m8n8.x4.shared.b16 {%0,%1,%2,%3}, [%4];"
                 : "=r"(r[0]), "=r"(r[1]), "=r"(r[2]), "=r"(r[3]) : "r"(addr));
}
__device__ __forceinline__ void ldsm4_t(uint32_t addr, uint32_t* r) {
    asm volatile("ldmatrix.sync.aligned.m8n8.x4.trans.shared.b16 {%0,%1,%2,%3}, [%4];"
                 : "=r"(r[0]), "=r"(r[1]), "=r"(r[2]), "=r"(r[3]) : "r"(addr));
}
__device__ __forceinline__ void mma_bf16(float* c, const uint32_t* a,
                                         const uint32_t* b) {
    asm volatile(
        "mma.sync.aligned.m16n8k16.row.col.f32.bf16.bf16.f32 "
        "{%0,%1,%2,%3}, {%4,%5,%6,%7}, {%8,%9}, {%0,%1,%2,%3};"
        : "+f"(c[0]), "+f"(c[1]), "+f"(c[2]), "+f"(c[3])
        : "r"(a[0]), "r"(a[1]), "r"(a[2]), "r"(a[3]), "r"(b[0]), "r"(b[1]));
}

__device__ __forceinline__ void split4(float4 v, uint2& hv, uint2& lv) {
    hv.x = pk_bf16x2(v.x, v.y);
    hv.y = pk_bf16x2(v.z, v.w);
    lv.x = pk_bf16x2(bf16_res(v.x), bf16_res(v.y));
    lv.y = pk_bf16x2(bf16_res(v.z), bf16_res(v.w));
}

// ---------------------------------------------------------------------------
// Kernel 0: pre-split 6 weight matrices (w_out pre-scaled by ln_out_scale),
// plus u/v fold vectors.
// ---------------------------------------------------------------------------
__global__ void __launch_bounds__(256)
k0_split(const float* __restrict__ w0, const float* __restrict__ w1,
         const float* __restrict__ w2, const float* __restrict__ w3,
         const float* __restrict__ w4, const float* __restrict__ w5,
         const float* __restrict__ so, const float* __restrict__ bo)
{
    if (blockIdx.x == 96) {
        int n = threadIdx.x;
        if (n < 128) {
            float u = 0.f, v = 0.f;
            for (int c = 0; c < 128; ++c) {
                float w = w5[c * 128 + n];
                u += so[c] * w;
                v += bo[c] * w;
            }
            g_u[n] = u; g_v[n] = v;
        }
        return;
    }
    const float* ws[6] = {w0, w1, w2, w3, w4, w5};
    int idx = blockIdx.x * 256 + threadIdx.x;
    int m = idx >> 12;
    int e = (idx & 4095) * 4;
    float4 v = *(const float4*)(ws[m] + e);
    if (m == 5) {
        float sc = so[e >> 7];
        v.x *= sc; v.y *= sc; v.z *= sc; v.w *= sc;
    }
    uint2 hv, lv;
    split4(v, hv, lv);
    *(uint2*)(g_wh + m * 16384 + e) = hv;
    *(uint2*)(g_wl + m * 16384 + e) = lv;
}

// ---------------------------------------------------------------------------
// Kernel 1: 256 threads, 64-pixel tiles, 2 CTAs/SM. One weight pair resident.
// (unchanged from round 12)
// ---------------------------------------------------------------------------
__global__ void __launch_bounds__(256, 2)
k1_all(const float* __restrict__ z, const float* __restrict__ mask,
       const float* __restrict__ ln_s, const float* __restrict__ ln_b,
       const float* __restrict__ b_lg, const float* __restrict__ b_l,
       const float* __restrict__ b_rg, const float* __restrict__ b_r,
       const float* __restrict__ b_g)
{
    extern __shared__ char smraw[];
    __nv_bfloat16* znh = (__nv_bfloat16*)smraw;          // [p<64][k] pitch 136
    __nv_bfloat16* znl = znh + 64 * PIT;
    __nv_bfloat16* Wh  = znl + 64 * PIT;                 // [k][n] pitch 136
    __nv_bfloat16* Wl  = Wh + 128 * PIT;
    float* bs = (float*)(Wl + 128 * PIT);
    // bs: [0)lg [128)l [256)rg [384)r [512)g [640)mask(64)

    const int tid = threadIdx.x, lane = tid & 31, wid = tid >> 5;
    const int pix0 = blockIdx.x * 64;

    const uint32_t whA = smem_u32(Wh), wlA = smem_u32(Wl);
    const uint32_t zh = smem_u32(znh), zl = smem_u32(znl);

#define STAGE_W(mi)                                                           \
    do {                                                                      \
        const __nv_bfloat16* SH = g_wh + (mi) * 16384;                        \
        const __nv_bfloat16* SL = g_wl + (mi) * 16384;                        \
        _Pragma("unroll")                                                     \
        for (int t = 0; t < 8; ++t) {                                         \
            int u = tid + t * 256;                                            \
            int r = u >> 4, c = u & 15;                                       \
            uint32_t doff = (uint32_t)(r * PITB + c * 16);                    \
            int goff = r * 128 + c * 8;                                       \
            cp16(whA + doff, SH + goff);                                      \
            cp16(wlA + doff, SL + goff);                                      \
        }                                                                     \
        CP_COMMIT();                                                          \
    } while (0)

    STAGE_W(0);   // lgate

    bs[tid]       = (tid < 128) ? b_lg[tid] : b_l[tid - 128];
    bs[256 + tid] = (tid < 128) ? b_rg[tid] : b_r[tid - 128];
    if (tid < 128) bs[512 + tid] = b_g[tid];
    if (tid < 64)  bs[640 + tid] = mask[pix0 + tid];

    // LayerNorm: 8 warps, 8 rows each (overlaps with weight cp.async)
    {
        float4 s4 = ((const float4*)ln_s)[lane];
        float4 b4 = ((const float4*)ln_b)[lane];
        float4 v[8];
#pragma unroll
        for (int t = 0; t < 8; ++t)
            v[t] = ((const float4*)(z + (size_t)(pix0 + t * 8 + wid) * CDIM))[lane];
#pragma unroll
        for (int t = 0; t < 8; ++t) {
            int r = t * 8 + wid;
            float s  = v[t].x + v[t].y + v[t].z + v[t].w;
            float ss = v[t].x*v[t].x + v[t].y*v[t].y + v[t].z*v[t].z + v[t].w*v[t].w;
#pragma unroll
            for (int o = 16; o > 0; o >>= 1) {
                s  += __shfl_xor_sync(0xffffffffu, s,  o);
                ss += __shfl_xor_sync(0xffffffffu, ss, o);
            }
            float mu   = s * 0.0078125f;
            float rstd = rsqrtf(ss * 0.0078125f - mu * mu + 1e-5f);
            float4 o4;
            o4.x = (v[t].x - mu) * rstd * s4.x + b4.x;
            o4.y = (v[t].y - mu) * rstd * s4.y + b4.y;
            o4.z = (v[t].z - mu) * rstd * s4.z + b4.z;
            o4.w = (v[t].w - mu) * rstd * s4.w + b4.w;
            uint2 hv, lv;
            split4(o4, hv, lv);
            *(uint2*)(&znh[r * PIT + lane * 4]) = hv;
            *(uint2*)(&znl[r * PIT + lane * 4]) = lv;
        }
    }
    CP_WAIT0();
    __syncthreads();

    const int wm = wid & 3, wn = wid >> 2;
    const int at_row = (lane & 7) + ((lane >> 4) << 3);
    const int at_col = ((lane >> 3) & 1) << 3;
    const int bp_row = wn * 32 + (lane & 7) + ((lane >> 4) << 3);
    const uint32_t bko = ((lane >> 3) & 1) * 16;

#define GEMM_W(ACC)                                                           \
    do {                                                                      \
        _Pragma("unroll")                                                     \
        for (int k16 = 0; k16 < 8; ++k16) {                                   \
            const int kb = k16 * 16;                                          \
            uint32_t bh[4][2], bl[4][2];                                      \
            _Pragma("unroll")                                                 \
            for (int ng = 0; ng < 2; ++ng) {                                  \
                uint32_t r4[4];                                               \
                uint32_t boff = (uint32_t)((bp_row + ng * 16) * PITB)         \
                                + kb * 2 + bko;                               \
                ldsm4(zh + boff, r4);                                         \
                bh[ng*2][0] = r4[0]; bh[ng*2][1] = r4[1];                     \
                bh[ng*2+1][0] = r4[2]; bh[ng*2+1][1] = r4[3];                 \
                ldsm4(zl + boff, r4);                                         \
                bl[ng*2][0] = r4[0]; bl[ng*2][1] = r4[1];                     \
                bl[ng*2+1][0] = r4[2]; bl[ng*2+1][1] = r4[3];                 \
            }                                                                 \
            uint32_t aoff[2];                                                 \
            _Pragma("unroll")                                                 \
            for (int mt = 0; mt < 2; ++mt)                                    \
                aoff[mt] = (uint32_t)((kb + at_row) * PITB) +                 \
                           (wm * 32 + mt * 16 + at_col) * 2;                  \
            uint32_t a4[2][4];                                                \
            _Pragma("unroll")                                                 \
            for (int mt = 0; mt < 2; ++mt) ldsm4_t(whA + aoff[mt], a4[mt]);   \
            _Pragma("unroll")                                                 \
            for (int mt = 0; mt < 2; ++mt)                                    \
                _Pragma("unroll")                                             \
                for (int nt = 0; nt < 4; ++nt)                                \
                    mma_bf16(ACC[mt][nt], a4[mt], bh[nt]);                    \
            _Pragma("unroll")                                                 \
            for (int mt = 0; mt < 2; ++mt)                                    \
                _Pragma("unroll")                                             \
                for (int nt = 0; nt < 4; ++nt)                                \
                    mma_bf16(ACC[mt][nt], a4[mt], bl[nt]);                    \
            _Pragma("unroll")                                                 \
            for (int mt = 0; mt < 2; ++mt) ldsm4_t(wlA + aoff[mt], a4[mt]);   \
            _Pragma("unroll")                                                 \
            for (int mt = 0; mt < 2; ++mt)                                    \
                _Pragma("unroll")                                             \
                for (int nt = 0; nt < 4; ++nt)                                \
                    mma_bf16(ACC[mt][nt], a4[mt], bh[nt]);                    \
        }                                                                     \
    } while (0)

    float P[2][4][4], Q[2][4][4];

#pragma unroll 1
    for (int ph = 0; ph < 2; ++ph) {
#pragma unroll
        for (int a = 0; a < 2; ++a)
#pragma unroll
            for (int b = 0; b < 4; ++b)
#pragma unroll
                for (int q = 0; q < 4; ++q) { P[a][b][q] = 0.f; Q[a][b][q] = 0.f; }

        GEMM_W(P);
        __syncthreads();
        STAGE_W(ph == 0 ? 1 : 3);
        CP_WAIT0();
        __syncthreads();
        GEMM_W(Q);
        __syncthreads();
        STAGE_W(ph == 0 ? 2 : 4);

        const float* bgp = bs + ph * 256;
        const float* bvp = bs + ph * 256 + 128;
        const float* msm = bs + 640;
        __nv_bfloat16* oh = (ph == 0) ? g_a_hi : g_b_hi;
        __nv_bfloat16* ol = (ph == 0) ? g_a_lo : g_b_lo;
#pragma unroll
        for (int mt = 0; mt < 2; ++mt) {
            int ch = wm * 32 + mt * 16 + (lane >> 2);
            float bg0v = bgp[ch], bg1v = bgp[ch + 8];
            float bv0v = bvp[ch], bv1v = bvp[ch + 8];
            size_t r0 = (size_t)ch * NN + pix0;
            size_t r1 = (size_t)(ch + 8) * NN + pix0;
#pragma unroll
            for (int nt = 0; nt < 4; ++nt) {
                int p = wn * 32 + nt * 8 + (lane & 3) * 2;
                float m0 = msm[p], m1 = msm[p + 1];
                float v00 = m0 * sigmf(P[mt][nt][0] + bg0v) * (Q[mt][nt][0] + bv0v);
                float v01 = m1 * sigmf(P[mt][nt][1] + bg0v) * (Q[mt][nt][1] + bv0v);
                float v10 = m0 * sigmf(P[mt][nt][2] + bg1v) * (Q[mt][nt][2] + bv1v);
                float v11 = m1 * sigmf(P[mt][nt][3] + bg1v) * (Q[mt][nt][3] + bv1v);
                *(uint32_t*)(oh + r0 + p) = pk_bf16x2(v00, v01);
                *(uint32_t*)(ol + r0 + p) = pk_bf16x2(bf16_res(v00), bf16_res(v01));
                *(uint32_t*)(oh + r1 + p) = pk_bf16x2(v10, v11);
                *(uint32_t*)(ol + r1 + p) = pk_bf16x2(bf16_res(v10), bf16_res(v11));
            }
        }
        CP_WAIT0();
        __syncthreads();
    }

    // ---- phase C: g = sig(zn @ Wg + bg), C[p][ch], fp16 out ----
    {
        const int wm2 = wid & 1, wn2 = wid >> 1;
        const int a_row = wm2 * 32 + (lane & 15);
        const uint32_t ako = (lane >> 4) * 16;
        const int bt_row = (lane & 7) + (((lane >> 3) & 1) << 3);
        const int bt_col = (lane >> 4) << 3;

#pragma unroll
        for (int a = 0; a < 2; ++a)
#pragma unroll
            for (int b = 0; b < 4; ++b)
#pragma unroll
                for (int q = 0; q < 4; ++q) P[a][b][q] = 0.f;

#pragma unroll
        for (int k16 = 0; k16 < 8; ++k16) {
            const int kb = k16 * 16;
            uint32_t bh[4][2], bl[4][2];
#pragma unroll
            for (int ng = 0; ng < 2; ++ng) {
                uint32_t r4[4];
                uint32_t boff = (uint32_t)((kb + bt_row) * PITB) +
                                (wn2 * 32 + ng * 16 + bt_col) * 2;
                ldsm4_t(whA + boff, r4);
                bh[ng*2][0] = r4[0]; bh[ng*2][1] = r4[1];
                bh[ng*2+1][0] = r4[2]; bh[ng*2+1][1] = r4[3];
                ldsm4_t(wlA + boff, r4);
                bl[ng*2][0] = r4[0]; bl[ng*2][1] = r4[1];
                bl[ng*2+1][0] = r4[2]; bl[ng*2+1][1] = r4[3];
            }
            uint32_t ah[2][4], al[2][4];
#pragma unroll
            for (int mt = 0; mt < 2; ++mt) {
                uint32_t aoff = (uint32_t)((a_row + mt * 16) * PITB) + kb * 2 + ako;
                ldsm4(zh + aoff, ah[mt]);
                ldsm4(zl + aoff, al[mt]);
            }
#pragma unroll
            for (int mt = 0; mt < 2; ++mt)
#pragma unroll
                for (int nt = 0; nt < 4; ++nt)
                    mma_bf16(P[mt][nt], ah[mt], bh[nt]);
#pragma unroll
            for (int mt = 0; mt < 2; ++mt)
#pragma unroll
                for (int nt = 0; nt < 4; ++nt)
                    mma_bf16(P[mt][nt], ah[mt], bl[nt]);
#pragma unroll
            for (int mt = 0; mt < 2; ++mt)
#pragma unroll
                for (int nt = 0; nt < 4; ++nt)
                    mma_bf16(P[mt][nt], al[mt], bh[nt]);
        }

        const float* bgp = bs + 512;
#pragma unroll
        for (int mt = 0; mt < 2; ++mt) {
            int p0 = pix0 + wm2 * 32 + mt * 16 + (lane >> 2);
#pragma unroll
            for (int nt = 0; nt < 4; ++nt) {
                int ch = wn2 * 32 + nt * 8 + (lane & 3) * 2;
                float b0 = bgp[ch], b1 = bgp[ch + 1];
                __half2 v0 = __floats2half2_rn(sigmf(P[mt][nt][0] + b0),
                                               sigmf(P[mt][nt][1] + b1));
                __half2 v1 = __floats2half2_rn(sigmf(P[mt][nt][2] + b0),
                                               sigmf(P[mt][nt][3] + b1));
                *(__half2*)(g_g + (size_t)p0 * CDIM + ch) = v0;
                *(__half2*)(g_g + (size_t)(p0 + 8) * CDIM + ch) = v1;
            }
        }
    }
#undef GEMM_W
#undef STAGE_W
}

// ---------------------------------------------------------------------------
// Kernel 2: per-channel X_c = A_c @ B_c^T. 256 threads, 2 CTAs/SM.
// (unchanged from round 11/12)
// ---------------------------------------------------------------------------
#define K2S 32768u

__global__ void __launch_bounds__(256, 2)
k2_mma()
{
    extern __shared__ char sm2[];
    const uint32_t smb = smem_u32(sm2);
    const int tid  = threadIdx.x;
    const int lane = tid & 31, wid = tid >> 5;
    const int wm = wid & 1, wn = wid >> 1;
    const int i0 = blockIdx.x * 128, j0 = blockIdx.y * 128;
    const size_t cbase = (size_t)blockIdx.z * NN;

    const __nv_bfloat16* Ah = g_a_hi + cbase + (size_t)i0 * NSEQ;
    const __nv_bfloat16* Al = g_a_lo + cbase + (size_t)i0 * NSEQ;
    const __nv_bfloat16* Bh = g_b_hi + cbase + (size_t)j0 * NSEQ;
    const __nv_bfloat16* Bl = g_b_lo + cbase + (size_t)j0 * NSEQ;

    float acc[4][4][4];
#pragma unroll
    for (int mt = 0; mt < 4; ++mt)
#pragma unroll
        for (int nt = 0; nt < 4; ++nt)
#pragma unroll
            for (int q = 0; q < 4; ++q) acc[mt][nt][q] = 0.f;

    const int arow = wm * 64 + (lane & 15);
    const int bnr  = wn * 32 + (lane & 7) + ((lane >> 4) << 3);
    const uint32_t a_koff = (uint32_t)((lane >> 4) << 4);
    const uint32_t b_koff = (uint32_t)(((lane >> 3) & 1) << 4);

#define K2_LOAD(kc, stg)                                                      \
    do {                                                                      \
        const int ke = (kc) * 32;                                             \
        _Pragma("unroll")                                                     \
        for (int t = 0; t < 2; ++t) {                                         \
            int v = tid + t * 256; int r = v >> 2, cu = v & 3;                \
            uint32_t so = SWZ64((uint32_t)(r * 64 + cu * 16));                \
            const size_t go = (size_t)r * NSEQ + ke + cu * 8;                 \
            cp16((stg) + so,           Ah + go);                              \
            cp16((stg) + 8192u + so,   Al + go);                              \
            cp16((stg) + 16384u + so,  Bh + go);                              \
            cp16((stg) + 24576u + so,  Bl + go);                              \
        }                                                                     \
        asm volatile("cp.async.commit_group;" ::: "memory");                  \
    } while (0)

    K2_LOAD(0, smb);
    K2_LOAD(1, smb + K2S);

#pragma unroll 1
    for (int kc = 0; kc < 16; ++kc) {
        if (kc < 15) asm volatile("cp.async.wait_group 1;" ::: "memory");
        else         asm volatile("cp.async.wait_group 0;" ::: "memory");
        __syncthreads();
        const uint32_t stg = smb + (uint32_t)(kc % 3) * K2S;

#pragma unroll
        for (int k16 = 0; k16 < 2; ++k16) {
            const uint32_t kbA = (uint32_t)(k16 * 32) + a_koff;
            const uint32_t kbB = (uint32_t)(k16 * 32) + b_koff;
            uint32_t bh[4][2], bl[4][2];
#pragma unroll
            for (int ng = 0; ng < 2; ++ng) {
                uint32_t r4[4];
                uint32_t off = SWZ64((uint32_t)((bnr + ng * 16) * 64) + kbB);
                ldsm4(stg + 16384u + off, r4);
                bh[ng * 2 + 0][0] = r4[0]; bh[ng * 2 + 0][1] = r4[1];
                bh[ng * 2 + 1][0] = r4[2]; bh[ng * 2 + 1][1] = r4[3];
                ldsm4(stg + 24576u + off, r4);
                bl[ng * 2 + 0][0] = r4[0]; bl[ng * 2 + 0][1] = r4[1];
                bl[ng * 2 + 1][0] = r4[2]; bl[ng * 2 + 1][1] = r4[3];
            }
            uint32_t aoff[4];
#pragma unroll
            for (int mt = 0; mt < 4; ++mt)
                aoff[mt] = SWZ64((uint32_t)((arow + mt * 16) * 64) + kbA);
            uint32_t a4[4][4];
#pragma unroll
            for (int mt = 0; mt < 4; ++mt) ldsm4(stg + aoff[mt], a4[mt]);
#pragma unroll
            for (int mt = 0; mt < 4; ++mt)
#pragma unroll
                for (int nt = 0; nt < 4; ++nt)
                    mma_bf16(acc[mt][nt], a4[mt], bh[nt]);
#pragma unroll
            for (int mt = 0; mt < 4; ++mt)
#pragma unroll
                for (int nt = 0; nt < 4; ++nt)
                    mma_bf16(acc[mt][nt], a4[mt], bl[nt]);
#pragma unroll
            for (int mt = 0; mt < 4; ++mt) ldsm4(stg + 8192u + aoff[mt], a4[mt]);
#pragma unroll
            for (int mt = 0; mt < 4; ++mt)
#pragma unroll
                for (int nt = 0; nt < 4; ++nt)
                    mma_bf16(acc[mt][nt], a4[mt], bh[nt]);
        }
        if (kc + 2 < 16) K2_LOAD(kc + 2, smb + (uint32_t)((kc + 2) % 3) * K2S);
    }

    __nv_bfloat16* Xh = g_xh + cbase + (size_t)(i0 + wm * 64) * NSEQ + j0 + wn * 32;
    __nv_bfloat16* Xl = g_xl + cbase + (size_t)(i0 + wm * 64) * NSEQ + j0 + wn * 32;
    const int rr = lane >> 2, cc = (lane & 3) * 2;
#pragma unroll
    for (int mt = 0; mt < 4; ++mt)
#pragma unroll
        for (int nt = 0; nt < 4; ++nt) {
            size_t o0 = (size_t)(mt * 16 + rr) * NSEQ + nt * 8 + cc;
            size_t o1 = o0 + 8 * NSEQ;
            float v0 = acc[mt][nt][0], v1 = acc[mt][nt][1];
            float v2 = acc[mt][nt][2], v3 = acc[mt][nt][3];
            *(uint32_t*)(Xh + o0) = pk_bf16x2(v0, v1);
            *(uint32_t*)(Xl + o0) = pk_bf16x2(bf16_res(v0), bf16_res(v1));
            *(uint32_t*)(Xh + o1) = pk_bf16x2(v2, v3);
            *(uint32_t*)(Xl + o1) = pk_bf16x2(bf16_res(v2), bf16_res(v3));
        }
#undef K2_LOAD
}

// ---------------------------------------------------------------------------
// Kernel 3: folded-LN out projection, 256 threads, 64-pixel tiles, 2 CTAs/SM.
//   y[p][n] = rs[p]*(x@W')[p][n] - rs[p]*mu[p]*u[n] + (v[n]+b_out[n]);
//   out = y * g (g read as fp16 from L2).
// ---------------------------------------------------------------------------
__global__ void __launch_bounds__(256, 2)
k3_mma(const float* __restrict__ b_out, float* __restrict__ out)
{
    extern __shared__ char smraw[];
    __nv_bfloat16* Xh = (__nv_bfloat16*)smraw;          // [c][p<64] pitch 72
    __nv_bfloat16* Xl = Xh + 128 * XPIT;
    __nv_bfloat16* Wh = Xl + 128 * XPIT;                // [k][n] pitch 136
    __nv_bfloat16* Wl = Wh + 128 * PIT;
    float* uS   = (float*)(Wl + 128 * PIT);   // 128
    float* wS   = uS + 128;                   // v + b_out, 128
    float* redS = wS + 128;                   // 256
    float* redQ = redS + 256;                 // 256
    float* rsS  = redQ + 256;                 // 64
    float* tS   = rsS + 64;                   // 64 (mu*rs)

    const int tid = threadIdx.x, lane = tid & 31, wid = tid >> 5;
    const int pix0 = blockIdx.x * 64;

    // async stage: x hi/lo 64-px tile + pre-split scaled w_out
    {
        const uint32_t xhA = smem_u32(Xh), xlA = smem_u32(Xl);
        const uint32_t whA = smem_u32(Wh), wlA = smem_u32(Wl);
        const __nv_bfloat16* GH = g_wh + 5 * 16384;
        const __nv_bfloat16* GL = g_wl + 5 * 16384;
#pragma unroll
        for (int t = 0; t < 4; ++t) {
            int u = tid + t * 256;                 // 1024 chunks per buffer
            int c = u >> 3, q = u & 7;
            uint32_t doff = (uint32_t)(c * (XPIT * 2) + q * 16);
            size_t goff = (size_t)c * NN + pix0 + q * 8;
            cp16(xhA + doff, g_xh + goff);
            cp16(xlA + doff, g_xl + goff);
        }
#pragma unroll
        for (int t = 0; t < 8; ++t) {
            int u = tid + t * 256;                 // 2048 chunks per matrix
            int r = u >> 4, c = u & 15;
            uint32_t doff = (uint32_t)(r * PITB + c * 16);
            int goff = r * 128 + c * 8;
            cp16(whA + doff, GH + goff);
            cp16(wlA + doff, GL + goff);
        }
        CP_COMMIT();
    }
    if (tid < 128) { uS[tid] = g_u[tid]; wS[tid] = g_v[tid] + b_out[tid]; }
    CP_WAIT0();
    __syncthreads();

    // stats over c (four threads per pixel, 32 channels each)
    const int p = tid & 63, quarter = tid >> 6;
    {
        float s = 0.f, ss = 0.f;
#pragma unroll 8
        for (int c = quarter * 32; c < quarter * 32 + 32; ++c) {
            float v = __bfloat162float(Xh[c * XPIT + p]) +
                      __bfloat162float(Xl[c * XPIT + p]);
            s += v; ss += v * v;
        }
        redS[tid] = s; redQ[tid] = ss;
    }
    __syncthreads();
    if (tid < 64) {
        float S  = redS[tid] + redS[tid + 64] + redS[tid + 128] + redS[tid + 192];
        float Qv = redQ[tid] + redQ[tid + 64] + redQ[tid + 128] + redQ[tid + 192];
        float mu = S * 0.0078125f;
        float rs = rsqrtf(Qv * 0.0078125f - mu * mu + 1e-5f);
        rsS[tid] = rs;
        tS[tid]  = mu * rs;
    }
    __syncthreads();

    // GEMM: C[p=64][n=128]; warps 2 (p) x 4 (n); A = X trans, B = W trans
    const int wm = wid & 1, wn = wid >> 1;
    const uint32_t xh = smem_u32(Xh), xl = smem_u32(Xl);
    const uint32_t wh = smem_u32(Wh), wl = smem_u32(Wl);

    float acc[2][4][4];
#pragma unroll
    for (int a = 0; a < 2; ++a)
#pragma unroll
        for (int b = 0; b < 4; ++b)
#pragma unroll
            for (int q = 0; q < 4; ++q) acc[a][b][q] = 0.f;

    const int at_row = (lane & 7) + ((lane >> 4) << 3);
    const int at_col = ((lane >> 3) & 1) << 3;
    const int bt_row = (lane & 7) + (((lane >> 3) & 1) << 3);
    const int bt_col = (lane >> 4) << 3;

#pragma unroll
    for (int k16 = 0; k16 < 8; ++k16) {
        const int kb = k16 * 16;
        uint32_t bh[4][2], bl[4][2];
#pragma unroll
        for (int ng = 0; ng < 2; ++ng) {
            uint32_t r4[4];
            uint32_t boff = (uint32_t)((kb + bt_row) * PITB) +
                            (wn * 32 + ng * 16 + bt_col) * 2;
            ldsm4_t(wh + boff, r4);
            bh[ng*2][0] = r4[0]; bh[ng*2][1] = r4[1];
            bh[ng*2+1][0] = r4[2]; bh[ng*2+1][1] = r4[3];
            ldsm4_t(wl + boff, r4);
            bl[ng*2][0] = r4[0]; bl[ng*2][1] = r4[1];
            bl[ng*2+1][0] = r4[2]; bl[ng*2+1][1] = r4[3];
        }
        uint32_t ah[2][4], al[2][4];
#pragma unroll
        for (int mt = 0; mt < 2; ++mt) {
            uint32_t aoff = (uint32_t)((kb + at_row) * (XPIT * 2)) +
                            (wm * 32 + mt * 16 + at_col) * 2;
            ldsm4_t(xh + aoff, ah[mt]);
            ldsm4_t(xl + aoff, al[mt]);
        }
#pragma unroll
        for (int mt = 0; mt < 2; ++mt)
#pragma unroll
            for (int nt = 0; nt < 4; ++nt)
                mma_bf16(acc[mt][nt], ah[mt], bh[nt]);
#pragma unroll
        for (int mt = 0; mt < 2; ++mt)
#pragma unroll
            for (int nt = 0; nt < 4; ++nt)
                mma_bf16(acc[mt][nt], ah[mt], bl[nt]);
#pragma unroll
        for (int mt = 0; mt < 2; ++mt)
#pragma unroll
            for (int nt = 0; nt < 4; ++nt)
                mma_bf16(acc[mt][nt], al[mt], bh[nt]);
    }

    // epilogue: y = rs*acc - t*u + w ; out = y * g (g fp16 from L2)
#pragma unroll
    for (int mt = 0; mt < 2; ++mt) {
        int pl = wm * 32 + mt * 16 + (lane >> 2);
        int p0 = pix0 + pl;
        float rs0 = rsS[pl],     t0 = tS[pl];
        float rs1 = rsS[pl + 8], t1 = tS[pl + 8];
#pragma unroll
        for (int nt = 0; nt < 4; ++nt) {
            int ch = wn * 32 + nt * 8 + (lane & 3) * 2;
            float u0 = uS[ch], u1 = uS[ch + 1];
            float w0 = wS[ch], w1 = wS[ch + 1];
            float2 g0 = __half22float2(
                *(const __half2*)(g_g + (size_t)p0 * CDIM + ch));
            float2 g1 = __half22float2(
                *(const __half2*)(g_g + (size_t)(p0 + 8) * CDIM + ch));
            float2 v0 = make_float2((rs0 * acc[mt][nt][0] - t0 * u0 + w0) * g0.x,
                                    (rs0 * acc[mt][nt][1] - t0 * u1 + w1) * g0.y);
            float2 v1 = make_float2((rs1 * acc[mt][nt][2] - t1 * u0 + w0) * g1.x,
                                    (rs1 * acc[mt][nt][3] - t1 * u1 + w1) * g1.y);
            *(float2*)(out + (size_t)p0 * CDIM + ch) = v0;
            *(float2*)(out + (size_t)(p0 + 8) * CDIM + ch) = v1;
        }
    }
}

// ---------------------------------------------------------------------------
extern "C" void kernel_launch(void* const* d_in, const int* in_sizes, int n_in,
                              void* d_out, int out_size)
{
    const float* z        = (const float*)d_in[0];
    const float* mask     = (const float*)d_in[1];
    const float* ln_in_s  = (const float*)d_in[2];
    const float* ln_in_b  = (const float*)d_in[3];
    const float* w_left   = (const float*)d_in[4];
    const float* b_left   = (const float*)d_in[5];
    const float* w_right  = (const float*)d_in[6];
    const float* b_right  = (const float*)d_in[7];
    const float* w_lgate  = (const float*)d_in[8];
    const float* b_lgate  = (const float*)d_in[9];
    const float* w_rgate  = (const float*)d_in[10];
    const float* b_rgate  = (const float*)d_in[11];
    const float* ln_out_s = (const float*)d_in[12];
    const float* ln_out_b = (const float*)d_in[13];
    const float* w_out    = (const float*)d_in[14];
    const float* b_out    = (const float*)d_in[15];
    const float* w_gate   = (const float*)d_in[16];
    const float* b_gate   = (const float*)d_in[17];
    float* out = (float*)d_out;

    const int smem1 = (64 * PIT + 64 * PIT + 2 * 128 * PIT) * 2 + 704 * 4; // ~107 KB
    const int smem2 = 3 * (int)K2S;                                        // 98304
    const int smem3 = (2 * 128 * XPIT + 2 * 128 * PIT) * 2 +
                      (2 * 128 + 2 * 256 + 2 * 64) * 4;                    // ~110 KB

    cudaFuncSetAttribute(k1_all, cudaFuncAttributeMaxDynamicSharedMemorySize, smem1);
    cudaFuncSetAttribute(k2_mma, cudaFuncAttributeMaxDynamicSharedMemorySize, smem2);
    cudaFuncSetAttribute(k3_mma, cudaFuncAttributeMaxDynamicSharedMemorySize, smem3);

    // 0) pre-split weights (w_out scaled by ln_out_scale) + u/v fold vectors
    k0_split<<<97, 256>>>(w_lgate, w_left, w_rgate, w_right, w_gate, w_out,
                          ln_out_s, ln_out_b);

    // 1) a, b, g projections from a single LN pass (2 CTAs/SM)
    k1_all<<<NN / 64, 256, smem1>>>(
        z, mask, ln_in_s, ln_in_b,
        b_lgate, b_left, b_rgate, b_right, b_gate);

    // 2) triangular einsum per channel (2 CTAs/SM)
    k2_mma<<<dim3(4, 4, CDIM), 256, smem2>>>();

    // 3) folded-LN out projection + gating (2 CTAs/SM)
    k3_mma<<<NN / 64, 256, smem3>>>(b_out, out);
}